// round 1
// baseline (speedup 1.0000x reference)
#include <cuda_runtime.h>
#include <math.h>

// ---------------- problem constants ----------------
#define S_LEN   1024
#define D_MODEL 1024
#define G_GRP   8
#define H_HEADS 16
#define DQK     128
#define DVV     128
#define FF_OUT  1024
#define NQ      (G_GRP*H_HEADS*DQK)    /* 16384 */
#define NKV     (G_GRP*(DQK+DVV))      /* 2048  */
#define NKHALF  (G_GRP*DQK)            /* 1024  */
#define ZD      NQ                     /* 16384 */
#define FF2     (2*FF_OUT)             /* 2048  */

// ---------------- scratch (device globals; no allocation allowed) ------------
__device__ float g_xn[S_LEN*D_MODEL];                       // 4 MB
__device__ float g_q[S_LEN*NQ];                             // 64 MB
__device__ float g_kv[S_LEN*NKV];                           // 8 MB
__device__ float g_vt[G_GRP*DVV*S_LEN];                     // 4 MB  (V transposed per group)
__device__ float g_scores[134217728];                       // 512 MB: G*H*S*S
__device__ float g_z[S_LEN*ZD];                             // 64 MB
__device__ float g_h1[S_LEN*FF2];                           // 8 MB

// ---------------- rmsnorm ----------------
__device__ __forceinline__ void rms_body(const float* __restrict__ in,
                                         const float* __restrict__ gamma,
                                         float* __restrict__ out, int cols)
{
    const float* x = in  + (size_t)blockIdx.x * cols;
    float*       y = out + (size_t)blockIdx.x * cols;
    float ss = 0.f;
    for (int c = threadIdx.x; c < cols; c += blockDim.x) { float v = x[c]; ss += v*v; }
    __shared__ float red[33];
    #pragma unroll
    for (int o = 16; o; o >>= 1) ss += __shfl_xor_sync(0xffffffffu, ss, o);
    if ((threadIdx.x & 31) == 0) red[threadIdx.x >> 5] = ss;
    __syncthreads();
    if (threadIdx.x < 32) {
        float v = (threadIdx.x < (blockDim.x >> 5)) ? red[threadIdx.x] : 0.f;
        #pragma unroll
        for (int o = 16; o; o >>= 1) v += __shfl_xor_sync(0xffffffffu, v, o);
        if (threadIdx.x == 0) red[32] = v;
    }
    __syncthreads();
    float scale = sqrtf((float)cols) / fmaxf(sqrtf(red[32]), 1e-12f);
    for (int c = threadIdx.x; c < cols; c += blockDim.x) y[c] = x[c] * scale * gamma[c];
}

__global__ void k_rms_x(const float* __restrict__ x, const float* __restrict__ gamma) {
    rms_body(x, gamma, g_xn, D_MODEL);
}
__global__ void k_rms_z(const float* __restrict__ gamma) {
    rms_body(g_z, gamma, g_z, ZD);
}

// ---------------- generic SGEMM: C = act(alpha * A(MxK) @ B(NxK)^T + bias) ----
#define BM 128
#define BN 128
#define BK 16
#define TM 8
#define TN 8

template<int ACT>   // 0 = none, 1 = silu
__device__ __forceinline__ void gemm_body(
    const float* __restrict__ A, const float* __restrict__ Bm,
    const float* __restrict__ bias, float* __restrict__ C,
    int N, int K, int lda, int ldb, int ldc, float alpha)
{
    __shared__ float As[BK][BM + 4];
    __shared__ float Bs[BK][BN + 4];
    const int tid = threadIdx.x;
    const int tx = tid & 15;
    const int ty = tid >> 4;
    const float* Ab = A  + (size_t)blockIdx.y * BM * lda;
    const float* Bb = Bm + (size_t)blockIdx.x * BN * ldb;

    float acc[TM][TN];
    #pragma unroll
    for (int i = 0; i < TM; i++)
        #pragma unroll
        for (int j = 0; j < TN; j++) acc[i][j] = 0.f;

    for (int k0 = 0; k0 < K; k0 += BK) {
        #pragma unroll
        for (int t = 0; t < 2; t++) {
            int i  = tid + t * 256;         // 0..511
            int r  = i >> 2;                // 0..127
            int c4 = (i & 3) * 4;           // 0,4,8,12
            float4 va = *(const float4*)(Ab + (size_t)r * lda + k0 + c4);
            As[c4+0][r] = va.x; As[c4+1][r] = va.y; As[c4+2][r] = va.z; As[c4+3][r] = va.w;
            float4 vb = *(const float4*)(Bb + (size_t)r * ldb + k0 + c4);
            Bs[c4+0][r] = vb.x; Bs[c4+1][r] = vb.y; Bs[c4+2][r] = vb.z; Bs[c4+3][r] = vb.w;
        }
        __syncthreads();
        #pragma unroll
        for (int k = 0; k < BK; k++) {
            float a[TM], b[TN];
            float4 a0 = *(const float4*)&As[k][ty * TM];
            float4 a1 = *(const float4*)&As[k][ty * TM + 4];
            float4 b0 = *(const float4*)&Bs[k][tx * TN];
            float4 b1 = *(const float4*)&Bs[k][tx * TN + 4];
            a[0]=a0.x; a[1]=a0.y; a[2]=a0.z; a[3]=a0.w;
            a[4]=a1.x; a[5]=a1.y; a[6]=a1.z; a[7]=a1.w;
            b[0]=b0.x; b[1]=b0.y; b[2]=b0.z; b[3]=b0.w;
            b[4]=b1.x; b[5]=b1.y; b[6]=b1.z; b[7]=b1.w;
            #pragma unroll
            for (int i = 0; i < TM; i++)
                #pragma unroll
                for (int j = 0; j < TN; j++)
                    acc[i][j] = fmaf(a[i], b[j], acc[i][j]);
        }
        __syncthreads();
    }

    #pragma unroll
    for (int i = 0; i < TM; i++) {
        int m = blockIdx.y * BM + ty * TM + i;
        #pragma unroll
        for (int j = 0; j < TN; j++) {
            int n = blockIdx.x * BN + tx * TN + j;
            float v = acc[i][j] * alpha + (bias ? bias[n] : 0.f);
            if (ACT == 1) v = v / (1.f + __expf(-v));
            C[(size_t)m * ldc + n] = v;
        }
    }
}

// ---------------- GEMM wrapper kernels ----------------
__global__ void k_qproj(const float* __restrict__ W, const float* __restrict__ b) {
    gemm_body<0>(g_xn, W, b, g_q, NQ, D_MODEL, D_MODEL, D_MODEL, NQ, 1.f);
}
__global__ void k_kvproj(const float* __restrict__ W, const float* __restrict__ b) {
    gemm_body<0>(g_xn, W, b, g_kv, NKV, D_MODEL, D_MODEL, D_MODEL, NKV, 1.f);
}
__global__ void k_scores() {
    int batch = blockIdx.z;                 // g*H + h
    int g = batch >> 4;
    gemm_body<0>(g_q + batch * DQK,
                 g_kv + g * DQK,
                 nullptr,
                 g_scores + (size_t)batch * S_LEN * S_LEN,
                 S_LEN, DQK, NQ, NKV, S_LEN,
                 0.08838834764831845f /* 1/sqrt(128) */);
}
__global__ void k_pv() {
    int batch = blockIdx.z;
    int g = batch >> 4;
    gemm_body<0>(g_scores + (size_t)batch * S_LEN * S_LEN,
                 g_vt + (size_t)g * DVV * S_LEN,
                 nullptr,
                 g_z + batch * DVV,
                 DVV, S_LEN, S_LEN, S_LEN, ZD, 1.f);
}
__global__ void k_ffn1(const float* __restrict__ W, const float* __restrict__ b) {
    gemm_body<1>(g_z, W, b, g_h1, FF2, ZD, ZD, ZD, FF2, 1.f);
}
__global__ void k_ffn2(const float* __restrict__ W, const float* __restrict__ b,
                       float* __restrict__ out) {
    gemm_body<1>(g_h1, W, b, out, FF_OUT, FF2, FF2, FF2, FF_OUT, 1.f);
}

// ---------------- V transpose: g_vt[g][d][t] = v[t][g][d] ----------------
__global__ void k_vt_build() {
    int idx = blockIdx.x * 256 + threadIdx.x;      // 0 .. G*DVV*S-1 (2^20)
    int t = idx & (S_LEN - 1);
    int d = (idx >> 10) & (DVV - 1);
    int g = idx >> 17;
    g_vt[idx] = g_kv[(size_t)t * NKV + NKHALF + g * DVV + d];
}

// ---------------- row softmax over 1024 cols (256 threads/row) --------------
__global__ void k_softmax() {
    float* row = g_scores + (size_t)blockIdx.x * S_LEN;
    __shared__ float red[33];
    int tid = threadIdx.x;
    float vals[4];
    float m = -1e30f;
    #pragma unroll
    for (int i = 0; i < 4; i++) { vals[i] = row[tid + i * 256]; m = fmaxf(m, vals[i]); }
    #pragma unroll
    for (int o = 16; o; o >>= 1) m = fmaxf(m, __shfl_xor_sync(0xffffffffu, m, o));
    if ((tid & 31) == 0) red[tid >> 5] = m;
    __syncthreads();
    if (tid < 32) {
        float v = (tid < 8) ? red[tid] : -1e30f;
        #pragma unroll
        for (int o = 4; o; o >>= 1) v = fmaxf(v, __shfl_xor_sync(0xffffffffu, v, o));
        if (tid == 0) red[32] = v;
    }
    __syncthreads();
    m = red[32];
    __syncthreads();
    float s = 0.f;
    #pragma unroll
    for (int i = 0; i < 4; i++) { vals[i] = __expf(vals[i] - m); s += vals[i]; }
    #pragma unroll
    for (int o = 16; o; o >>= 1) s += __shfl_xor_sync(0xffffffffu, s, o);
    if ((tid & 31) == 0) red[tid >> 5] = s;
    __syncthreads();
    if (tid < 32) {
        float v = (tid < 8) ? red[tid] : 0.f;
        #pragma unroll
        for (int o = 4; o; o >>= 1) v += __shfl_xor_sync(0xffffffffu, v, o);
        if (tid == 0) red[32] = v;
    }
    __syncthreads();
    float inv = 1.f / red[32];
    #pragma unroll
    for (int i = 0; i < 4; i++) row[tid + i * 256] = vals[i] * inv;
}

// ---------------- launch ----------------
extern "C" void kernel_launch(void* const* d_in, const int* in_sizes, int n_in,
                              void* d_out, int out_size) {
    const float* x     = (const float*)d_in[0];
    const float* gin   = (const float*)d_in[1];
    const float* Wq_w  = (const float*)d_in[2];
    const float* Wq_b  = (const float*)d_in[3];
    const float* Wkv_w = (const float*)d_in[4];
    const float* Wkv_b = (const float*)d_in[5];
    const float* gz    = (const float*)d_in[6];
    const float* W1    = (const float*)d_in[7];
    const float* b1    = (const float*)d_in[8];
    const float* W2    = (const float*)d_in[9];
    const float* b2    = (const float*)d_in[10];
    float* out = (float*)d_out;

    k_rms_x  <<<S_LEN, 256>>>(x, gin);
    k_qproj  <<<dim3(NQ / BN,     S_LEN / BM), 256>>>(Wq_w, Wq_b);
    k_kvproj <<<dim3(NKV / BN,    S_LEN / BM), 256>>>(Wkv_w, Wkv_b);
    k_vt_build<<<(G_GRP * DVV * S_LEN) / 256, 256>>>();
    k_scores <<<dim3(S_LEN / BN,  S_LEN / BM, G_GRP * H_HEADS), 256>>>();
    k_softmax<<<G_GRP * H_HEADS * S_LEN, 256>>>();
    k_pv     <<<dim3(DVV / BN,    S_LEN / BM, G_GRP * H_HEADS), 256>>>();
    k_rms_z  <<<S_LEN, 256>>>(gz);
    k_ffn1   <<<dim3(FF2 / BN,    S_LEN / BM), 256>>>(W1, b1);
    k_ffn2   <<<dim3(FF_OUT / BN, S_LEN / BM), 256>>>(W2, b2, out);
}

// round 5
// speedup vs baseline: 1.7665x; 1.7665x over previous
#include <cuda_runtime.h>
#include <cuda_bf16.h>
#include <math.h>
#include <stdint.h>

// ---------------- problem constants ----------------
#define S_LEN   1024
#define D_MODEL 1024
#define G_GRP   8
#define H_HEADS 16
#define DQK     128
#define DVV     128
#define FF_OUT  1024
#define NQ      (G_GRP*H_HEADS*DQK)    /* 16384 */
#define NKV     (G_GRP*(DQK+DVV))      /* 2048  */
#define NKHALF  (G_GRP*DQK)            /* 1024  */
#define ZD      NQ                     /* 16384 */
#define FF2     (2*FF_OUT)             /* 2048  */
#define ATT_SCALE 0.08838834764831845f /* 1/sqrt(128) */

// ---------------- scratch (device globals; no allocation allowed) ------------
// NOTE: these symbols must ONLY be referenced from device code. Passing them
// as kernel arguments from host code silently passes the host shadow address
// (which GB300 ATS will happily dereference) — that was the R2-R4 bug.
__device__ float g_xn[S_LEN*D_MODEL];                       // 4 MB
__device__ float g_q[S_LEN*NQ];                             // 64 MB
__device__ float g_kv[S_LEN*NKV];                           // 8 MB
__device__ float g_vt[G_GRP*DVV*S_LEN];                     // 4 MB
__device__ float g_scores[134217728];                       // 512 MB: G*H*S*S
__device__ float g_z[S_LEN*ZD];                             // 64 MB
__device__ float g_h1[S_LEN*FF2];                           // 8 MB

// ---------------- rmsnorm ----------------
__device__ __forceinline__ void rms_body(const float* __restrict__ in,
                                         const float* __restrict__ gamma,
                                         float* __restrict__ out, int cols)
{
    const float* x = in  + (size_t)blockIdx.x * cols;
    float*       y = out + (size_t)blockIdx.x * cols;
    float ss = 0.f;
    for (int c = threadIdx.x; c < cols; c += blockDim.x) { float v = x[c]; ss += v*v; }
    __shared__ float red[33];
    #pragma unroll
    for (int o = 16; o; o >>= 1) ss += __shfl_xor_sync(0xffffffffu, ss, o);
    if ((threadIdx.x & 31) == 0) red[threadIdx.x >> 5] = ss;
    __syncthreads();
    if (threadIdx.x < 32) {
        float v = (threadIdx.x < (blockDim.x >> 5)) ? red[threadIdx.x] : 0.f;
        #pragma unroll
        for (int o = 16; o; o >>= 1) v += __shfl_xor_sync(0xffffffffu, v, o);
        if (threadIdx.x == 0) red[32] = v;
    }
    __syncthreads();
    float scale = sqrtf((float)cols) / fmaxf(sqrtf(red[32]), 1e-12f);
    for (int c = threadIdx.x; c < cols; c += blockDim.x) y[c] = x[c] * scale * gamma[c];
}

__global__ void k_rms_x(const float* __restrict__ x, const float* __restrict__ gamma) {
    rms_body(x, gamma, g_xn, D_MODEL);
}
__global__ void k_rms_z(const float* __restrict__ gamma) {
    rms_body(g_z, gamma, g_z, ZD);
}

// ---------------- bf16 split-precision mma GEMM: C = A(MxK) @ B(NxK)^T -------
// block tile 128x128, BK=32, 8 warps; warp tile 32(m)x64(n) = 2x8 m16n8k16
// A = Ahi + Alo (bf16 split); C accumulates Ahi*Bhi + Ahi*Blo + Alo*Bhi in fp32.

__device__ __forceinline__ uint32_t pack2bf(float x, float y) {
    __nv_bfloat162 p = __floats2bfloat162_rn(x, y);
    return *reinterpret_cast<uint32_t*>(&p);
}

__device__ __forceinline__ void mma_bf16(float* d, const uint32_t* a, const uint32_t* b) {
    asm volatile(
        "mma.sync.aligned.m16n8k16.row.col.f32.bf16.bf16.f32 "
        "{%0,%1,%2,%3}, {%4,%5,%6,%7}, {%8,%9}, {%0,%1,%2,%3};"
        : "+f"(d[0]), "+f"(d[1]), "+f"(d[2]), "+f"(d[3])
        : "r"(a[0]), "r"(a[1]), "r"(a[2]), "r"(a[3]), "r"(b[0]), "r"(b[1]));
}

#define BM 128
#define BN 128
#define BK 32
#define KP (BK/2)        /* packed bf16x2 k-width = 16 */
#define LDP (KP + 4)     /* padded stride (uint32 units) = 20 */

__device__ __forceinline__ void gemm_tc(
    const float* __restrict__ A, const float* __restrict__ Bm,
    float* __restrict__ C, int K, int lda, int ldb, int ldc)
{
    __shared__ uint32_t AsH[BM][LDP];
    __shared__ uint32_t AsL[BM][LDP];
    __shared__ uint32_t BsH[BN][LDP];
    __shared__ uint32_t BsL[BN][LDP];
    const int tid  = threadIdx.x;
    const int wid  = tid >> 5;
    const int lane = tid & 31;
    const int grp  = lane >> 2;   // 0..7
    const int tig  = lane & 3;    // 0..3
    const int mbase = (wid & 3) * 32;   // 4 warps along M
    const int nbase = (wid >> 2) * 64;  // 2 warps along N

    const float* Ab = A  + (size_t)blockIdx.y * BM * lda;
    const float* Bb = Bm + (size_t)blockIdx.x * BN * ldb;

    float acc[2][8][4];
    #pragma unroll
    for (int mi = 0; mi < 2; mi++)
        #pragma unroll
        for (int ni = 0; ni < 8; ni++)
            #pragma unroll
            for (int v = 0; v < 4; v++) acc[mi][ni][v] = 0.f;

    for (int k0 = 0; k0 < K; k0 += BK) {
        #pragma unroll
        for (int t = 0; t < 4; t++) {
            int i  = tid + t * 256;         // 0..1023
            int r  = i >> 3;                // 0..127
            int c  = (i & 7) * 4;           // float col: 0,4,..28
            int pc = c >> 1;                // packed col: 0,2,..14

            float4 va = *(const float4*)(Ab + (size_t)r * lda + k0 + c);
            float hx = __bfloat162float(__float2bfloat16_rn(va.x));
            float hy = __bfloat162float(__float2bfloat16_rn(va.y));
            float hz = __bfloat162float(__float2bfloat16_rn(va.z));
            float hw = __bfloat162float(__float2bfloat16_rn(va.w));
            *(uint2*)&AsH[r][pc] = make_uint2(pack2bf(hx, hy), pack2bf(hz, hw));
            *(uint2*)&AsL[r][pc] = make_uint2(pack2bf(va.x - hx, va.y - hy),
                                              pack2bf(va.z - hz, va.w - hw));

            float4 vb = *(const float4*)(Bb + (size_t)r * ldb + k0 + c);
            hx = __bfloat162float(__float2bfloat16_rn(vb.x));
            hy = __bfloat162float(__float2bfloat16_rn(vb.y));
            hz = __bfloat162float(__float2bfloat16_rn(vb.z));
            hw = __bfloat162float(__float2bfloat16_rn(vb.w));
            *(uint2*)&BsH[r][pc] = make_uint2(pack2bf(hx, hy), pack2bf(hz, hw));
            *(uint2*)&BsL[r][pc] = make_uint2(pack2bf(vb.x - hx, vb.y - hy),
                                              pack2bf(vb.z - hz, vb.w - hw));
        }
        __syncthreads();
        #pragma unroll
        for (int kk = 0; kk < KP; kk += 8) {   // two k16 steps per BK=32
            uint32_t bH[8][2], bL[8][2];
            #pragma unroll
            for (int ni = 0; ni < 8; ni++) {
                int nrow = nbase + ni * 8 + grp;
                bH[ni][0] = BsH[nrow][kk + tig];
                bH[ni][1] = BsH[nrow][kk + tig + 4];
                bL[ni][0] = BsL[nrow][kk + tig];
                bL[ni][1] = BsL[nrow][kk + tig + 4];
            }
            #pragma unroll
            for (int mi = 0; mi < 2; mi++) {
                int r0 = mbase + mi * 16 + grp;
                uint32_t aH[4], aL[4];
                aH[0] = AsH[r0    ][kk + tig];
                aH[1] = AsH[r0 + 8][kk + tig];
                aH[2] = AsH[r0    ][kk + tig + 4];
                aH[3] = AsH[r0 + 8][kk + tig + 4];
                aL[0] = AsL[r0    ][kk + tig];
                aL[1] = AsL[r0 + 8][kk + tig];
                aL[2] = AsL[r0    ][kk + tig + 4];
                aL[3] = AsL[r0 + 8][kk + tig + 4];
                #pragma unroll
                for (int ni = 0; ni < 8; ni++) {
                    mma_bf16(acc[mi][ni], aH, bH[ni]);
                    mma_bf16(acc[mi][ni], aH, bL[ni]);
                    mma_bf16(acc[mi][ni], aL, bH[ni]);
                }
            }
        }
        __syncthreads();
    }

    // C layout (m16n8): c0=(grp, 2t), c1=(grp, 2t+1), c2=(grp+8, 2t), c3=(grp+8, 2t+1)
    #pragma unroll
    for (int mi = 0; mi < 2; mi++)
        #pragma unroll
        for (int ni = 0; ni < 8; ni++) {
            int row = blockIdx.y * BM + mbase + mi * 16 + grp;
            int col = blockIdx.x * BN + nbase + ni * 8 + tig * 2;
            *(float2*)&C[(size_t)row * ldc + col] =
                make_float2(acc[mi][ni][0], acc[mi][ni][1]);
            *(float2*)&C[(size_t)(row + 8) * ldc + col] =
                make_float2(acc[mi][ni][2], acc[mi][ni][3]);
        }
}

// ---------------- GEMM wrapper kernels ----------------
__global__ void k_qproj(const float* __restrict__ W) {
    gemm_tc(g_xn, W, g_q, D_MODEL, D_MODEL, D_MODEL, NQ);
}
__global__ void k_kvproj(const float* __restrict__ W) {
    gemm_tc(g_xn, W, g_kv, D_MODEL, D_MODEL, D_MODEL, NKV);
}
__global__ void k_scores() {
    int batch = blockIdx.z;                 // g*H + h
    int g = batch >> 4;
    gemm_tc(g_q + batch * DQK,
            g_kv + g * DQK,
            g_scores + (size_t)batch * S_LEN * S_LEN,
            DQK, NQ, NKV, S_LEN);
}
__global__ void k_pv() {
    int batch = blockIdx.z;
    int g = batch >> 4;
    gemm_tc(g_scores + (size_t)batch * S_LEN * S_LEN,
            g_vt + (size_t)g * DVV * S_LEN,
            g_z + batch * DVV,
            S_LEN, S_LEN, S_LEN, ZD);
}
__global__ void k_ffn1(const float* __restrict__ W) {
    gemm_tc(g_z, W, g_h1, ZD, ZD, ZD, FF2);
}
__global__ void k_ffn2(const float* __restrict__ W, float* __restrict__ out) {
    gemm_tc(g_h1, W, out, FF2, FF2, FF2, FF_OUT);
}

// ---------------- elementwise epilogues (globals referenced in DEVICE code) --
__global__ void k_bias_q(const float* __restrict__ bias) {
    int idx = blockIdx.x * 256 + threadIdx.x;
    g_q[idx] += bias[idx & (NQ - 1)];
}
__global__ void k_bias_kv(const float* __restrict__ bias) {
    int idx = blockIdx.x * 256 + threadIdx.x;
    g_kv[idx] += bias[idx & (NKV - 1)];
}
__global__ void k_silu_h1(const float* __restrict__ bias) {
    int idx = blockIdx.x * 256 + threadIdx.x;
    float v = g_h1[idx] + bias[idx & (FF2 - 1)];
    g_h1[idx] = v / (1.f + __expf(-v));
}
__global__ void k_silu_out(float* __restrict__ C, const float* __restrict__ bias) {
    int idx = blockIdx.x * 256 + threadIdx.x;
    float v = C[idx] + bias[idx & (FF_OUT - 1)];
    C[idx] = v / (1.f + __expf(-v));
}

// ---------------- V transpose: g_vt[g][d][t] = v[t][g][d] ----------------
__global__ void k_vt_build() {
    int idx = blockIdx.x * 256 + threadIdx.x;      // 0 .. G*DVV*S-1 (2^20)
    int t = idx & (S_LEN - 1);
    int d = (idx >> 10) & (DVV - 1);
    int g = idx >> 17;
    g_vt[idx] = g_kv[(size_t)t * NKV + NKHALF + g * DVV + d];
}

// ---------------- row softmax over 1024 cols (scale folded in) --------------
__global__ void k_softmax() {
    float* row = g_scores + (size_t)blockIdx.x * S_LEN;
    __shared__ float red[33];
    int tid = threadIdx.x;
    float vals[4];
    float m = -1e30f;
    #pragma unroll
    for (int i = 0; i < 4; i++) { vals[i] = row[tid + i * 256] * ATT_SCALE; m = fmaxf(m, vals[i]); }
    #pragma unroll
    for (int o = 16; o; o >>= 1) m = fmaxf(m, __shfl_xor_sync(0xffffffffu, m, o));
    if ((tid & 31) == 0) red[tid >> 5] = m;
    __syncthreads();
    if (tid < 32) {
        float v = (tid < 8) ? red[tid] : -1e30f;
        #pragma unroll
        for (int o = 4; o; o >>= 1) v = fmaxf(v, __shfl_xor_sync(0xffffffffu, v, o));
        if (tid == 0) red[32] = v;
    }
    __syncthreads();
    m = red[32];
    __syncthreads();
    float s = 0.f;
    #pragma unroll
    for (int i = 0; i < 4; i++) { vals[i] = __expf(vals[i] - m); s += vals[i]; }
    #pragma unroll
    for (int o = 16; o; o >>= 1) s += __shfl_xor_sync(0xffffffffu, s, o);
    if ((tid & 31) == 0) red[tid >> 5] = s;
    __syncthreads();
    if (tid < 32) {
        float v = (tid < 8) ? red[tid] : 0.f;
        #pragma unroll
        for (int o = 4; o; o >>= 1) v += __shfl_xor_sync(0xffffffffu, v, o);
        if (tid == 0) red[32] = v;
    }
    __syncthreads();
    float inv = 1.f / red[32];
    #pragma unroll
    for (int i = 0; i < 4; i++) row[tid + i * 256] = vals[i] * inv;
}

// ---------------- launch ----------------
extern "C" void kernel_launch(void* const* d_in, const int* in_sizes, int n_in,
                              void* d_out, int out_size) {
    const float* x     = (const float*)d_in[0];
    const float* gin   = (const float*)d_in[1];
    const float* Wq_w  = (const float*)d_in[2];
    const float* Wq_b  = (const float*)d_in[3];
    const float* Wkv_w = (const float*)d_in[4];
    const float* Wkv_b = (const float*)d_in[5];
    const float* gz    = (const float*)d_in[6];
    const float* W1    = (const float*)d_in[7];
    const float* b1    = (const float*)d_in[8];
    const float* W2    = (const float*)d_in[9];
    const float* b2    = (const float*)d_in[10];
    float* out = (float*)d_out;

    k_rms_x   <<<S_LEN, 256>>>(x, gin);
    k_qproj   <<<dim3(NQ / BN,     S_LEN / BM), 256>>>(Wq_w);
    k_bias_q  <<<(S_LEN * NQ) / 256, 256>>>(Wq_b);
    k_kvproj  <<<dim3(NKV / BN,    S_LEN / BM), 256>>>(Wkv_w);
    k_bias_kv <<<(S_LEN * NKV) / 256, 256>>>(Wkv_b);
    k_vt_build<<<(G_GRP * DVV * S_LEN) / 256, 256>>>();
    k_scores  <<<dim3(S_LEN / BN,  S_LEN / BM, G_GRP * H_HEADS), 256>>>();
    k_softmax <<<G_GRP * H_HEADS * S_LEN, 256>>>();
    k_pv      <<<dim3(DVV / BN,    S_LEN / BM, G_GRP * H_HEADS), 256>>>();
    k_rms_z   <<<S_LEN, 256>>>(gz);
    k_ffn1    <<<dim3(FF2 / BN,    S_LEN / BM), 256>>>(W1);
    k_silu_h1 <<<(S_LEN * FF2) / 256, 256>>>(b1);
    k_ffn2    <<<dim3(FF_OUT / BN, S_LEN / BM), 256>>>(W2, out);
    k_silu_out<<<(S_LEN * FF_OUT) / 256, 256>>>(out, b2);
}

// round 6
// speedup vs baseline: 2.4905x; 1.4098x over previous
#include <cuda_runtime.h>
#include <cuda_bf16.h>
#include <math.h>
#include <stdint.h>

// ---------------- problem constants ----------------
#define S_LEN   1024
#define D_MODEL 1024
#define G_GRP   8
#define H_HEADS 16
#define DQK     128
#define DVV     128
#define FF_OUT  1024
#define NQ      (G_GRP*H_HEADS*DQK)    /* 16384 */
#define NKV     (G_GRP*(DQK+DVV))      /* 2048  */
#define NKHALF  (G_GRP*DQK)            /* 1024  */
#define ZD      NQ                     /* 16384 */
#define FF2     (2*FF_OUT)             /* 2048  */
#define ATT_SCALE 0.08838834764831845f /* 1/sqrt(128) */

typedef __nv_bfloat16 bf16;

// ---------------- scratch (device globals; referenced ONLY in device code) ---
// (passing these as kernel args from host passes the host shadow — R2-R4 bug)
__device__ __align__(256) float g_q[S_LEN*NQ];
__device__ __align__(256) float g_kv[S_LEN*NKV];
__device__ __align__(256) float g_scores[134217728];   // G*H*S*S fp32
__device__ __align__(256) float g_z[S_LEN*ZD];
__device__ __align__(256) float g_h1[S_LEN*FF2];

// bf16 hi/lo split operands
__device__ __align__(256) bf16 xh [S_LEN*D_MODEL],  xl [S_LEN*D_MODEL];
__device__ __align__(256) bf16 wqh[NQ*D_MODEL],     wql[NQ*D_MODEL];
__device__ __align__(256) bf16 wkh[NKV*D_MODEL],    wkl[NKV*D_MODEL];
__device__ __align__(256) bf16 qh [S_LEN*NQ],       ql [S_LEN*NQ];
__device__ __align__(256) bf16 kvh[S_LEN*NKV],      kvl[S_LEN*NKV];
__device__ __align__(256) bf16 vth[G_GRP*DVV*S_LEN],vtl[G_GRP*DVV*S_LEN];
__device__ __align__(256) bf16 ph [134217728],      pl [134217728];
__device__ __align__(256) bf16 zh [S_LEN*ZD],       zl [S_LEN*ZD];
__device__ __align__(256) bf16 w1h[FF2*ZD],         w1l[FF2*ZD];
__device__ __align__(256) bf16 h1h[S_LEN*FF2],      h1l[S_LEN*FF2];
__device__ __align__(256) bf16 w2h[FF_OUT*FF2],     w2l[FF_OUT*FF2];

// ---------------- helpers ----------------
__device__ __forceinline__ void split_store(bf16* dh, bf16* dl, size_t i, float v) {
    bf16 h = __float2bfloat16_rn(v);
    dh[i] = h;
    dl[i] = __float2bfloat16_rn(v - __bfloat162float(h));
}

// ---------------- rmsnorm (writes bf16 hi/lo) ----------------
__device__ __forceinline__ void rms_body(const float* __restrict__ in,
                                         const float* __restrict__ gamma,
                                         bf16* __restrict__ oh, bf16* __restrict__ ol,
                                         int cols)
{
    const float* x = in + (size_t)blockIdx.x * cols;
    size_t obase = (size_t)blockIdx.x * cols;
    float ss = 0.f;
    for (int c = threadIdx.x; c < cols; c += blockDim.x) { float v = x[c]; ss += v*v; }
    __shared__ float red[33];
    #pragma unroll
    for (int o = 16; o; o >>= 1) ss += __shfl_xor_sync(0xffffffffu, ss, o);
    if ((threadIdx.x & 31) == 0) red[threadIdx.x >> 5] = ss;
    __syncthreads();
    if (threadIdx.x < 32) {
        float v = (threadIdx.x < (blockDim.x >> 5)) ? red[threadIdx.x] : 0.f;
        #pragma unroll
        for (int o = 16; o; o >>= 1) v += __shfl_xor_sync(0xffffffffu, v, o);
        if (threadIdx.x == 0) red[32] = v;
    }
    __syncthreads();
    float scale = sqrtf((float)cols) / fmaxf(sqrtf(red[32]), 1e-12f);
    for (int c = threadIdx.x; c < cols; c += blockDim.x)
        split_store(oh, ol, obase + c, x[c] * scale * gamma[c]);
}

__global__ void k_rms_x(const float* __restrict__ x, const float* __restrict__ gamma) {
    rms_body(x, gamma, xh, xl, D_MODEL);
}
__global__ void k_rms_z(const float* __restrict__ gamma) {
    rms_body(g_z, gamma, zh, zl, ZD);
}

// ---------------- weight split (selector avoids passing device globals) -----
__global__ void k_split_w(const float* __restrict__ src, int which) {
    size_t i = (size_t)blockIdx.x * 256 + threadIdx.x;
    float v = src[i];
    switch (which) {
        case 0: split_store(wqh, wql, i, v); break;
        case 1: split_store(wkh, wkl, i, v); break;
        case 2: split_store(w1h, w1l, i, v); break;
        case 3: split_store(w2h, w2l, i, v); break;
    }
}

// ---------------- bf16 split mma GEMM with cp.async double buffering --------
// C(128x128 tile) = A(MxK) @ B(NxK)^T, A/B pre-split bf16 hi/lo.
// acc += Ah*Bh + Ah*Bl + Al*Bh  (fp32 accum)

__device__ __forceinline__ void mma_bf16(float* d, const uint32_t* a, uint32_t b0, uint32_t b1) {
    asm volatile(
        "mma.sync.aligned.m16n8k16.row.col.f32.bf16.bf16.f32 "
        "{%0,%1,%2,%3}, {%4,%5,%6,%7}, {%8,%9}, {%0,%1,%2,%3};"
        : "+f"(d[0]), "+f"(d[1]), "+f"(d[2]), "+f"(d[3])
        : "r"(a[0]), "r"(a[1]), "r"(a[2]), "r"(a[3]), "r"(b0), "r"(b1));
}

#define BM 128
#define BN 128
#define BK 32
#define LDP 20                       /* padded row width in uint32 words      */
#define ARR_W (BM*LDP)               /* words per array  = 2560 (10240 B)     */
#define STG_W (4*ARR_W)              /* words per stage  = 10240 (40960 B)    */
#define SMEM_BYTES (2*STG_W*4)       /* 81920 B dynamic                       */

__device__ __forceinline__ void cp16(uint32_t dst, const void* src) {
    asm volatile("cp.async.cg.shared.global [%0], [%1], 16;" :: "r"(dst), "l"(src));
}

__device__ __forceinline__ void stage_fill(
    uint32_t sbase,                     // shared byte address of stage start
    const bf16* __restrict__ Ah, const bf16* __restrict__ Al,
    const bf16* __restrict__ Bh, const bf16* __restrict__ Bl,
    int k0, int lda, int ldb)
{
    int tid = threadIdx.x;
    #pragma unroll
    for (int j = 0; j < 2; j++) {
        int chunk = tid + j * 256;            // 0..511
        int row = chunk >> 2;                 // 0..127
        int seg = chunk & 3;                  // 16B segment within 64B row
        uint32_t off = (uint32_t)(row * LDP * 4 + seg * 16);
        size_t a_off = (size_t)row * lda + k0 + seg * 8;
        size_t b_off = (size_t)row * ldb + k0 + seg * 8;
        cp16(sbase + 0u*ARR_W*4u + off, Ah + a_off);
        cp16(sbase + 1u*ARR_W*4u + off, Al + a_off);
        cp16(sbase + 2u*ARR_W*4u + off, Bh + b_off);
        cp16(sbase + 3u*ARR_W*4u + off, Bl + b_off);
    }
}

template<bool ATOMIC>
__device__ __forceinline__ void gemm_core(
    const bf16* __restrict__ Ah, const bf16* __restrict__ Al,
    const bf16* __restrict__ Bh, const bf16* __restrict__ Bl,
    float* __restrict__ C, int kbeg, int kend, int lda, int ldb, int ldc)
{
    extern __shared__ uint32_t sh[];
    const uint32_t sb = (uint32_t)__cvta_generic_to_shared(sh);

    const int tid  = threadIdx.x;
    const int wid  = tid >> 5;
    const int lane = tid & 31;
    const int grp  = lane >> 2;
    const int tig  = lane & 3;
    const int mbase = (wid & 3) * 32;
    const int nbase = (wid >> 2) * 64;

    const bf16* Abh = Ah + (size_t)blockIdx.y * BM * lda;
    const bf16* Abl = Al + (size_t)blockIdx.y * BM * lda;
    const bf16* Bbh = Bh + (size_t)blockIdx.x * BN * ldb;
    const bf16* Bbl = Bl + (size_t)blockIdx.x * BN * ldb;

    float acc[2][8][4];
    #pragma unroll
    for (int mi = 0; mi < 2; mi++)
        #pragma unroll
        for (int ni = 0; ni < 8; ni++)
            #pragma unroll
            for (int v = 0; v < 4; v++) acc[mi][ni][v] = 0.f;

    // prologue: stage 0
    stage_fill(sb, Abh, Abl, Bbh, Bbl, kbeg, lda, ldb);
    asm volatile("cp.async.commit_group;");

    int s = 0;
    for (int k0 = kbeg; k0 < kend; k0 += BK, s ^= 1) {
        if (k0 + BK < kend)
            stage_fill(sb + (uint32_t)(s ^ 1) * STG_W * 4u,
                       Abh, Abl, Bbh, Bbl, k0 + BK, lda, ldb);
        asm volatile("cp.async.commit_group;");
        asm volatile("cp.async.wait_group 1;");
        __syncthreads();

        const uint32_t* AsH = sh + s * STG_W;
        const uint32_t* AsL = AsH + ARR_W;
        const uint32_t* BsH = AsH + 2 * ARR_W;
        const uint32_t* BsL = AsH + 3 * ARR_W;

        #pragma unroll
        for (int kk = 0; kk < 16; kk += 8) {
            uint32_t aH[2][4], aL[2][4];
            #pragma unroll
            for (int mi = 0; mi < 2; mi++) {
                int r0 = mbase + mi * 16 + grp;
                aH[mi][0] = AsH[ r0      * LDP + kk + tig];
                aH[mi][1] = AsH[(r0 + 8) * LDP + kk + tig];
                aH[mi][2] = AsH[ r0      * LDP + kk + tig + 4];
                aH[mi][3] = AsH[(r0 + 8) * LDP + kk + tig + 4];
                aL[mi][0] = AsL[ r0      * LDP + kk + tig];
                aL[mi][1] = AsL[(r0 + 8) * LDP + kk + tig];
                aL[mi][2] = AsL[ r0      * LDP + kk + tig + 4];
                aL[mi][3] = AsL[(r0 + 8) * LDP + kk + tig + 4];
            }
            #pragma unroll
            for (int ni = 0; ni < 8; ni++) {
                int nr = (nbase + ni * 8 + grp) * LDP;
                uint32_t bh0 = BsH[nr + kk + tig];
                uint32_t bh1 = BsH[nr + kk + tig + 4];
                uint32_t bl0 = BsL[nr + kk + tig];
                uint32_t bl1 = BsL[nr + kk + tig + 4];
                #pragma unroll
                for (int mi = 0; mi < 2; mi++) {
                    mma_bf16(acc[mi][ni], aH[mi], bh0, bh1);
                    mma_bf16(acc[mi][ni], aH[mi], bl0, bl1);
                    mma_bf16(acc[mi][ni], aL[mi], bh0, bh1);
                }
            }
        }
        __syncthreads();
    }

    #pragma unroll
    for (int mi = 0; mi < 2; mi++)
        #pragma unroll
        for (int ni = 0; ni < 8; ni++) {
            int row = blockIdx.y * BM + mbase + mi * 16 + grp;
            int col = blockIdx.x * BN + nbase + ni * 8 + tig * 2;
            if (ATOMIC) {
                atomicAdd(&C[(size_t)row * ldc + col],           acc[mi][ni][0]);
                atomicAdd(&C[(size_t)row * ldc + col + 1],       acc[mi][ni][1]);
                atomicAdd(&C[(size_t)(row + 8) * ldc + col],     acc[mi][ni][2]);
                atomicAdd(&C[(size_t)(row + 8) * ldc + col + 1], acc[mi][ni][3]);
            } else {
                *(float2*)&C[(size_t)row * ldc + col] =
                    make_float2(acc[mi][ni][0], acc[mi][ni][1]);
                *(float2*)&C[(size_t)(row + 8) * ldc + col] =
                    make_float2(acc[mi][ni][2], acc[mi][ni][3]);
            }
        }
}

// ---------------- GEMM wrapper kernels ----------------
__global__ void __launch_bounds__(256, 2) k_qproj() {
    gemm_core<false>(xh, xl, wqh, wql, g_q, 0, D_MODEL, D_MODEL, D_MODEL, NQ);
}
__global__ void __launch_bounds__(256, 2) k_kvproj() {
    gemm_core<false>(xh, xl, wkh, wkl, g_kv, 0, D_MODEL, D_MODEL, D_MODEL, NKV);
}
__global__ void __launch_bounds__(256, 2) k_scores() {
    int batch = blockIdx.z;                 // g*H + h
    int g = batch >> 4;
    gemm_core<false>(qh + batch * DQK, ql + batch * DQK,
                     kvh + g * DQK,   kvl + g * DQK,
                     g_scores + (size_t)batch * S_LEN * S_LEN,
                     0, DQK, NQ, NKV, S_LEN);
}
__global__ void __launch_bounds__(256, 2) k_pv() {
    int batch = blockIdx.z;
    int g = batch >> 4;
    gemm_core<false>(ph + (size_t)batch * S_LEN * S_LEN,
                     pl + (size_t)batch * S_LEN * S_LEN,
                     vth + (size_t)g * DVV * S_LEN,
                     vtl + (size_t)g * DVV * S_LEN,
                     g_z + batch * DVV,
                     0, S_LEN, S_LEN, S_LEN, ZD);
}
__global__ void __launch_bounds__(256, 2) k_ffn1() {
    int kb = blockIdx.z * (ZD / 4);
    gemm_core<true>(zh, zl, w1h, w1l, g_h1, kb, kb + ZD / 4, ZD, ZD, FF2);
}
__global__ void __launch_bounds__(256, 2) k_ffn2(float* __restrict__ out) {
    int kb = blockIdx.z * (FF2 / 4);
    gemm_core<true>(h1h, h1l, w2h, w2l, out, kb, kb + FF2 / 4, FF2, FF2, FF_OUT);
}

// ---------------- elementwise epilogues ----------------
__global__ void k_bias_q(const float* __restrict__ bias) {     // + fold ATT_SCALE
    size_t i = (size_t)blockIdx.x * 256 + threadIdx.x;
    float v = (g_q[i] + bias[i & (NQ - 1)]) * ATT_SCALE;
    split_store(qh, ql, i, v);
}
__global__ void k_bias_kv(const float* __restrict__ bias) {
    size_t i = (size_t)blockIdx.x * 256 + threadIdx.x;
    float v = g_kv[i] + bias[i & (NKV - 1)];
    g_kv[i] = v;
    split_store(kvh, kvl, i, v);
}
__global__ void k_vt_build() {
    int idx = blockIdx.x * 256 + threadIdx.x;      // 0 .. G*DVV*S-1
    int t = idx & (S_LEN - 1);
    int d = (idx >> 10) & (DVV - 1);
    int g = idx >> 17;
    split_store(vth, vtl, idx, g_kv[(size_t)t * NKV + NKHALF + g * DVV + d]);
}
__global__ void k_zero_h1() {
    g_h1[(size_t)blockIdx.x * 256 + threadIdx.x] = 0.f;
}
__global__ void k_zero_out(float* __restrict__ out) {
    out[(size_t)blockIdx.x * 256 + threadIdx.x] = 0.f;
}
__global__ void k_silu_h1(const float* __restrict__ bias) {
    size_t i = (size_t)blockIdx.x * 256 + threadIdx.x;
    float v = g_h1[i] + bias[i & (FF2 - 1)];
    v = v / (1.f + __expf(-v));
    split_store(h1h, h1l, i, v);
}
__global__ void k_silu_out(float* __restrict__ C, const float* __restrict__ bias) {
    size_t i = (size_t)blockIdx.x * 256 + threadIdx.x;
    float v = C[i] + bias[i & (FF_OUT - 1)];
    C[i] = v / (1.f + __expf(-v));
}

// ---------------- row softmax over 1024 cols (q pre-scaled; writes hi/lo) ---
__global__ void k_softmax() {
    size_t rbase = (size_t)blockIdx.x * S_LEN;
    const float* row = g_scores + rbase;
    __shared__ float red[33];
    int tid = threadIdx.x;
    float vals[4];
    float m = -1e30f;
    #pragma unroll
    for (int i = 0; i < 4; i++) { vals[i] = row[tid + i * 256]; m = fmaxf(m, vals[i]); }
    #pragma unroll
    for (int o = 16; o; o >>= 1) m = fmaxf(m, __shfl_xor_sync(0xffffffffu, m, o));
    if ((tid & 31) == 0) red[tid >> 5] = m;
    __syncthreads();
    if (tid < 32) {
        float v = (tid < 8) ? red[tid] : -1e30f;
        #pragma unroll
        for (int o = 4; o; o >>= 1) v = fmaxf(v, __shfl_xor_sync(0xffffffffu, v, o));
        if (tid == 0) red[32] = v;
    }
    __syncthreads();
    m = red[32];
    __syncthreads();
    float s = 0.f;
    #pragma unroll
    for (int i = 0; i < 4; i++) { vals[i] = __expf(vals[i] - m); s += vals[i]; }
    #pragma unroll
    for (int o = 16; o; o >>= 1) s += __shfl_xor_sync(0xffffffffu, s, o);
    if ((tid & 31) == 0) red[tid >> 5] = s;
    __syncthreads();
    if (tid < 32) {
        float v = (tid < 8) ? red[tid] : 0.f;
        #pragma unroll
        for (int o = 4; o; o >>= 1) v += __shfl_xor_sync(0xffffffffu, v, o);
        if (tid == 0) red[32] = v;
    }
    __syncthreads();
    float inv = 1.f / red[32];
    #pragma unroll
    for (int i = 0; i < 4; i++)
        split_store(ph, pl, rbase + tid + i * 256, vals[i] * inv);
}

// ---------------- launch ----------------
extern "C" void kernel_launch(void* const* d_in, const int* in_sizes, int n_in,
                              void* d_out, int out_size) {
    const float* x     = (const float*)d_in[0];
    const float* gin   = (const float*)d_in[1];
    const float* Wq_w  = (const float*)d_in[2];
    const float* Wq_b  = (const float*)d_in[3];
    const float* Wkv_w = (const float*)d_in[4];
    const float* Wkv_b = (const float*)d_in[5];
    const float* gz    = (const float*)d_in[6];
    const float* W1    = (const float*)d_in[7];
    const float* b1    = (const float*)d_in[8];
    const float* W2    = (const float*)d_in[9];
    const float* b2    = (const float*)d_in[10];
    float* out = (float*)d_out;

    cudaFuncSetAttribute(k_qproj,  cudaFuncAttributeMaxDynamicSharedMemorySize, SMEM_BYTES);
    cudaFuncSetAttribute(k_kvproj, cudaFuncAttributeMaxDynamicSharedMemorySize, SMEM_BYTES);
    cudaFuncSetAttribute(k_scores, cudaFuncAttributeMaxDynamicSharedMemorySize, SMEM_BYTES);
    cudaFuncSetAttribute(k_pv,     cudaFuncAttributeMaxDynamicSharedMemorySize, SMEM_BYTES);
    cudaFuncSetAttribute(k_ffn1,   cudaFuncAttributeMaxDynamicSharedMemorySize, SMEM_BYTES);
    cudaFuncSetAttribute(k_ffn2,   cudaFuncAttributeMaxDynamicSharedMemorySize, SMEM_BYTES);

    k_rms_x   <<<S_LEN, 256>>>(x, gin);
    k_split_w <<<(NQ * D_MODEL) / 256, 256>>>(Wq_w, 0);
    k_split_w <<<(NKV * D_MODEL) / 256, 256>>>(Wkv_w, 1);
    k_split_w <<<(FF2 * ZD) / 256, 256>>>(W1, 2);
    k_split_w <<<(FF_OUT * FF2) / 256, 256>>>(W2, 3);

    k_qproj   <<<dim3(NQ / BN,     S_LEN / BM), 256, SMEM_BYTES>>>();
    k_bias_q  <<<(S_LEN * NQ) / 256, 256>>>(Wq_b);
    k_kvproj  <<<dim3(NKV / BN,    S_LEN / BM), 256, SMEM_BYTES>>>();
    k_bias_kv <<<(S_LEN * NKV) / 256, 256>>>(Wkv_b);
    k_vt_build<<<(G_GRP * DVV * S_LEN) / 256, 256>>>();

    k_scores  <<<dim3(S_LEN / BN,  S_LEN / BM, G_GRP * H_HEADS), 256, SMEM_BYTES>>>();
    k_softmax <<<G_GRP * H_HEADS * S_LEN, 256>>>();
    k_pv      <<<dim3(1,           S_LEN / BM, G_GRP * H_HEADS), 256, SMEM_BYTES>>>();

    k_rms_z   <<<S_LEN, 256>>>(gz);
    k_zero_h1 <<<(S_LEN * FF2) / 256, 256>>>();
    k_ffn1    <<<dim3(FF2 / BN,    S_LEN / BM, 4), 256, SMEM_BYTES>>>();
    k_silu_h1 <<<(S_LEN * FF2) / 256, 256>>>(b1);
    k_zero_out<<<(S_LEN * FF_OUT) / 256, 256>>>(out);
    k_ffn2    <<<dim3(FF_OUT / BN, S_LEN / BM, 4), 256, SMEM_BYTES>>>(out);
    k_silu_out<<<(S_LEN * FF_OUT) / 256, 256>>>(out, b2);
}

// round 7
// speedup vs baseline: 2.8352x; 1.1384x over previous
#include <cuda_runtime.h>
#include <cuda_bf16.h>
#include <math.h>
#include <stdint.h>

// ---------------- problem constants ----------------
#define S_LEN   1024
#define D_MODEL 1024
#define G_GRP   8
#define H_HEADS 16
#define DQK     128
#define DVV     128
#define FF_OUT  1024
#define NQ      (G_GRP*H_HEADS*DQK)    /* 16384 */
#define NKV     (G_GRP*(DQK+DVV))      /* 2048  */
#define NKHALF  (G_GRP*DQK)            /* 1024  */
#define ZD      NQ                     /* 16384 */
#define FF2     (2*FF_OUT)             /* 2048  */
#define ATT_SCALE 0.08838834764831845f /* 1/sqrt(128) */

typedef __nv_bfloat16 bf16;

// ---------------- scratch (device globals; referenced ONLY in device code) ---
// (passing these as kernel args from host passes the host shadow — R2-R4 bug)
__device__ __align__(256) float g_q[S_LEN*NQ];
__device__ __align__(256) float g_kv[S_LEN*NKV];
__device__ __align__(256) float g_scores[134217728];   // G*H*S*S fp32
__device__ __align__(256) float g_z[S_LEN*ZD];
__device__ __align__(256) float g_h1[S_LEN*FF2];

// bf16 hi/lo split operands
__device__ __align__(256) bf16 xh [S_LEN*D_MODEL],  xl [S_LEN*D_MODEL];
__device__ __align__(256) bf16 wqh[NQ*D_MODEL],     wql[NQ*D_MODEL];
__device__ __align__(256) bf16 wkh[NKV*D_MODEL],    wkl[NKV*D_MODEL];
__device__ __align__(256) bf16 qh [S_LEN*NQ],       ql [S_LEN*NQ];
__device__ __align__(256) bf16 kvh[S_LEN*NKV],      kvl[S_LEN*NKV];
__device__ __align__(256) bf16 vth[G_GRP*DVV*S_LEN],vtl[G_GRP*DVV*S_LEN];
__device__ __align__(256) bf16 ph [134217728],      pl [134217728];
__device__ __align__(256) bf16 zh [S_LEN*ZD],       zl [S_LEN*ZD];
__device__ __align__(256) bf16 w1h[FF2*ZD],         w1l[FF2*ZD];
__device__ __align__(256) bf16 h1h[S_LEN*FF2],      h1l[S_LEN*FF2];
__device__ __align__(256) bf16 w2h[FF_OUT*FF2],     w2l[FF_OUT*FF2];

// ---------------- helpers ----------------
__device__ __forceinline__ uint32_t pack2bf(float x, float y) {
    __nv_bfloat162 p = __floats2bfloat162_rn(x, y);
    return *reinterpret_cast<uint32_t*>(&p);
}
__device__ __forceinline__ void split_store(bf16* dh, bf16* dl, size_t i, float v) {
    bf16 h = __float2bfloat16_rn(v);
    dh[i] = h;
    dl[i] = __float2bfloat16_rn(v - __bfloat162float(h));
}
// packed: split 4 consecutive floats -> uint2 writes to dh/dl (i4 must be 4-aligned)
__device__ __forceinline__ void split4(bf16* dh, bf16* dl, size_t i4, float4 v) {
    float hx = __bfloat162float(__float2bfloat16_rn(v.x));
    float hy = __bfloat162float(__float2bfloat16_rn(v.y));
    float hz = __bfloat162float(__float2bfloat16_rn(v.z));
    float hw = __bfloat162float(__float2bfloat16_rn(v.w));
    *(uint2*)(dh + i4) = make_uint2(pack2bf(hx, hy), pack2bf(hz, hw));
    *(uint2*)(dl + i4) = make_uint2(pack2bf(v.x - hx, v.y - hy), pack2bf(v.z - hz, v.w - hw));
}

// ---------------- rmsnorm (writes bf16 hi/lo, vectorized) ----------------
__device__ __forceinline__ void rms_body(const float* __restrict__ in,
                                         const float* __restrict__ gamma,
                                         bf16* __restrict__ oh, bf16* __restrict__ ol,
                                         int cols)
{
    const float4* x4 = (const float4*)(in + (size_t)blockIdx.x * cols);
    const float4* g4 = (const float4*)gamma;
    size_t obase = (size_t)blockIdx.x * cols;
    int nv = cols >> 2;
    float ss = 0.f;
    for (int c = threadIdx.x; c < nv; c += blockDim.x) {
        float4 v = x4[c];
        ss += v.x*v.x + v.y*v.y + v.z*v.z + v.w*v.w;
    }
    __shared__ float red[33];
    #pragma unroll
    for (int o = 16; o; o >>= 1) ss += __shfl_xor_sync(0xffffffffu, ss, o);
    if ((threadIdx.x & 31) == 0) red[threadIdx.x >> 5] = ss;
    __syncthreads();
    if (threadIdx.x < 32) {
        float v = (threadIdx.x < (blockDim.x >> 5)) ? red[threadIdx.x] : 0.f;
        #pragma unroll
        for (int o = 16; o; o >>= 1) v += __shfl_xor_sync(0xffffffffu, v, o);
        if (threadIdx.x == 0) red[32] = v;
    }
    __syncthreads();
    float scale = sqrtf((float)cols) / fmaxf(sqrtf(red[32]), 1e-12f);
    for (int c = threadIdx.x; c < nv; c += blockDim.x) {
        float4 v = x4[c];
        float4 g = g4[c];
        v.x *= scale * g.x; v.y *= scale * g.y; v.z *= scale * g.z; v.w *= scale * g.w;
        split4(oh, ol, obase + (size_t)c * 4, v);
    }
}

__global__ void k_rms_x(const float* __restrict__ x, const float* __restrict__ gamma) {
    rms_body(x, gamma, xh, xl, D_MODEL);
}
__global__ void k_rms_z(const float* __restrict__ gamma) {
    rms_body(g_z, gamma, zh, zl, ZD);
}

// ---------------- weight split (vectorized) ----------------
__global__ void k_split_w(const float* __restrict__ src, int which) {
    size_t i4 = ((size_t)blockIdx.x * 256 + threadIdx.x) * 4;
    float4 v = *(const float4*)(src + i4);
    switch (which) {
        case 0: split4(wqh, wql, i4, v); break;
        case 1: split4(wkh, wkl, i4, v); break;
        case 2: split4(w1h, w1l, i4, v); break;
        case 3: split4(w2h, w2l, i4, v); break;
    }
}

// ---------------- bf16 split mma GEMM, cp.async double buffer + ldmatrix ----
// C(128x128 tile) = A(MxK)@B(NxK)^T ; acc += Ah*Bh + Ah*Bl + Al*Bh (fp32)

__device__ __forceinline__ void mma_bf16(float* d, const uint32_t* a, uint32_t b0, uint32_t b1) {
    asm volatile(
        "mma.sync.aligned.m16n8k16.row.col.f32.bf16.bf16.f32 "
        "{%0,%1,%2,%3}, {%4,%5,%6,%7}, {%8,%9}, {%0,%1,%2,%3};"
        : "+f"(d[0]), "+f"(d[1]), "+f"(d[2]), "+f"(d[3])
        : "r"(a[0]), "r"(a[1]), "r"(a[2]), "r"(a[3]), "r"(b0), "r"(b1));
}
__device__ __forceinline__ void ldsm_x4(uint32_t* r, uint32_t saddr) {
    asm volatile("ldmatrix.sync.aligned.m8n8.x4.shared.b16 {%0,%1,%2,%3}, [%4];"
        : "=r"(r[0]), "=r"(r[1]), "=r"(r[2]), "=r"(r[3]) : "r"(saddr));
}

#define BM 128
#define BN 128
#define BK 32
#define LDP 20                       /* padded row width in uint32 words      */
#define ARR_W (BM*LDP)               /* words per array  = 2560 (10240 B)     */
#define STG_W (4*ARR_W)              /* words per stage  = 10240 (40960 B)    */
#define SMEM_BYTES (2*STG_W*4)       /* 81920 B dynamic                       */

__device__ __forceinline__ void cp16(uint32_t dst, const void* src) {
    asm volatile("cp.async.cg.shared.global [%0], [%1], 16;" :: "r"(dst), "l"(src));
}

__device__ __forceinline__ void stage_fill(
    uint32_t sbase,
    const bf16* __restrict__ Ah, const bf16* __restrict__ Al,
    const bf16* __restrict__ Bh, const bf16* __restrict__ Bl,
    int k0, int lda, int ldb)
{
    int tid = threadIdx.x;
    #pragma unroll
    for (int j = 0; j < 2; j++) {
        int chunk = tid + j * 256;            // 0..511
        int row = chunk >> 2;                 // 0..127
        int seg = chunk & 3;                  // 16B segment within 64B row
        uint32_t off = (uint32_t)(row * LDP * 4 + seg * 16);
        size_t a_off = (size_t)row * lda + k0 + seg * 8;
        size_t b_off = (size_t)row * ldb + k0 + seg * 8;
        cp16(sbase + 0u*ARR_W*4u + off, Ah + a_off);
        cp16(sbase + 1u*ARR_W*4u + off, Al + a_off);
        cp16(sbase + 2u*ARR_W*4u + off, Bh + b_off);
        cp16(sbase + 3u*ARR_W*4u + off, Bl + b_off);
    }
}

template<bool ATOMIC>
__device__ __forceinline__ void gemm_core(
    const bf16* __restrict__ Ah, const bf16* __restrict__ Al,
    const bf16* __restrict__ Bh, const bf16* __restrict__ Bl,
    float* __restrict__ C, int kbeg, int kend, int lda, int ldb, int ldc)
{
    extern __shared__ uint32_t sh[];
    const uint32_t sb = (uint32_t)__cvta_generic_to_shared(sh);

    const int tid  = threadIdx.x;
    const int wid  = tid >> 5;
    const int lane = tid & 31;
    const int grp  = lane >> 2;
    const int tig  = lane & 3;
    const int mbase = (wid & 3) * 32;
    const int nbase = (wid >> 2) * 64;

    const bf16* Abh = Ah + (size_t)blockIdx.y * BM * lda;
    const bf16* Abl = Al + (size_t)blockIdx.y * BM * lda;
    const bf16* Bbh = Bh + (size_t)blockIdx.x * BN * ldb;
    const bf16* Bbl = Bl + (size_t)blockIdx.x * BN * ldb;

    // ldmatrix per-lane word offsets (within an array)
    const int a_off = (mbase + (lane & 15)) * LDP + ((lane & 16) ? 4 : 0);
    const int b_off = (nbase + ((lane >> 4) * 8) + (lane & 7)) * LDP + ((lane & 8) ? 4 : 0);

    float acc[2][8][4];
    #pragma unroll
    for (int mi = 0; mi < 2; mi++)
        #pragma unroll
        for (int ni = 0; ni < 8; ni++)
            #pragma unroll
            for (int v = 0; v < 4; v++) acc[mi][ni][v] = 0.f;

    stage_fill(sb, Abh, Abl, Bbh, Bbl, kbeg, lda, ldb);
    asm volatile("cp.async.commit_group;");

    int s = 0;
    for (int k0 = kbeg; k0 < kend; k0 += BK, s ^= 1) {
        if (k0 + BK < kend)
            stage_fill(sb + (uint32_t)(s ^ 1) * STG_W * 4u,
                       Abh, Abl, Bbh, Bbl, k0 + BK, lda, ldb);
        asm volatile("cp.async.commit_group;");
        asm volatile("cp.async.wait_group 1;");
        __syncthreads();

        const uint32_t stg = sb + (uint32_t)s * STG_W * 4u;
        #pragma unroll
        for (int kk = 0; kk < 16; kk += 8) {
            uint32_t aH[2][4], aL[2][4];
            ldsm_x4(aH[0], stg + 0u*ARR_W*4u + (uint32_t)(a_off + kk) * 4u);
            ldsm_x4(aH[1], stg + 0u*ARR_W*4u + (uint32_t)(a_off + kk + 16*LDP) * 4u);
            ldsm_x4(aL[0], stg + 1u*ARR_W*4u + (uint32_t)(a_off + kk) * 4u);
            ldsm_x4(aL[1], stg + 1u*ARR_W*4u + (uint32_t)(a_off + kk + 16*LDP) * 4u);
            #pragma unroll
            for (int ni2 = 0; ni2 < 4; ni2++) {
                uint32_t bH4[4], bL4[4];
                ldsm_x4(bH4, stg + 2u*ARR_W*4u + (uint32_t)(b_off + kk + ni2*16*LDP) * 4u);
                ldsm_x4(bL4, stg + 3u*ARR_W*4u + (uint32_t)(b_off + kk + ni2*16*LDP) * 4u);
                #pragma unroll
                for (int h = 0; h < 2; h++) {
                    int ni = ni2 * 2 + h;
                    #pragma unroll
                    for (int mi = 0; mi < 2; mi++) {
                        mma_bf16(acc[mi][ni], aH[mi], bH4[h*2], bH4[h*2+1]);
                        mma_bf16(acc[mi][ni], aH[mi], bL4[h*2], bL4[h*2+1]);
                        mma_bf16(acc[mi][ni], aL[mi], bH4[h*2], bH4[h*2+1]);
                    }
                }
            }
        }
        __syncthreads();
    }

    #pragma unroll
    for (int mi = 0; mi < 2; mi++)
        #pragma unroll
        for (int ni = 0; ni < 8; ni++) {
            int row = blockIdx.y * BM + mbase + mi * 16 + grp;
            int col = blockIdx.x * BN + nbase + ni * 8 + tig * 2;
            if (ATOMIC) {
                atomicAdd(&C[(size_t)row * ldc + col],           acc[mi][ni][0]);
                atomicAdd(&C[(size_t)row * ldc + col + 1],       acc[mi][ni][1]);
                atomicAdd(&C[(size_t)(row + 8) * ldc + col],     acc[mi][ni][2]);
                atomicAdd(&C[(size_t)(row + 8) * ldc + col + 1], acc[mi][ni][3]);
            } else {
                *(float2*)&C[(size_t)row * ldc + col] =
                    make_float2(acc[mi][ni][0], acc[mi][ni][1]);
                *(float2*)&C[(size_t)(row + 8) * ldc + col] =
                    make_float2(acc[mi][ni][2], acc[mi][ni][3]);
            }
        }
}

// ---------------- GEMM wrapper kernels ----------------
__global__ void __launch_bounds__(256, 2) k_qproj() {
    gemm_core<false>(xh, xl, wqh, wql, g_q, 0, D_MODEL, D_MODEL, D_MODEL, NQ);
}
__global__ void __launch_bounds__(256, 2) k_kvproj() {
    gemm_core<false>(xh, xl, wkh, wkl, g_kv, 0, D_MODEL, D_MODEL, D_MODEL, NKV);
}
__global__ void __launch_bounds__(256, 2) k_scores() {
    int batch = blockIdx.z;                 // g*H + h
    int g = batch >> 4;
    gemm_core<false>(qh + batch * DQK, ql + batch * DQK,
                     kvh + g * DQK,   kvl + g * DQK,
                     g_scores + (size_t)batch * S_LEN * S_LEN,
                     0, DQK, NQ, NKV, S_LEN);
}
__global__ void __launch_bounds__(256, 2) k_pv() {
    int batch = blockIdx.z;
    int g = batch >> 4;
    gemm_core<false>(ph + (size_t)batch * S_LEN * S_LEN,
                     pl + (size_t)batch * S_LEN * S_LEN,
                     vth + (size_t)g * DVV * S_LEN,
                     vtl + (size_t)g * DVV * S_LEN,
                     g_z + batch * DVV,
                     0, S_LEN, S_LEN, S_LEN, ZD);
}
__global__ void __launch_bounds__(256, 2) k_ffn1() {
    int kb = blockIdx.z * (ZD / 4);
    gemm_core<true>(zh, zl, w1h, w1l, g_h1, kb, kb + ZD / 4, ZD, ZD, FF2);
}
__global__ void __launch_bounds__(256, 2) k_ffn2(float* __restrict__ out) {
    int kb = blockIdx.z * (FF2 / 4);
    gemm_core<true>(h1h, h1l, w2h, w2l, out, kb, kb + FF2 / 4, FF2, FF2, FF_OUT);
}

// ---------------- elementwise epilogues (vectorized) ----------------
__global__ void k_bias_q(const float* __restrict__ bias) {     // + fold ATT_SCALE
    size_t i4 = ((size_t)blockIdx.x * 256 + threadIdx.x) * 4;
    float4 v = *(const float4*)(g_q + i4);
    float4 b = *(const float4*)(bias + (i4 & (NQ - 1)));
    v.x = (v.x + b.x) * ATT_SCALE; v.y = (v.y + b.y) * ATT_SCALE;
    v.z = (v.z + b.z) * ATT_SCALE; v.w = (v.w + b.w) * ATT_SCALE;
    split4(qh, ql, i4, v);
}
__global__ void k_bias_kv(const float* __restrict__ bias) {
    size_t i4 = ((size_t)blockIdx.x * 256 + threadIdx.x) * 4;
    float4 v = *(const float4*)(g_kv + i4);
    float4 b = *(const float4*)(bias + (i4 & (NKV - 1)));
    v.x += b.x; v.y += b.y; v.z += b.z; v.w += b.w;
    *(float4*)(g_kv + i4) = v;
    split4(kvh, kvl, i4, v);
}
// tiled transpose: vt[g][d][t] = kv[t][NKHALF + g*128 + d]
__global__ void k_vt_build() {
    __shared__ float tile[32][33];
    int t0 = blockIdx.x * 32, d0 = blockIdx.y * 32, g = blockIdx.z;
    #pragma unroll
    for (int j = 0; j < 4; j++) {
        int t = t0 + threadIdx.y + 8 * j;
        tile[threadIdx.y + 8 * j][threadIdx.x] =
            g_kv[(size_t)t * NKV + NKHALF + g * DVV + d0 + threadIdx.x];
    }
    __syncthreads();
    #pragma unroll
    for (int j = 0; j < 4; j++) {
        int d = d0 + threadIdx.y + 8 * j;
        split_store(vth, vtl,
                    ((size_t)g * DVV + d) * S_LEN + t0 + threadIdx.x,
                    tile[threadIdx.x][threadIdx.y + 8 * j]);
    }
}
__global__ void k_zero_h1() {
    size_t i4 = ((size_t)blockIdx.x * 256 + threadIdx.x) * 4;
    *(float4*)(g_h1 + i4) = make_float4(0.f, 0.f, 0.f, 0.f);
}
__global__ void k_zero_out(float* __restrict__ out) {
    size_t i4 = ((size_t)blockIdx.x * 256 + threadIdx.x) * 4;
    *(float4*)(out + i4) = make_float4(0.f, 0.f, 0.f, 0.f);
}
__global__ void k_silu_h1(const float* __restrict__ bias) {
    size_t i4 = ((size_t)blockIdx.x * 256 + threadIdx.x) * 4;
    float4 v = *(const float4*)(g_h1 + i4);
    float4 b = *(const float4*)(bias + (i4 & (FF2 - 1)));
    v.x += b.x; v.y += b.y; v.z += b.z; v.w += b.w;
    v.x /= (1.f + __expf(-v.x)); v.y /= (1.f + __expf(-v.y));
    v.z /= (1.f + __expf(-v.z)); v.w /= (1.f + __expf(-v.w));
    split4(h1h, h1l, i4, v);
}
__global__ void k_silu_out(float* __restrict__ C, const float* __restrict__ bias) {
    size_t i4 = ((size_t)blockIdx.x * 256 + threadIdx.x) * 4;
    float4 v = *(const float4*)(C + i4);
    float4 b = *(const float4*)(bias + (i4 & (FF_OUT - 1)));
    v.x += b.x; v.y += b.y; v.z += b.z; v.w += b.w;
    v.x /= (1.f + __expf(-v.x)); v.y /= (1.f + __expf(-v.y));
    v.z /= (1.f + __expf(-v.z)); v.w /= (1.f + __expf(-v.w));
    *(float4*)(C + i4) = v;
}

// ---------------- row softmax over 1024 cols (q pre-scaled; writes hi/lo) ---
__global__ void k_softmax() {
    size_t rbase = (size_t)blockIdx.x * S_LEN;
    const float4* row4 = (const float4*)(g_scores + rbase);
    __shared__ float red[33];
    int tid = threadIdx.x;
    float4 v = row4[tid];
    float m = fmaxf(fmaxf(v.x, v.y), fmaxf(v.z, v.w));
    #pragma unroll
    for (int o = 16; o; o >>= 1) m = fmaxf(m, __shfl_xor_sync(0xffffffffu, m, o));
    if ((tid & 31) == 0) red[tid >> 5] = m;
    __syncthreads();
    if (tid < 32) {
        float t = (tid < 8) ? red[tid] : -1e30f;
        #pragma unroll
        for (int o = 4; o; o >>= 1) t = fmaxf(t, __shfl_xor_sync(0xffffffffu, t, o));
        if (tid == 0) red[32] = t;
    }
    __syncthreads();
    m = red[32];
    __syncthreads();
    v.x = __expf(v.x - m); v.y = __expf(v.y - m);
    v.z = __expf(v.z - m); v.w = __expf(v.w - m);
    float s = v.x + v.y + v.z + v.w;
    #pragma unroll
    for (int o = 16; o; o >>= 1) s += __shfl_xor_sync(0xffffffffu, s, o);
    if ((tid & 31) == 0) red[tid >> 5] = s;
    __syncthreads();
    if (tid < 32) {
        float t = (tid < 8) ? red[tid] : 0.f;
        #pragma unroll
        for (int o = 4; o; o >>= 1) t += __shfl_xor_sync(0xffffffffu, t, o);
        if (tid == 0) red[32] = t;
    }
    __syncthreads();
    float inv = 1.f / red[32];
    v.x *= inv; v.y *= inv; v.z *= inv; v.w *= inv;
    split4(ph, pl, rbase + (size_t)tid * 4, v);
}

// ---------------- launch ----------------
extern "C" void kernel_launch(void* const* d_in, const int* in_sizes, int n_in,
                              void* d_out, int out_size) {
    const float* x     = (const float*)d_in[0];
    const float* gin   = (const float*)d_in[1];
    const float* Wq_w  = (const float*)d_in[2];
    const float* Wq_b  = (const float*)d_in[3];
    const float* Wkv_w = (const float*)d_in[4];
    const float* Wkv_b = (const float*)d_in[5];
    const float* gz    = (const float*)d_in[6];
    const float* W1    = (const float*)d_in[7];
    const float* b1    = (const float*)d_in[8];
    const float* W2    = (const float*)d_in[9];
    const float* b2    = (const float*)d_in[10];
    float* out = (float*)d_out;

    cudaFuncSetAttribute(k_qproj,  cudaFuncAttributeMaxDynamicSharedMemorySize, SMEM_BYTES);
    cudaFuncSetAttribute(k_kvproj, cudaFuncAttributeMaxDynamicSharedMemorySize, SMEM_BYTES);
    cudaFuncSetAttribute(k_scores, cudaFuncAttributeMaxDynamicSharedMemorySize, SMEM_BYTES);
    cudaFuncSetAttribute(k_pv,     cudaFuncAttributeMaxDynamicSharedMemorySize, SMEM_BYTES);
    cudaFuncSetAttribute(k_ffn1,   cudaFuncAttributeMaxDynamicSharedMemorySize, SMEM_BYTES);
    cudaFuncSetAttribute(k_ffn2,   cudaFuncAttributeMaxDynamicSharedMemorySize, SMEM_BYTES);

    k_rms_x   <<<S_LEN, 256>>>(x, gin);
    k_split_w <<<(NQ * D_MODEL) / 1024, 256>>>(Wq_w, 0);
    k_split_w <<<(NKV * D_MODEL) / 1024, 256>>>(Wkv_w, 1);
    k_split_w <<<(FF2 * ZD) / 1024, 256>>>(W1, 2);
    k_split_w <<<(FF_OUT * FF2) / 1024, 256>>>(W2, 3);

    k_qproj   <<<dim3(NQ / BN,     S_LEN / BM), 256, SMEM_BYTES>>>();
    k_bias_q  <<<(S_LEN * NQ) / 1024, 256>>>(Wq_b);
    k_kvproj  <<<dim3(NKV / BN,    S_LEN / BM), 256, SMEM_BYTES>>>();
    k_bias_kv <<<(S_LEN * NKV) / 1024, 256>>>(Wkv_b);
    k_vt_build<<<dim3(S_LEN / 32, DVV / 32, G_GRP), dim3(32, 8)>>>();

    k_scores  <<<dim3(S_LEN / BN,  S_LEN / BM, G_GRP * H_HEADS), 256, SMEM_BYTES>>>();
    k_softmax <<<G_GRP * H_HEADS * S_LEN, 256>>>();
    k_pv      <<<dim3(1,           S_LEN / BM, G_GRP * H_HEADS), 256, SMEM_BYTES>>>();

    k_rms_z   <<<S_LEN, 256>>>(gz);
    k_zero_h1 <<<(S_LEN * FF2) / 1024, 256>>>();
    k_ffn1    <<<dim3(FF2 / BN,    S_LEN / BM, 4), 256, SMEM_BYTES>>>();
    k_silu_h1 <<<(S_LEN * FF2) / 1024, 256>>>(b1);
    k_zero_out<<<(S_LEN * FF_OUT) / 1024, 256>>>(out);
    k_ffn2    <<<dim3(FF_OUT / BN, S_LEN / BM, 4), 256, SMEM_BYTES>>>(out);
    k_silu_out<<<(S_LEN * FF_OUT) / 1024, 256>>>(out, b2);
}

// round 10
// speedup vs baseline: 2.8426x; 1.0026x over previous
#include <cuda_runtime.h>
#include <cuda_bf16.h>
#include <math.h>
#include <stdint.h>

// ---------------- problem constants ----------------
#define S_LEN   1024
#define D_MODEL 1024
#define G_GRP   8
#define H_HEADS 16
#define DQK     128
#define DVV     128
#define FF_OUT  1024
#define NQ      (G_GRP*H_HEADS*DQK)    /* 16384 */
#define NKV     (G_GRP*(DQK+DVV))      /* 2048  */
#define NKHALF  (G_GRP*DQK)            /* 1024  */
#define ZD      NQ                     /* 16384 */
#define FF2     (2*FF_OUT)             /* 2048  */
#define ATT_SCALE 0.08838834764831845f /* 1/sqrt(128) */

typedef __nv_bfloat16 bf16;

// ---------------- scratch (device globals; referenced ONLY in device code) ---
// (passing these as kernel args from host passes the host shadow — R2-R4 bug)
__device__ __align__(256) float g_kv[S_LEN*NKV];
__device__ __align__(256) float g_scores[134217728];   // G*H*S*S fp32
__device__ __align__(256) float g_z[S_LEN*ZD];
__device__ __align__(256) float g_h1[S_LEN*FF2];

// bf16 hi/lo split operands
__device__ __align__(256) bf16 xh [S_LEN*D_MODEL],  xl [S_LEN*D_MODEL];
__device__ __align__(256) bf16 wqh[NQ*D_MODEL],     wql[NQ*D_MODEL];
__device__ __align__(256) bf16 wkh[NKV*D_MODEL],    wkl[NKV*D_MODEL];
__device__ __align__(256) bf16 qh [S_LEN*NQ],       ql [S_LEN*NQ];
__device__ __align__(256) bf16 kvh[S_LEN*NKV],      kvl[S_LEN*NKV];
__device__ __align__(256) bf16 vth[G_GRP*DVV*S_LEN],vtl[G_GRP*DVV*S_LEN];
__device__ __align__(256) bf16 ph [134217728],      pl [134217728];
__device__ __align__(256) bf16 zh [S_LEN*ZD],       zl [S_LEN*ZD];
__device__ __align__(256) bf16 w1h[FF2*ZD],         w1l[FF2*ZD];
__device__ __align__(256) bf16 h1h[S_LEN*FF2],      h1l[S_LEN*FF2];
__device__ __align__(256) bf16 w2h[FF_OUT*FF2],     w2l[FF_OUT*FF2];

// ---------------- helpers ----------------
__device__ __forceinline__ uint32_t pack2bf(float x, float y) {
    __nv_bfloat162 p = __floats2bfloat162_rn(x, y);
    return *reinterpret_cast<uint32_t*>(&p);
}
__device__ __forceinline__ void split_store(bf16* dh, bf16* dl, size_t i, float v) {
    bf16 h = __float2bfloat16_rn(v);
    dh[i] = h;
    dl[i] = __float2bfloat16_rn(v - __bfloat162float(h));
}
// split a pair of consecutive values (i must be 2-aligned)
__device__ __forceinline__ void split2(bf16* dh, bf16* dl, size_t i, float x, float y) {
    float hx = __bfloat162float(__float2bfloat16_rn(x));
    float hy = __bfloat162float(__float2bfloat16_rn(y));
    *(uint32_t*)(dh + i) = pack2bf(hx, hy);
    *(uint32_t*)(dl + i) = pack2bf(x - hx, y - hy);
}
__device__ __forceinline__ void split4(bf16* dh, bf16* dl, size_t i4, float4 v) {
    float hx = __bfloat162float(__float2bfloat16_rn(v.x));
    float hy = __bfloat162float(__float2bfloat16_rn(v.y));
    float hz = __bfloat162float(__float2bfloat16_rn(v.z));
    float hw = __bfloat162float(__float2bfloat16_rn(v.w));
    *(uint2*)(dh + i4) = make_uint2(pack2bf(hx, hy), pack2bf(hz, hw));
    *(uint2*)(dl + i4) = make_uint2(pack2bf(v.x - hx, v.y - hy), pack2bf(v.z - hz, v.w - hw));
}

// ---------------- bf16 split mma GEMM, 2-stage cp.async + ldmatrix ----------
// C(128x128 tile) = A(MxK)@B(NxK)^T ; acc += Ah*Bh + Ah*Bl + Al*Bh (fp32)

__device__ __forceinline__ void mma_bf16(float* d, const uint32_t* a, uint32_t b0, uint32_t b1) {
    asm volatile(
        "mma.sync.aligned.m16n8k16.row.col.f32.bf16.bf16.f32 "
        "{%0,%1,%2,%3}, {%4,%5,%6,%7}, {%8,%9}, {%0,%1,%2,%3};"
        : "+f"(d[0]), "+f"(d[1]), "+f"(d[2]), "+f"(d[3])
        : "r"(a[0]), "r"(a[1]), "r"(a[2]), "r"(a[3]), "r"(b0), "r"(b1));
}
__device__ __forceinline__ void ldsm_x4(uint32_t* r, uint32_t saddr) {
    asm volatile("ldmatrix.sync.aligned.m8n8.x4.shared.b16 {%0,%1,%2,%3}, [%4];"
        : "=r"(r[0]), "=r"(r[1]), "=r"(r[2]), "=r"(r[3]) : "r"(saddr));
}

#define BM 128
#define BN 128
#define BK 32
#define LDP 20                       /* row stride words: 80B = 16B-aligned + conflict-free */
#define ARR_W (BM*LDP)               /* words per array  = 2560 (10240 B)     */
#define STG_W (4*ARR_W)              /* words per stage  = 10240 (40960 B)    */
#define SMEM_BYTES (2*STG_W*4)       /* 81920 B dynamic (2 stages)            */

__device__ __forceinline__ void cp16(uint32_t dst, const void* src) {
    asm volatile("cp.async.cg.shared.global [%0], [%1], 16;" :: "r"(dst), "l"(src));
}

__device__ __forceinline__ void stage_fill(
    uint32_t sbase,
    const bf16* __restrict__ Ah, const bf16* __restrict__ Al,
    const bf16* __restrict__ Bh, const bf16* __restrict__ Bl,
    int k0, int lda, int ldb)
{
    int tid = threadIdx.x;
    #pragma unroll
    for (int j = 0; j < 2; j++) {
        int chunk = tid + j * 256;            // 0..511
        int row = chunk >> 2;                 // 0..127
        int seg = chunk & 3;                  // 16B segment within 64B row
        uint32_t off = (uint32_t)(row * LDP * 4 + seg * 16);
        size_t a_off = (size_t)row * lda + k0 + seg * 8;
        size_t b_off = (size_t)row * ldb + k0 + seg * 8;
        cp16(sbase + 0u*ARR_W*4u + off, Ah + a_off);
        cp16(sbase + 1u*ARR_W*4u + off, Al + a_off);
        cp16(sbase + 2u*ARR_W*4u + off, Bh + b_off);
        cp16(sbase + 3u*ARR_W*4u + off, Bl + b_off);
    }
}

// MODE: 0 = plain fp32 store, 1 = atomic fp32 add,
//       2 = (acc+bias)*scale -> split(oh,ol),
//       3 = acc+bias -> C fp32 AND split(oh,ol)
template<int MODE>
__device__ __forceinline__ void gemm_core(
    const bf16* __restrict__ Ah, const bf16* __restrict__ Al,
    const bf16* __restrict__ Bh, const bf16* __restrict__ Bl,
    float* __restrict__ C, bf16* __restrict__ oh, bf16* __restrict__ ol,
    const float* __restrict__ bias, float scale,
    int kbeg, int kend, int lda, int ldb, int ldc)
{
    extern __shared__ uint32_t sh[];
    const uint32_t sb = (uint32_t)__cvta_generic_to_shared(sh);

    const int tid  = threadIdx.x;
    const int wid  = tid >> 5;
    const int lane = tid & 31;
    const int grp  = lane >> 2;
    const int tig  = lane & 3;
    const int mbase = (wid & 3) * 32;
    const int nbase = (wid >> 2) * 64;

    const bf16* Abh = Ah + (size_t)blockIdx.y * BM * lda;
    const bf16* Abl = Al + (size_t)blockIdx.y * BM * lda;
    const bf16* Bbh = Bh + (size_t)blockIdx.x * BN * ldb;
    const bf16* Bbl = Bl + (size_t)blockIdx.x * BN * ldb;

    const int a_off = (mbase + (lane & 15)) * LDP + ((lane & 16) ? 4 : 0);
    const int b_off = (nbase + ((lane >> 4) * 8) + (lane & 7)) * LDP + ((lane & 8) ? 4 : 0);

    float acc[2][8][4];
    #pragma unroll
    for (int mi = 0; mi < 2; mi++)
        #pragma unroll
        for (int ni = 0; ni < 8; ni++)
            #pragma unroll
            for (int v = 0; v < 4; v++) acc[mi][ni][v] = 0.f;

    stage_fill(sb, Abh, Abl, Bbh, Bbl, kbeg, lda, ldb);
    asm volatile("cp.async.commit_group;" ::: "memory");

    int s = 0;
    for (int k0 = kbeg; k0 < kend; k0 += BK, s ^= 1) {
        if (k0 + BK < kend)
            stage_fill(sb + (uint32_t)(s ^ 1) * STG_W * 4u,
                       Abh, Abl, Bbh, Bbl, k0 + BK, lda, ldb);
        asm volatile("cp.async.commit_group;" ::: "memory");
        asm volatile("cp.async.wait_group 1;" ::: "memory");
        __syncthreads();

        const uint32_t stg = sb + (uint32_t)s * STG_W * 4u;
        #pragma unroll
        for (int kk = 0; kk < 16; kk += 8) {
            uint32_t aH[2][4], aL[2][4];
            ldsm_x4(aH[0], stg + 0u*ARR_W*4u + (uint32_t)(a_off + kk) * 4u);
            ldsm_x4(aH[1], stg + 0u*ARR_W*4u + (uint32_t)(a_off + kk + 16*LDP) * 4u);
            ldsm_x4(aL[0], stg + 1u*ARR_W*4u + (uint32_t)(a_off + kk) * 4u);
            ldsm_x4(aL[1], stg + 1u*ARR_W*4u + (uint32_t)(a_off + kk + 16*LDP) * 4u);
            #pragma unroll
            for (int ni2 = 0; ni2 < 4; ni2++) {
                uint32_t bH4[4], bL4[4];
                ldsm_x4(bH4, stg + 2u*ARR_W*4u + (uint32_t)(b_off + kk + ni2*16*LDP) * 4u);
                ldsm_x4(bL4, stg + 3u*ARR_W*4u + (uint32_t)(b_off + kk + ni2*16*LDP) * 4u);
                #pragma unroll
                for (int h = 0; h < 2; h++) {
                    int ni = ni2 * 2 + h;
                    #pragma unroll
                    for (int mi = 0; mi < 2; mi++) {
                        mma_bf16(acc[mi][ni], aH[mi], bH4[h*2], bH4[h*2+1]);
                        mma_bf16(acc[mi][ni], aH[mi], bL4[h*2], bL4[h*2+1]);
                        mma_bf16(acc[mi][ni], aL[mi], bH4[h*2], bH4[h*2+1]);
                    }
                }
            }
        }
        __syncthreads();
    }

    #pragma unroll
    for (int mi = 0; mi < 2; mi++)
        #pragma unroll
        for (int ni = 0; ni < 8; ni++) {
            int row = blockIdx.y * BM + mbase + mi * 16 + grp;
            int col = blockIdx.x * BN + nbase + ni * 8 + tig * 2;
            float c0 = acc[mi][ni][0], c1 = acc[mi][ni][1];
            float c2 = acc[mi][ni][2], c3 = acc[mi][ni][3];
            if (MODE == 0) {
                *(float2*)&C[(size_t)row * ldc + col]       = make_float2(c0, c1);
                *(float2*)&C[(size_t)(row + 8) * ldc + col] = make_float2(c2, c3);
            } else if (MODE == 1) {
                atomicAdd(&C[(size_t)row * ldc + col],           c0);
                atomicAdd(&C[(size_t)row * ldc + col + 1],       c1);
                atomicAdd(&C[(size_t)(row + 8) * ldc + col],     c2);
                atomicAdd(&C[(size_t)(row + 8) * ldc + col + 1], c3);
            } else {
                float b0 = bias[col], b1 = bias[col + 1];
                float v0 = (c0 + b0) * scale, v1 = (c1 + b1) * scale;
                float v2 = (c2 + b0) * scale, v3 = (c3 + b1) * scale;
                if (MODE == 3) {
                    *(float2*)&C[(size_t)row * ldc + col]       = make_float2(v0, v1);
                    *(float2*)&C[(size_t)(row + 8) * ldc + col] = make_float2(v2, v3);
                }
                split2(oh, ol, (size_t)row * ldc + col,       v0, v1);
                split2(oh, ol, (size_t)(row + 8) * ldc + col, v2, v3);
            }
        }
}

// ---------------- GEMM wrapper kernels ----------------
__global__ void __launch_bounds__(256, 2) k_qproj(const float* __restrict__ bias) {
    gemm_core<2>(xh, xl, wqh, wql, nullptr, qh, ql, bias, ATT_SCALE,
                 0, D_MODEL, D_MODEL, D_MODEL, NQ);
}
__global__ void __launch_bounds__(256, 2) k_kvproj(const float* __restrict__ bias) {
    gemm_core<3>(xh, xl, wkh, wkl, g_kv, kvh, kvl, bias, 1.f,
                 0, D_MODEL, D_MODEL, D_MODEL, NKV);
}
__global__ void __launch_bounds__(256, 2) k_scores() {
    int batch = blockIdx.z;                 // g*H + h
    int g = batch >> 4;
    gemm_core<0>(qh + batch * DQK, ql + batch * DQK,
                 kvh + g * DQK,   kvl + g * DQK,
                 g_scores + (size_t)batch * S_LEN * S_LEN, nullptr, nullptr, nullptr, 1.f,
                 0, DQK, NQ, NKV, S_LEN);
}
__global__ void __launch_bounds__(256, 2) k_pv() {
    int batch = blockIdx.z;
    int g = batch >> 4;
    gemm_core<0>(ph + (size_t)batch * S_LEN * S_LEN,
                 pl + (size_t)batch * S_LEN * S_LEN,
                 vth + (size_t)g * DVV * S_LEN,
                 vtl + (size_t)g * DVV * S_LEN,
                 g_z + batch * DVV, nullptr, nullptr, nullptr, 1.f,
                 0, S_LEN, S_LEN, S_LEN, ZD);
}
__global__ void __launch_bounds__(256, 2) k_ffn1() {
    int kb = blockIdx.z * (ZD / 2);
    gemm_core<1>(zh, zl, w1h, w1l, g_h1, nullptr, nullptr, nullptr, 1.f,
                 kb, kb + ZD / 2, ZD, ZD, FF2);
}
__global__ void __launch_bounds__(256, 2) k_ffn2(float* __restrict__ out) {
    int kb = blockIdx.z * (FF2 / 4);
    gemm_core<1>(h1h, h1l, w2h, w2l, out, nullptr, nullptr, nullptr, 1.f,
                 kb, kb + FF2 / 4, FF2, FF2, FF_OUT);
}

// ---------------- rmsnorm (writes bf16 hi/lo, vectorized) ----------------
__device__ __forceinline__ void rms_body(const float* __restrict__ in,
                                         const float* __restrict__ gamma,
                                         bf16* __restrict__ oh, bf16* __restrict__ ol,
                                         int cols)
{
    const float4* x4 = (const float4*)(in + (size_t)blockIdx.x * cols);
    const float4* g4 = (const float4*)gamma;
    size_t obase = (size_t)blockIdx.x * cols;
    int nv = cols >> 2;
    float ss = 0.f;
    for (int c = threadIdx.x; c < nv; c += blockDim.x) {
        float4 v = x4[c];
        ss += v.x*v.x + v.y*v.y + v.z*v.z + v.w*v.w;
    }
    __shared__ float red[33];
    #pragma unroll
    for (int o = 16; o; o >>= 1) ss += __shfl_xor_sync(0xffffffffu, ss, o);
    if ((threadIdx.x & 31) == 0) red[threadIdx.x >> 5] = ss;
    __syncthreads();
    if (threadIdx.x < 32) {
        float v = (threadIdx.x < (blockDim.x >> 5)) ? red[threadIdx.x] : 0.f;
        #pragma unroll
        for (int o = 16; o; o >>= 1) v += __shfl_xor_sync(0xffffffffu, v, o);
        if (threadIdx.x == 0) red[32] = v;
    }
    __syncthreads();
    float scale = sqrtf((float)cols) / fmaxf(sqrtf(red[32]), 1e-12f);
    for (int c = threadIdx.x; c < nv; c += blockDim.x) {
        float4 v = x4[c];
        float4 g = g4[c];
        v.x *= scale * g.x; v.y *= scale * g.y; v.z *= scale * g.z; v.w *= scale * g.w;
        split4(oh, ol, obase + (size_t)c * 4, v);
    }
}
__global__ void k_rms_x(const float* __restrict__ x, const float* __restrict__ gamma) {
    rms_body(x, gamma, xh, xl, D_MODEL);
}
__global__ void k_rms_z(const float* __restrict__ gamma) {
    rms_body(g_z, gamma, zh, zl, ZD);
}

// ---------------- weight split (vectorized) ----------------
__global__ void k_split_w(const float* __restrict__ src, int which) {
    size_t i4 = ((size_t)blockIdx.x * 256 + threadIdx.x) * 4;
    float4 v = *(const float4*)(src + i4);
    switch (which) {
        case 0: split4(wqh, wql, i4, v); break;
        case 1: split4(wkh, wkl, i4, v); break;
        case 2: split4(w1h, w1l, i4, v); break;
        case 3: split4(w2h, w2l, i4, v); break;
    }
}

// ---------------- elementwise kernels ----------------
// tiled transpose: vt[g][d][t] = kv[t][NKHALF + g*128 + d]
__global__ void k_vt_build() {
    __shared__ float tile[32][33];
    int t0 = blockIdx.x * 32, d0 = blockIdx.y * 32, g = blockIdx.z;
    #pragma unroll
    for (int j = 0; j < 4; j++) {
        int t = t0 + threadIdx.y + 8 * j;
        tile[threadIdx.y + 8 * j][threadIdx.x] =
            g_kv[(size_t)t * NKV + NKHALF + g * DVV + d0 + threadIdx.x];
    }
    __syncthreads();
    #pragma unroll
    for (int j = 0; j < 4; j++) {
        int d = d0 + threadIdx.y + 8 * j;
        split_store(vth, vtl,
                    ((size_t)g * DVV + d) * S_LEN + t0 + threadIdx.x,
                    tile[threadIdx.x][threadIdx.y + 8 * j]);
    }
}
__global__ void k_zero_h1() {
    size_t i4 = ((size_t)blockIdx.x * 256 + threadIdx.x) * 4;
    *(float4*)(g_h1 + i4) = make_float4(0.f, 0.f, 0.f, 0.f);
}
__global__ void k_zero_out(float* __restrict__ out) {
    size_t i4 = ((size_t)blockIdx.x * 256 + threadIdx.x) * 4;
    *(float4*)(out + i4) = make_float4(0.f, 0.f, 0.f, 0.f);
}
__global__ void k_silu_h1(const float* __restrict__ bias) {
    size_t i4 = ((size_t)blockIdx.x * 256 + threadIdx.x) * 4;
    float4 v = *(const float4*)(g_h1 + i4);
    float4 b = *(const float4*)(bias + (i4 & (FF2 - 1)));
    v.x += b.x; v.y += b.y; v.z += b.z; v.w += b.w;
    v.x /= (1.f + __expf(-v.x)); v.y /= (1.f + __expf(-v.y));
    v.z /= (1.f + __expf(-v.z)); v.w /= (1.f + __expf(-v.w));
    split4(h1h, h1l, i4, v);
}
__global__ void k_silu_out(float* __restrict__ C, const float* __restrict__ bias) {
    size_t i4 = ((size_t)blockIdx.x * 256 + threadIdx.x) * 4;
    float4 v = *(const float4*)(C + i4);
    float4 b = *(const float4*)(bias + (i4 & (FF_OUT - 1)));
    v.x += b.x; v.y += b.y; v.z += b.z; v.w += b.w;
    v.x /= (1.f + __expf(-v.x)); v.y /= (1.f + __expf(-v.y));
    v.z /= (1.f + __expf(-v.z)); v.w /= (1.f + __expf(-v.w));
    *(float4*)(C + i4) = v;
}

// ---------------- row softmax over 1024 cols (q pre-scaled; writes hi/lo) ---
__global__ void k_softmax() {
    size_t rbase = (size_t)blockIdx.x * S_LEN;
    const float4* row4 = (const float4*)(g_scores + rbase);
    __shared__ float red[33];
    int tid = threadIdx.x;
    float4 v = row4[tid];
    float m = fmaxf(fmaxf(v.x, v.y), fmaxf(v.z, v.w));
    #pragma unroll
    for (int o = 16; o; o >>= 1) m = fmaxf(m, __shfl_xor_sync(0xffffffffu, m, o));
    if ((tid & 31) == 0) red[tid >> 5] = m;
    __syncthreads();
    if (tid < 32) {
        float t = (tid < 8) ? red[tid] : -1e30f;
        #pragma unroll
        for (int o = 4; o; o >>= 1) t = fmaxf(t, __shfl_xor_sync(0xffffffffu, t, o));
        if (tid == 0) red[32] = t;
    }
    __syncthreads();
    m = red[32];
    __syncthreads();
    v.x = __expf(v.x - m); v.y = __expf(v.y - m);
    v.z = __expf(v.z - m); v.w = __expf(v.w - m);
    float s = v.x + v.y + v.z + v.w;
    #pragma unroll
    for (int o = 16; o; o >>= 1) s += __shfl_xor_sync(0xffffffffu, s, o);
    if ((tid & 31) == 0) red[tid >> 5] = s;
    __syncthreads();
    if (tid < 32) {
        float t = (tid < 8) ? red[tid] : 0.f;
        #pragma unroll
        for (int o = 4; o; o >>= 1) t += __shfl_xor_sync(0xffffffffu, t, o);
        if (tid == 0) red[32] = t;
    }
    __syncthreads();
    float inv = 1.f / red[32];
    v.x *= inv; v.y *= inv; v.z *= inv; v.w *= inv;
    split4(ph, pl, rbase + (size_t)tid * 4, v);
}

// ---------------- launch ----------------
extern "C" void kernel_launch(void* const* d_in, const int* in_sizes, int n_in,
                              void* d_out, int out_size) {
    const float* x     = (const float*)d_in[0];
    const float* gin   = (const float*)d_in[1];
    const float* Wq_w  = (const float*)d_in[2];
    const float* Wq_b  = (const float*)d_in[3];
    const float* Wkv_w = (const float*)d_in[4];
    const float* Wkv_b = (const float*)d_in[5];
    const float* gz    = (const float*)d_in[6];
    const float* W1    = (const float*)d_in[7];
    const float* b1    = (const float*)d_in[8];
    const float* W2    = (const float*)d_in[9];
    const float* b2    = (const float*)d_in[10];
    float* out = (float*)d_out;

    cudaFuncSetAttribute(k_qproj,  cudaFuncAttributeMaxDynamicSharedMemorySize, SMEM_BYTES);
    cudaFuncSetAttribute(k_kvproj, cudaFuncAttributeMaxDynamicSharedMemorySize, SMEM_BYTES);
    cudaFuncSetAttribute(k_scores, cudaFuncAttributeMaxDynamicSharedMemorySize, SMEM_BYTES);
    cudaFuncSetAttribute(k_pv,     cudaFuncAttributeMaxDynamicSharedMemorySize, SMEM_BYTES);
    cudaFuncSetAttribute(k_ffn1,   cudaFuncAttributeMaxDynamicSharedMemorySize, SMEM_BYTES);
    cudaFuncSetAttribute(k_ffn2,   cudaFuncAttributeMaxDynamicSharedMemorySize, SMEM_BYTES);

    k_rms_x   <<<S_LEN, 256>>>(x, gin);
    k_split_w <<<(NQ * D_MODEL) / 1024, 256>>>(Wq_w, 0);
    k_split_w <<<(NKV * D_MODEL) / 1024, 256>>>(Wkv_w, 1);
    k_split_w <<<(FF2 * ZD) / 1024, 256>>>(W1, 2);
    k_split_w <<<(FF_OUT * FF2) / 1024, 256>>>(W2, 3);

    k_qproj   <<<dim3(NQ / BN,     S_LEN / BM), 256, SMEM_BYTES>>>(Wq_b);
    k_kvproj  <<<dim3(NKV / BN,    S_LEN / BM), 256, SMEM_BYTES>>>(Wkv_b);
    k_vt_build<<<dim3(S_LEN / 32, DVV / 32, G_GRP), dim3(32, 8)>>>();

    k_scores  <<<dim3(S_LEN / BN,  S_LEN / BM, G_GRP * H_HEADS), 256, SMEM_BYTES>>>();
    k_softmax <<<G_GRP * H_HEADS * S_LEN, 256>>>();
    k_pv      <<<dim3(1,           S_LEN / BM, G_GRP * H_HEADS), 256, SMEM_BYTES>>>();

    k_rms_z   <<<S_LEN, 256>>>(gz);
    k_zero_h1 <<<(S_LEN * FF2) / 1024, 256>>>();
    k_ffn1    <<<dim3(FF2 / BN,    S_LEN / BM, 2), 256, SMEM_BYTES>>>();
    k_silu_h1 <<<(S_LEN * FF2) / 1024, 256>>>(b1);
    k_zero_out<<<(S_LEN * FF_OUT) / 1024, 256>>>(out);
    k_ffn2    <<<dim3(FF_OUT / BN, S_LEN / BM, 4), 256, SMEM_BYTES>>>(out);
    k_silu_out<<<(S_LEN * FF_OUT) / 1024, 256>>>(out, b2);
}

// round 11
// speedup vs baseline: 3.1773x; 1.1177x over previous
#include <cuda_runtime.h>
#include <cuda_fp16.h>
#include <math.h>
#include <stdint.h>

// ---------------- problem constants ----------------
#define S_LEN   1024
#define D_MODEL 1024
#define G_GRP   8
#define H_HEADS 16
#define DQK     128
#define DVV     128
#define FF_OUT  1024
#define NQ      (G_GRP*H_HEADS*DQK)    /* 16384 */
#define NKV     (G_GRP*(DQK+DVV))      /* 2048  */
#define NKHALF  (G_GRP*DQK)            /* 1024  */
#define ZD      NQ                     /* 16384 */
#define FF2     (2*FF_OUT)             /* 2048  */
#define ATT_SCALE 0.08838834764831845f /* 1/sqrt(128) */

typedef __half hf;

// ---------------- scratch (device globals; referenced ONLY in device code) ---
// (passing these as kernel args from host passes the host shadow — R2-R4 bug)
__device__ __align__(256) float g_kv[S_LEN*NKV];
__device__ __align__(256) float g_scores[134217728];   // G*H*S*S fp32
__device__ __align__(256) float g_z[S_LEN*ZD];
__device__ __align__(256) float g_h1[S_LEN*FF2];

// fp16 hi/lo split operands (fp16 split pair carries ~21 mantissa bits)
__device__ __align__(256) hf xh [S_LEN*D_MODEL],  xl [S_LEN*D_MODEL];
__device__ __align__(256) hf wqh[NQ*D_MODEL],     wql[NQ*D_MODEL];
__device__ __align__(256) hf wkh[NKV*D_MODEL],    wkl[NKV*D_MODEL];
__device__ __align__(256) hf qh [S_LEN*NQ],       ql [S_LEN*NQ];
__device__ __align__(256) hf kvh[S_LEN*NKV],      kvl[S_LEN*NKV];
__device__ __align__(256) hf vth[G_GRP*DVV*S_LEN],vtl[G_GRP*DVV*S_LEN];
__device__ __align__(256) hf ph [134217728],      pl [134217728];
__device__ __align__(256) hf zh [S_LEN*ZD],       zl [S_LEN*ZD];
__device__ __align__(256) hf w1h[FF2*ZD];         // SINGLE fp16 (2-term ffn1)
__device__ __align__(256) hf h1h[S_LEN*FF2],      h1l[S_LEN*FF2];
__device__ __align__(256) hf w2h[FF_OUT*FF2],     w2l[FF_OUT*FF2];

// ---------------- helpers ----------------
__device__ __forceinline__ uint32_t pack2h(float x, float y) {
    __half2 p = __floats2half2_rn(x, y);
    return *reinterpret_cast<uint32_t*>(&p);
}
__device__ __forceinline__ void split_store(hf* dh, hf* dl, size_t i, float v) {
    hf h = __float2half_rn(v);
    dh[i] = h;
    dl[i] = __float2half_rn(v - __half2float(h));
}
// split a pair of consecutive values (i must be 2-aligned)
__device__ __forceinline__ void split2(hf* dh, hf* dl, size_t i, float x, float y) {
    float hx = __half2float(__float2half_rn(x));
    float hy = __half2float(__float2half_rn(y));
    *(uint32_t*)(dh + i) = pack2h(hx, hy);
    *(uint32_t*)(dl + i) = pack2h(x - hx, y - hy);
}
__device__ __forceinline__ void split4(hf* dh, hf* dl, size_t i4, float4 v) {
    float hx = __half2float(__float2half_rn(v.x));
    float hy = __half2float(__float2half_rn(v.y));
    float hz = __half2float(__float2half_rn(v.z));
    float hw = __half2float(__float2half_rn(v.w));
    *(uint2*)(dh + i4) = make_uint2(pack2h(hx, hy), pack2h(hz, hw));
    *(uint2*)(dl + i4) = make_uint2(pack2h(v.x - hx, v.y - hy), pack2h(v.z - hz, v.w - hw));
}

// ---------------- fp16 split mma GEMM, 2-stage cp.async + ldmatrix ----------
// C(128x128 tile) = A(MxK)@B(NxK)^T
// terms: Ah*Bh always; + Ah*Bl if SB; + Al*Bh if SA   (fp32 accum)

__device__ __forceinline__ void mma_f16(float* d, const uint32_t* a, uint32_t b0, uint32_t b1) {
    asm volatile(
        "mma.sync.aligned.m16n8k16.row.col.f32.f16.f16.f32 "
        "{%0,%1,%2,%3}, {%4,%5,%6,%7}, {%8,%9}, {%0,%1,%2,%3};"
        : "+f"(d[0]), "+f"(d[1]), "+f"(d[2]), "+f"(d[3])
        : "r"(a[0]), "r"(a[1]), "r"(a[2]), "r"(a[3]), "r"(b0), "r"(b1));
}
__device__ __forceinline__ void ldsm_x4(uint32_t* r, uint32_t saddr) {
    asm volatile("ldmatrix.sync.aligned.m8n8.x4.shared.b16 {%0,%1,%2,%3}, [%4];"
        : "=r"(r[0]), "=r"(r[1]), "=r"(r[2]), "=r"(r[3]) : "r"(saddr));
}

#define BM 128
#define BN 128
#define BK 32
#define LDP 20                       /* row stride words: 80B = 16B-aligned + conflict-free */
#define ARR_W (BM*LDP)               /* words per array  = 2560 (10240 B)     */
#define STG_W (4*ARR_W)              /* words per stage  = 10240 (40960 B)    */
#define SMEM_BYTES (2*STG_W*4)       /* 81920 B dynamic (2 stages)            */

__device__ __forceinline__ void cp16(uint32_t dst, const void* src) {
    asm volatile("cp.async.cg.shared.global [%0], [%1], 16;" :: "r"(dst), "l"(src));
}

template<bool SA, bool SB>
__device__ __forceinline__ void stage_fill(
    uint32_t sbase,
    const hf* __restrict__ Ah, const hf* __restrict__ Al,
    const hf* __restrict__ Bh, const hf* __restrict__ Bl,
    int k0, int lda, int ldb)
{
    int tid = threadIdx.x;
    #pragma unroll
    for (int j = 0; j < 2; j++) {
        int chunk = tid + j * 256;            // 0..511
        int row = chunk >> 2;                 // 0..127
        int seg = chunk & 3;                  // 16B segment within 64B row
        uint32_t off = (uint32_t)(row * LDP * 4 + seg * 16);
        size_t a_off = (size_t)row * lda + k0 + seg * 8;
        size_t b_off = (size_t)row * ldb + k0 + seg * 8;
        cp16(sbase + 0u*ARR_W*4u + off, Ah + a_off);
        if (SA) cp16(sbase + 1u*ARR_W*4u + off, Al + a_off);
        cp16(sbase + 2u*ARR_W*4u + off, Bh + b_off);
        if (SB) cp16(sbase + 3u*ARR_W*4u + off, Bl + b_off);
    }
}

// MODE: 0 = plain fp32 store, 1 = atomic fp32 add,
//       2 = (acc+bias)*scale -> split(oh,ol),
//       3 = acc+bias -> C fp32 AND split(oh,ol)
template<int MODE, bool SA, bool SB>
__device__ __forceinline__ void gemm_core(
    const hf* __restrict__ Ah, const hf* __restrict__ Al,
    const hf* __restrict__ Bh, const hf* __restrict__ Bl,
    float* __restrict__ C, hf* __restrict__ oh, hf* __restrict__ ol,
    const float* __restrict__ bias, float scale,
    int kbeg, int kend, int lda, int ldb, int ldc)
{
    extern __shared__ uint32_t sh[];
    const uint32_t sb = (uint32_t)__cvta_generic_to_shared(sh);

    const int tid  = threadIdx.x;
    const int wid  = tid >> 5;
    const int lane = tid & 31;
    const int grp  = lane >> 2;
    const int tig  = lane & 3;
    const int mbase = (wid & 3) * 32;
    const int nbase = (wid >> 2) * 64;

    const hf* Abh = Ah + (size_t)blockIdx.y * BM * lda;
    const hf* Abl = SA ? Al + (size_t)blockIdx.y * BM * lda : nullptr;
    const hf* Bbh = Bh + (size_t)blockIdx.x * BN * ldb;
    const hf* Bbl = SB ? Bl + (size_t)blockIdx.x * BN * ldb : nullptr;

    const int a_off = (mbase + (lane & 15)) * LDP + ((lane & 16) ? 4 : 0);
    const int b_off = (nbase + ((lane >> 4) * 8) + (lane & 7)) * LDP + ((lane & 8) ? 4 : 0);

    float acc[2][8][4];
    #pragma unroll
    for (int mi = 0; mi < 2; mi++)
        #pragma unroll
        for (int ni = 0; ni < 8; ni++)
            #pragma unroll
            for (int v = 0; v < 4; v++) acc[mi][ni][v] = 0.f;

    stage_fill<SA,SB>(sb, Abh, Abl, Bbh, Bbl, kbeg, lda, ldb);
    asm volatile("cp.async.commit_group;" ::: "memory");

    int s = 0;
    for (int k0 = kbeg; k0 < kend; k0 += BK, s ^= 1) {
        if (k0 + BK < kend)
            stage_fill<SA,SB>(sb + (uint32_t)(s ^ 1) * STG_W * 4u,
                              Abh, Abl, Bbh, Bbl, k0 + BK, lda, ldb);
        asm volatile("cp.async.commit_group;" ::: "memory");
        asm volatile("cp.async.wait_group 1;" ::: "memory");
        __syncthreads();

        const uint32_t stg = sb + (uint32_t)s * STG_W * 4u;
        #pragma unroll
        for (int kk = 0; kk < 16; kk += 8) {
            uint32_t aH[2][4], aL[2][4];
            ldsm_x4(aH[0], stg + 0u*ARR_W*4u + (uint32_t)(a_off + kk) * 4u);
            ldsm_x4(aH[1], stg + 0u*ARR_W*4u + (uint32_t)(a_off + kk + 16*LDP) * 4u);
            if (SA) {
                ldsm_x4(aL[0], stg + 1u*ARR_W*4u + (uint32_t)(a_off + kk) * 4u);
                ldsm_x4(aL[1], stg + 1u*ARR_W*4u + (uint32_t)(a_off + kk + 16*LDP) * 4u);
            }
            #pragma unroll
            for (int ni2 = 0; ni2 < 4; ni2++) {
                uint32_t bH4[4], bL4[4];
                ldsm_x4(bH4, stg + 2u*ARR_W*4u + (uint32_t)(b_off + kk + ni2*16*LDP) * 4u);
                if (SB)
                    ldsm_x4(bL4, stg + 3u*ARR_W*4u + (uint32_t)(b_off + kk + ni2*16*LDP) * 4u);
                #pragma unroll
                for (int h = 0; h < 2; h++) {
                    int ni = ni2 * 2 + h;
                    #pragma unroll
                    for (int mi = 0; mi < 2; mi++) {
                        mma_f16(acc[mi][ni], aH[mi], bH4[h*2], bH4[h*2+1]);
                        if (SB) mma_f16(acc[mi][ni], aH[mi], bL4[h*2], bL4[h*2+1]);
                        if (SA) mma_f16(acc[mi][ni], aL[mi], bH4[h*2], bH4[h*2+1]);
                    }
                }
            }
        }
        __syncthreads();
    }

    #pragma unroll
    for (int mi = 0; mi < 2; mi++)
        #pragma unroll
        for (int ni = 0; ni < 8; ni++) {
            int row = blockIdx.y * BM + mbase + mi * 16 + grp;
            int col = blockIdx.x * BN + nbase + ni * 8 + tig * 2;
            float c0 = acc[mi][ni][0], c1 = acc[mi][ni][1];
            float c2 = acc[mi][ni][2], c3 = acc[mi][ni][3];
            if (MODE == 0) {
                *(float2*)&C[(size_t)row * ldc + col]       = make_float2(c0, c1);
                *(float2*)&C[(size_t)(row + 8) * ldc + col] = make_float2(c2, c3);
            } else if (MODE == 1) {
                atomicAdd(&C[(size_t)row * ldc + col],           c0);
                atomicAdd(&C[(size_t)row * ldc + col + 1],       c1);
                atomicAdd(&C[(size_t)(row + 8) * ldc + col],     c2);
                atomicAdd(&C[(size_t)(row + 8) * ldc + col + 1], c3);
            } else {
                float b0 = bias[col], b1 = bias[col + 1];
                float v0 = (c0 + b0) * scale, v1 = (c1 + b1) * scale;
                float v2 = (c2 + b0) * scale, v3 = (c3 + b1) * scale;
                if (MODE == 3) {
                    *(float2*)&C[(size_t)row * ldc + col]       = make_float2(v0, v1);
                    *(float2*)&C[(size_t)(row + 8) * ldc + col] = make_float2(v2, v3);
                }
                split2(oh, ol, (size_t)row * ldc + col,       v0, v1);
                split2(oh, ol, (size_t)(row + 8) * ldc + col, v2, v3);
            }
        }
}

// ---------------- GEMM wrapper kernels ----------------
__global__ void __launch_bounds__(256, 2) k_qproj(const float* __restrict__ bias) {
    gemm_core<2,true,true>(xh, xl, wqh, wql, nullptr, qh, ql, bias, ATT_SCALE,
                           0, D_MODEL, D_MODEL, D_MODEL, NQ);
}
__global__ void __launch_bounds__(256, 2) k_kvproj(const float* __restrict__ bias) {
    gemm_core<3,true,true>(xh, xl, wkh, wkl, g_kv, kvh, kvl, bias, 1.f,
                           0, D_MODEL, D_MODEL, D_MODEL, NKV);
}
__global__ void __launch_bounds__(256, 2) k_scores() {
    int batch = blockIdx.z;                 // g*H + h
    int g = batch >> 4;
    gemm_core<0,true,true>(qh + batch * DQK, ql + batch * DQK,
                           kvh + g * DQK,   kvl + g * DQK,
                           g_scores + (size_t)batch * S_LEN * S_LEN,
                           nullptr, nullptr, nullptr, 1.f,
                           0, DQK, NQ, NKV, S_LEN);
}
__global__ void __launch_bounds__(256, 2) k_pv() {
    int batch = blockIdx.z;
    int g = batch >> 4;
    gemm_core<0,true,true>(ph + (size_t)batch * S_LEN * S_LEN,
                           pl + (size_t)batch * S_LEN * S_LEN,
                           vth + (size_t)g * DVV * S_LEN,
                           vtl + (size_t)g * DVV * S_LEN,
                           g_z + batch * DVV, nullptr, nullptr, nullptr, 1.f,
                           0, S_LEN, S_LEN, S_LEN, ZD);
}
__global__ void __launch_bounds__(256, 2) k_ffn1() {
    // 2-term: z split (exact), W1 single fp16 (sole value-path rounding source)
    int kb = blockIdx.z * (ZD / 2);
    gemm_core<1,true,false>(zh, zl, w1h, nullptr, g_h1, nullptr, nullptr, nullptr, 1.f,
                            kb, kb + ZD / 2, ZD, ZD, FF2);
}
__global__ void __launch_bounds__(256, 2) k_ffn2(float* __restrict__ out) {
    int kb = blockIdx.z * (FF2 / 4);
    gemm_core<1,true,true>(h1h, h1l, w2h, w2l, out, nullptr, nullptr, nullptr, 1.f,
                           kb, kb + FF2 / 4, FF2, FF2, FF_OUT);
}

// ---------------- rmsnorm (writes fp16 hi/lo, vectorized) ----------------
__device__ __forceinline__ void rms_body(const float* __restrict__ in,
                                         const float* __restrict__ gamma,
                                         hf* __restrict__ oh, hf* __restrict__ ol,
                                         int cols)
{
    const float4* x4 = (const float4*)(in + (size_t)blockIdx.x * cols);
    const float4* g4 = (const float4*)gamma;
    size_t obase = (size_t)blockIdx.x * cols;
    int nv = cols >> 2;
    float ss = 0.f;
    for (int c = threadIdx.x; c < nv; c += blockDim.x) {
        float4 v = x4[c];
        ss += v.x*v.x + v.y*v.y + v.z*v.z + v.w*v.w;
    }
    __shared__ float red[33];
    #pragma unroll
    for (int o = 16; o; o >>= 1) ss += __shfl_xor_sync(0xffffffffu, ss, o);
    if ((threadIdx.x & 31) == 0) red[threadIdx.x >> 5] = ss;
    __syncthreads();
    if (threadIdx.x < 32) {
        float v = (threadIdx.x < (blockDim.x >> 5)) ? red[threadIdx.x] : 0.f;
        #pragma unroll
        for (int o = 16; o; o >>= 1) v += __shfl_xor_sync(0xffffffffu, v, o);
        if (threadIdx.x == 0) red[32] = v;
    }
    __syncthreads();
    float scale = sqrtf((float)cols) / fmaxf(sqrtf(red[32]), 1e-12f);
    for (int c = threadIdx.x; c < nv; c += blockDim.x) {
        float4 v = x4[c];
        float4 g = g4[c];
        v.x *= scale * g.x; v.y *= scale * g.y; v.z *= scale * g.z; v.w *= scale * g.w;
        split4(oh, ol, obase + (size_t)c * 4, v);
    }
}
__global__ void k_rms_x(const float* __restrict__ x, const float* __restrict__ gamma) {
    rms_body(x, gamma, xh, xl, D_MODEL);
}
__global__ void k_rms_z(const float* __restrict__ gamma) {
    rms_body(g_z, gamma, zh, zl, ZD);
}

// ---------------- weight split (vectorized; W1 = single fp16) ----------------
__global__ void k_split_w(const float* __restrict__ src, int which) {
    size_t i4 = ((size_t)blockIdx.x * 256 + threadIdx.x) * 4;
    float4 v = *(const float4*)(src + i4);
    switch (which) {
        case 0: split4(wqh, wql, i4, v); break;
        case 1: split4(wkh, wkl, i4, v); break;
        case 2: *(uint2*)(w1h + i4) = make_uint2(pack2h(v.x, v.y), pack2h(v.z, v.w)); break;
        case 3: split4(w2h, w2l, i4, v); break;
    }
}

// ---------------- elementwise kernels ----------------
// tiled transpose: vt[g][d][t] = kv[t][NKHALF + g*128 + d]
__global__ void k_vt_build() {
    __shared__ float tile[32][33];
    int t0 = blockIdx.x * 32, d0 = blockIdx.y * 32, g = blockIdx.z;
    #pragma unroll
    for (int j = 0; j < 4; j++) {
        int t = t0 + threadIdx.y + 8 * j;
        tile[threadIdx.y + 8 * j][threadIdx.x] =
            g_kv[(size_t)t * NKV + NKHALF + g * DVV + d0 + threadIdx.x];
    }
    __syncthreads();
    #pragma unroll
    for (int j = 0; j < 4; j++) {
        int d = d0 + threadIdx.y + 8 * j;
        split_store(vth, vtl,
                    ((size_t)g * DVV + d) * S_LEN + t0 + threadIdx.x,
                    tile[threadIdx.x][threadIdx.y + 8 * j]);
    }
}
__global__ void k_zero_h1() {
    size_t i4 = ((size_t)blockIdx.x * 256 + threadIdx.x) * 4;
    *(float4*)(g_h1 + i4) = make_float4(0.f, 0.f, 0.f, 0.f);
}
__global__ void k_zero_out(float* __restrict__ out) {
    size_t i4 = ((size_t)blockIdx.x * 256 + threadIdx.x) * 4;
    *(float4*)(out + i4) = make_float4(0.f, 0.f, 0.f, 0.f);
}
__global__ void k_silu_h1(const float* __restrict__ bias) {
    size_t i4 = ((size_t)blockIdx.x * 256 + threadIdx.x) * 4;
    float4 v = *(const float4*)(g_h1 + i4);
    float4 b = *(const float4*)(bias + (i4 & (FF2 - 1)));
    v.x += b.x; v.y += b.y; v.z += b.z; v.w += b.w;
    v.x /= (1.f + __expf(-v.x)); v.y /= (1.f + __expf(-v.y));
    v.z /= (1.f + __expf(-v.z)); v.w /= (1.f + __expf(-v.w));
    split4(h1h, h1l, i4, v);
}
__global__ void k_silu_out(float* __restrict__ C, const float* __restrict__ bias) {
    size_t i4 = ((size_t)blockIdx.x * 256 + threadIdx.x) * 4;
    float4 v = *(const float4*)(C + i4);
    float4 b = *(const float4*)(bias + (i4 & (FF_OUT - 1)));
    v.x += b.x; v.y += b.y; v.z += b.z; v.w += b.w;
    v.x /= (1.f + __expf(-v.x)); v.y /= (1.f + __expf(-v.y));
    v.z /= (1.f + __expf(-v.z)); v.w /= (1.f + __expf(-v.w));
    *(float4*)(C + i4) = v;
}

// ---------------- row softmax over 1024 cols (q pre-scaled; writes hi/lo) ---
__global__ void k_softmax() {
    size_t rbase = (size_t)blockIdx.x * S_LEN;
    const float4* row4 = (const float4*)(g_scores + rbase);
    __shared__ float red[33];
    int tid = threadIdx.x;
    float4 v = row4[tid];
    float m = fmaxf(fmaxf(v.x, v.y), fmaxf(v.z, v.w));
    #pragma unroll
    for (int o = 16; o; o >>= 1) m = fmaxf(m, __shfl_xor_sync(0xffffffffu, m, o));
    if ((tid & 31) == 0) red[tid >> 5] = m;
    __syncthreads();
    if (tid < 32) {
        float t = (tid < 8) ? red[tid] : -1e30f;
        #pragma unroll
        for (int o = 4; o; o >>= 1) t = fmaxf(t, __shfl_xor_sync(0xffffffffu, t, o));
        if (tid == 0) red[32] = t;
    }
    __syncthreads();
    m = red[32];
    __syncthreads();
    v.x = __expf(v.x - m); v.y = __expf(v.y - m);
    v.z = __expf(v.z - m); v.w = __expf(v.w - m);
    float s = v.x + v.y + v.z + v.w;
    #pragma unroll
    for (int o = 16; o; o >>= 1) s += __shfl_xor_sync(0xffffffffu, s, o);
    if ((tid & 31) == 0) red[tid >> 5] = s;
    __syncthreads();
    if (tid < 32) {
        float t = (tid < 8) ? red[tid] : 0.f;
        #pragma unroll
        for (int o = 4; o; o >>= 1) t += __shfl_xor_sync(0xffffffffu, t, o);
        if (tid == 0) red[32] = t;
    }
    __syncthreads();
    float inv = 1.f / red[32];
    v.x *= inv; v.y *= inv; v.z *= inv; v.w *= inv;
    split4(ph, pl, rbase + (size_t)tid * 4, v);
}

// ---------------- launch ----------------
extern "C" void kernel_launch(void* const* d_in, const int* in_sizes, int n_in,
                              void* d_out, int out_size) {
    const float* x     = (const float*)d_in[0];
    const float* gin   = (const float*)d_in[1];
    const float* Wq_w  = (const float*)d_in[2];
    const float* Wq_b  = (const float*)d_in[3];
    const float* Wkv_w = (const float*)d_in[4];
    const float* Wkv_b = (const float*)d_in[5];
    const float* gz    = (const float*)d_in[6];
    const float* W1    = (const float*)d_in[7];
    const float* b1    = (const float*)d_in[8];
    const float* W2    = (const float*)d_in[9];
    const float* b2    = (const float*)d_in[10];
    float* out = (float*)d_out;

    cudaFuncSetAttribute(k_qproj,  cudaFuncAttributeMaxDynamicSharedMemorySize, SMEM_BYTES);
    cudaFuncSetAttribute(k_kvproj, cudaFuncAttributeMaxDynamicSharedMemorySize, SMEM_BYTES);
    cudaFuncSetAttribute(k_scores, cudaFuncAttributeMaxDynamicSharedMemorySize, SMEM_BYTES);
    cudaFuncSetAttribute(k_pv,     cudaFuncAttributeMaxDynamicSharedMemorySize, SMEM_BYTES);
    cudaFuncSetAttribute(k_ffn1,   cudaFuncAttributeMaxDynamicSharedMemorySize, SMEM_BYTES);
    cudaFuncSetAttribute(k_ffn2,   cudaFuncAttributeMaxDynamicSharedMemorySize, SMEM_BYTES);

    k_rms_x   <<<S_LEN, 256>>>(x, gin);
    k_split_w <<<(NQ * D_MODEL) / 1024, 256>>>(Wq_w, 0);
    k_split_w <<<(NKV * D_MODEL) / 1024, 256>>>(Wkv_w, 1);
    k_split_w <<<(FF2 * ZD) / 1024, 256>>>(W1, 2);
    k_split_w <<<(FF_OUT * FF2) / 1024, 256>>>(W2, 3);

    k_qproj   <<<dim3(NQ / BN,     S_LEN / BM), 256, SMEM_BYTES>>>(Wq_b);
    k_kvproj  <<<dim3(NKV / BN,    S_LEN / BM), 256, SMEM_BYTES>>>(Wkv_b);
    k_vt_build<<<dim3(S_LEN / 32, DVV / 32, G_GRP), dim3(32, 8)>>>();

    k_scores  <<<dim3(S_LEN / BN,  S_LEN / BM, G_GRP * H_HEADS), 256, SMEM_BYTES>>>();
    k_softmax <<<G_GRP * H_HEADS * S_LEN, 256>>>();
    k_pv      <<<dim3(1,           S_LEN / BM, G_GRP * H_HEADS), 256, SMEM_BYTES>>>();

    k_rms_z   <<<S_LEN, 256>>>(gz);
    k_zero_h1 <<<(S_LEN * FF2) / 1024, 256>>>();
    k_ffn1    <<<dim3(FF2 / BN,    S_LEN / BM, 2), 256, SMEM_BYTES>>>();
    k_silu_h1 <<<(S_LEN * FF2) / 1024, 256>>>(b1);
    k_zero_out<<<(S_LEN * FF_OUT) / 1024, 256>>>(out);
    k_ffn2    <<<dim3(FF_OUT / BN, S_LEN / BM, 4), 256, SMEM_BYTES>>>(out);
    k_silu_out<<<(S_LEN * FF_OUT) / 1024, 256>>>(out, b2);
}

// round 12
// speedup vs baseline: 3.7534x; 1.1813x over previous
#include <cuda_runtime.h>
#include <cuda_fp16.h>
#include <math.h>
#include <stdint.h>

// ---------------- problem constants ----------------
#define S_LEN   1024
#define D_MODEL 1024
#define G_GRP   8
#define H_HEADS 16
#define DQK     128
#define DVV     128
#define FF_OUT  1024
#define NQ      (G_GRP*H_HEADS*DQK)    /* 16384 */
#define NKV     (G_GRP*(DQK+DVV))      /* 2048  */
#define NKHALF  (G_GRP*DQK)            /* 1024  */
#define ZD      NQ                     /* 16384 */
#define FF2     (2*FF_OUT)             /* 2048  */
#define ATT_SCALE 0.08838834764831845f /* 1/sqrt(128) */

typedef __half hf;

// ---------------- scratch (device globals; referenced ONLY in device code) ---
// (passing these as kernel args from host passes the host shadow — R2-R4 bug)
__device__ __align__(256) float g_kv[S_LEN*NKV];
__device__ __align__(256) float g_scores[134217728];   // G*H*S*S fp32
__device__ __align__(256) float g_z[S_LEN*ZD];
__device__ __align__(256) float g_h1[S_LEN*FF2];

// fp16 operands. Split pairs (hi+lo ≈ 21 mantissa bits) where precision-critical;
// single fp16 where the calibrated error budget allows (Wq, K, P, W1).
__device__ __align__(256) hf xh [S_LEN*D_MODEL],  xl [S_LEN*D_MODEL];
__device__ __align__(256) hf wqh[NQ*D_MODEL];                       // SINGLE
__device__ __align__(256) hf wkh[NKV*D_MODEL],    wkl[NKV*D_MODEL];
__device__ __align__(256) hf qh [S_LEN*NQ],       ql [S_LEN*NQ];
__device__ __align__(256) hf kvh[S_LEN*NKV],      kvl[S_LEN*NKV];   // kvh doubles as single-K
__device__ __align__(256) hf vth[G_GRP*DVV*S_LEN],vtl[G_GRP*DVV*S_LEN];
__device__ __align__(256) hf ph [134217728];                        // SINGLE (P)
__device__ __align__(256) hf zh [S_LEN*ZD],       zl [S_LEN*ZD];
__device__ __align__(256) hf w1h[FF2*ZD];                           // SINGLE
__device__ __align__(256) hf h1h[S_LEN*FF2],      h1l[S_LEN*FF2];
__device__ __align__(256) hf w2h[FF_OUT*FF2],     w2l[FF_OUT*FF2];

// ---------------- helpers ----------------
__device__ __forceinline__ uint32_t pack2h(float x, float y) {
    __half2 p = __floats2half2_rn(x, y);
    return *reinterpret_cast<uint32_t*>(&p);
}
__device__ __forceinline__ void split_store(hf* dh, hf* dl, size_t i, float v) {
    hf h = __float2half_rn(v);
    dh[i] = h;
    dl[i] = __float2half_rn(v - __half2float(h));
}
// split a pair of consecutive values (i must be 2-aligned)
__device__ __forceinline__ void split2(hf* dh, hf* dl, size_t i, float x, float y) {
    float hx = __half2float(__float2half_rn(x));
    float hy = __half2float(__float2half_rn(y));
    *(uint32_t*)(dh + i) = pack2h(hx, hy);
    *(uint32_t*)(dl + i) = pack2h(x - hx, y - hy);
}
__device__ __forceinline__ void split4(hf* dh, hf* dl, size_t i4, float4 v) {
    float hx = __half2float(__float2half_rn(v.x));
    float hy = __half2float(__float2half_rn(v.y));
    float hz = __half2float(__float2half_rn(v.z));
    float hw = __half2float(__float2half_rn(v.w));
    *(uint2*)(dh + i4) = make_uint2(pack2h(hx, hy), pack2h(hz, hw));
    *(uint2*)(dl + i4) = make_uint2(pack2h(v.x - hx, v.y - hy), pack2h(v.z - hz, v.w - hw));
}

// ---------------- fp16 split mma GEMM, 2-stage cp.async + ldmatrix ----------
// C(128x128 tile) = A(MxK)@B(NxK)^T
// terms: Ah*Bh always; + Ah*Bl if SB; + Al*Bh if SA   (fp32 accum)

__device__ __forceinline__ void mma_f16(float* d, const uint32_t* a, uint32_t b0, uint32_t b1) {
    asm volatile(
        "mma.sync.aligned.m16n8k16.row.col.f32.f16.f16.f32 "
        "{%0,%1,%2,%3}, {%4,%5,%6,%7}, {%8,%9}, {%0,%1,%2,%3};"
        : "+f"(d[0]), "+f"(d[1]), "+f"(d[2]), "+f"(d[3])
        : "r"(a[0]), "r"(a[1]), "r"(a[2]), "r"(a[3]), "r"(b0), "r"(b1));
}
__device__ __forceinline__ void ldsm_x4(uint32_t* r, uint32_t saddr) {
    asm volatile("ldmatrix.sync.aligned.m8n8.x4.shared.b16 {%0,%1,%2,%3}, [%4];"
        : "=r"(r[0]), "=r"(r[1]), "=r"(r[2]), "=r"(r[3]) : "r"(saddr));
}

#define BM 128
#define BN 128
#define BK 32
#define LDP 20                       /* row stride words: 80B = 16B-aligned + conflict-free */
#define ARR_W (BM*LDP)               /* words per array  = 2560 (10240 B)     */
#define STG_W (4*ARR_W)              /* words per stage  = 10240 (40960 B)    */
#define SMEM_BYTES (2*STG_W*4)       /* 81920 B dynamic (2 stages)            */

__device__ __forceinline__ void cp16(uint32_t dst, const void* src) {
    asm volatile("cp.async.cg.shared.global [%0], [%1], 16;" :: "r"(dst), "l"(src));
}

template<bool SA, bool SB>
__device__ __forceinline__ void stage_fill(
    uint32_t sbase,
    const hf* __restrict__ Ah, const hf* __restrict__ Al,
    const hf* __restrict__ Bh, const hf* __restrict__ Bl,
    int k0, int lda, int ldb)
{
    int tid = threadIdx.x;
    #pragma unroll
    for (int j = 0; j < 2; j++) {
        int chunk = tid + j * 256;            // 0..511
        int row = chunk >> 2;                 // 0..127
        int seg = chunk & 3;                  // 16B segment within 64B row
        uint32_t off = (uint32_t)(row * LDP * 4 + seg * 16);
        size_t a_off = (size_t)row * lda + k0 + seg * 8;
        size_t b_off = (size_t)row * ldb + k0 + seg * 8;
        cp16(sbase + 0u*ARR_W*4u + off, Ah + a_off);
        if (SA) cp16(sbase + 1u*ARR_W*4u + off, Al + a_off);
        cp16(sbase + 2u*ARR_W*4u + off, Bh + b_off);
        if (SB) cp16(sbase + 3u*ARR_W*4u + off, Bl + b_off);
    }
}

// MODE: 0 = plain fp32 store, 1 = atomic fp32 add,
//       2 = (acc+bias)*scale -> split(oh,ol),
//       3 = acc+bias -> C fp32 AND split(oh,ol)
template<int MODE, bool SA, bool SB>
__device__ __forceinline__ void gemm_core(
    const hf* __restrict__ Ah, const hf* __restrict__ Al,
    const hf* __restrict__ Bh, const hf* __restrict__ Bl,
    float* __restrict__ C, hf* __restrict__ oh, hf* __restrict__ ol,
    const float* __restrict__ bias, float scale,
    int kbeg, int kend, int lda, int ldb, int ldc)
{
    extern __shared__ uint32_t sh[];
    const uint32_t sb = (uint32_t)__cvta_generic_to_shared(sh);

    const int tid  = threadIdx.x;
    const int wid  = tid >> 5;
    const int lane = tid & 31;
    const int grp  = lane >> 2;
    const int tig  = lane & 3;
    const int mbase = (wid & 3) * 32;
    const int nbase = (wid >> 2) * 64;

    const hf* Abh = Ah + (size_t)blockIdx.y * BM * lda;
    const hf* Abl = SA ? Al + (size_t)blockIdx.y * BM * lda : nullptr;
    const hf* Bbh = Bh + (size_t)blockIdx.x * BN * ldb;
    const hf* Bbl = SB ? Bl + (size_t)blockIdx.x * BN * ldb : nullptr;

    const int a_off = (mbase + (lane & 15)) * LDP + ((lane & 16) ? 4 : 0);
    const int b_off = (nbase + ((lane >> 4) * 8) + (lane & 7)) * LDP + ((lane & 8) ? 4 : 0);

    float acc[2][8][4];
    #pragma unroll
    for (int mi = 0; mi < 2; mi++)
        #pragma unroll
        for (int ni = 0; ni < 8; ni++)
            #pragma unroll
            for (int v = 0; v < 4; v++) acc[mi][ni][v] = 0.f;

    stage_fill<SA,SB>(sb, Abh, Abl, Bbh, Bbl, kbeg, lda, ldb);
    asm volatile("cp.async.commit_group;" ::: "memory");

    int s = 0;
    for (int k0 = kbeg; k0 < kend; k0 += BK, s ^= 1) {
        if (k0 + BK < kend)
            stage_fill<SA,SB>(sb + (uint32_t)(s ^ 1) * STG_W * 4u,
                              Abh, Abl, Bbh, Bbl, k0 + BK, lda, ldb);
        asm volatile("cp.async.commit_group;" ::: "memory");
        asm volatile("cp.async.wait_group 1;" ::: "memory");
        __syncthreads();

        const uint32_t stg = sb + (uint32_t)s * STG_W * 4u;
        #pragma unroll
        for (int kk = 0; kk < 16; kk += 8) {
            uint32_t aH[2][4], aL[2][4];
            ldsm_x4(aH[0], stg + 0u*ARR_W*4u + (uint32_t)(a_off + kk) * 4u);
            ldsm_x4(aH[1], stg + 0u*ARR_W*4u + (uint32_t)(a_off + kk + 16*LDP) * 4u);
            if (SA) {
                ldsm_x4(aL[0], stg + 1u*ARR_W*4u + (uint32_t)(a_off + kk) * 4u);
                ldsm_x4(aL[1], stg + 1u*ARR_W*4u + (uint32_t)(a_off + kk + 16*LDP) * 4u);
            }
            #pragma unroll
            for (int ni2 = 0; ni2 < 4; ni2++) {
                uint32_t bH4[4], bL4[4];
                ldsm_x4(bH4, stg + 2u*ARR_W*4u + (uint32_t)(b_off + kk + ni2*16*LDP) * 4u);
                if (SB)
                    ldsm_x4(bL4, stg + 3u*ARR_W*4u + (uint32_t)(b_off + kk + ni2*16*LDP) * 4u);
                #pragma unroll
                for (int h = 0; h < 2; h++) {
                    int ni = ni2 * 2 + h;
                    #pragma unroll
                    for (int mi = 0; mi < 2; mi++) {
                        mma_f16(acc[mi][ni], aH[mi], bH4[h*2], bH4[h*2+1]);
                        if (SB) mma_f16(acc[mi][ni], aH[mi], bL4[h*2], bL4[h*2+1]);
                        if (SA) mma_f16(acc[mi][ni], aL[mi], bH4[h*2], bH4[h*2+1]);
                    }
                }
            }
        }
        __syncthreads();
    }

    #pragma unroll
    for (int mi = 0; mi < 2; mi++)
        #pragma unroll
        for (int ni = 0; ni < 8; ni++) {
            int row = blockIdx.y * BM + mbase + mi * 16 + grp;
            int col = blockIdx.x * BN + nbase + ni * 8 + tig * 2;
            float c0 = acc[mi][ni][0], c1 = acc[mi][ni][1];
            float c2 = acc[mi][ni][2], c3 = acc[mi][ni][3];
            if (MODE == 0) {
                *(float2*)&C[(size_t)row * ldc + col]       = make_float2(c0, c1);
                *(float2*)&C[(size_t)(row + 8) * ldc + col] = make_float2(c2, c3);
            } else if (MODE == 1) {
                atomicAdd(&C[(size_t)row * ldc + col],           c0);
                atomicAdd(&C[(size_t)row * ldc + col + 1],       c1);
                atomicAdd(&C[(size_t)(row + 8) * ldc + col],     c2);
                atomicAdd(&C[(size_t)(row + 8) * ldc + col + 1], c3);
            } else {
                float b0 = bias[col], b1 = bias[col + 1];
                float v0 = (c0 + b0) * scale, v1 = (c1 + b1) * scale;
                float v2 = (c2 + b0) * scale, v3 = (c3 + b1) * scale;
                if (MODE == 3) {
                    *(float2*)&C[(size_t)row * ldc + col]       = make_float2(v0, v1);
                    *(float2*)&C[(size_t)(row + 8) * ldc + col] = make_float2(v2, v3);
                }
                split2(oh, ol, (size_t)row * ldc + col,       v0, v1);
                split2(oh, ol, (size_t)(row + 8) * ldc + col, v2, v3);
            }
        }
}

// ---------------- GEMM wrapper kernels ----------------
__global__ void __launch_bounds__(256, 2) k_qproj(const float* __restrict__ bias) {
    // 2-term: x split, Wq SINGLE
    gemm_core<2,true,false>(xh, xl, wqh, nullptr, nullptr, qh, ql, bias, ATT_SCALE,
                            0, D_MODEL, D_MODEL, D_MODEL, NQ);
}
__global__ void __launch_bounds__(256, 2) k_kvproj(const float* __restrict__ bias) {
    gemm_core<3,true,true>(xh, xl, wkh, wkl, g_kv, kvh, kvl, bias, 1.f,
                           0, D_MODEL, D_MODEL, D_MODEL, NKV);
}
__global__ void __launch_bounds__(256, 2) k_scores() {
    // 2-term: q split, K SINGLE (kvh = fp16 hi of k)
    int batch = blockIdx.z;                 // g*H + h
    int g = batch >> 4;
    gemm_core<0,true,false>(qh + batch * DQK, ql + batch * DQK,
                            kvh + g * DQK,   nullptr,
                            g_scores + (size_t)batch * S_LEN * S_LEN,
                            nullptr, nullptr, nullptr, 1.f,
                            0, DQK, NQ, NKV, S_LEN);
}
__global__ void __launch_bounds__(256, 2) k_pv() {
    // 2-term: P SINGLE, V split
    int batch = blockIdx.z;
    int g = batch >> 4;
    gemm_core<0,false,true>(ph + (size_t)batch * S_LEN * S_LEN, nullptr,
                            vth + (size_t)g * DVV * S_LEN,
                            vtl + (size_t)g * DVV * S_LEN,
                            g_z + batch * DVV, nullptr, nullptr, nullptr, 1.f,
                            0, S_LEN, S_LEN, S_LEN, ZD);
}
__global__ void __launch_bounds__(256, 2) k_ffn1() {
    // 2-term: z split, W1 SINGLE
    int kb = blockIdx.z * (ZD / 2);
    gemm_core<1,true,false>(zh, zl, w1h, nullptr, g_h1, nullptr, nullptr, nullptr, 1.f,
                            kb, kb + ZD / 2, ZD, ZD, FF2);
}
__global__ void __launch_bounds__(256, 2) k_ffn2(float* __restrict__ out) {
    int kb = blockIdx.z * (FF2 / 4);
    gemm_core<1,true,true>(h1h, h1l, w2h, w2l, out, nullptr, nullptr, nullptr, 1.f,
                           kb, kb + FF2 / 4, FF2, FF2, FF_OUT);
}

// ---------------- rmsnorm (writes fp16 hi/lo, vectorized) ----------------
__device__ __forceinline__ void rms_body(const float* __restrict__ in,
                                         const float* __restrict__ gamma,
                                         hf* __restrict__ oh, hf* __restrict__ ol,
                                         int cols)
{
    const float4* x4 = (const float4*)(in + (size_t)blockIdx.x * cols);
    const float4* g4 = (const float4*)gamma;
    size_t obase = (size_t)blockIdx.x * cols;
    int nv = cols >> 2;
    float ss = 0.f;
    for (int c = threadIdx.x; c < nv; c += blockDim.x) {
        float4 v = x4[c];
        ss += v.x*v.x + v.y*v.y + v.z*v.z + v.w*v.w;
    }
    __shared__ float red[33];
    #pragma unroll
    for (int o = 16; o; o >>= 1) ss += __shfl_xor_sync(0xffffffffu, ss, o);
    if ((threadIdx.x & 31) == 0) red[threadIdx.x >> 5] = ss;
    __syncthreads();
    if (threadIdx.x < 32) {
        float v = (threadIdx.x < (blockDim.x >> 5)) ? red[threadIdx.x] : 0.f;
        #pragma unroll
        for (int o = 16; o; o >>= 1) v += __shfl_xor_sync(0xffffffffu, v, o);
        if (threadIdx.x == 0) red[32] = v;
    }
    __syncthreads();
    float scale = sqrtf((float)cols) / fmaxf(sqrtf(red[32]), 1e-12f);
    for (int c = threadIdx.x; c < nv; c += blockDim.x) {
        float4 v = x4[c];
        float4 g = g4[c];
        v.x *= scale * g.x; v.y *= scale * g.y; v.z *= scale * g.z; v.w *= scale * g.w;
        split4(oh, ol, obase + (size_t)c * 4, v);
    }
}
__global__ void k_rms_x(const float* __restrict__ x, const float* __restrict__ gamma) {
    rms_body(x, gamma, xh, xl, D_MODEL);
}
__global__ void k_rms_z(const float* __restrict__ gamma) {
    rms_body(g_z, gamma, zh, zl, ZD);
}

// ---------------- weight split (vectorized; Wq,W1 single fp16) --------------
__global__ void k_split_w(const float* __restrict__ src, int which) {
    size_t i4 = ((size_t)blockIdx.x * 256 + threadIdx.x) * 4;
    float4 v = *(const float4*)(src + i4);
    switch (which) {
        case 0: *(uint2*)(wqh + i4) = make_uint2(pack2h(v.x, v.y), pack2h(v.z, v.w)); break;
        case 1: split4(wkh, wkl, i4, v); break;
        case 2: *(uint2*)(w1h + i4) = make_uint2(pack2h(v.x, v.y), pack2h(v.z, v.w)); break;
        case 3: split4(w2h, w2l, i4, v); break;
    }
}

// ---------------- elementwise kernels ----------------
// tiled transpose: vt[g][d][t] = kv[t][NKHALF + g*128 + d]
__global__ void k_vt_build() {
    __shared__ float tile[32][33];
    int t0 = blockIdx.x * 32, d0 = blockIdx.y * 32, g = blockIdx.z;
    #pragma unroll
    for (int j = 0; j < 4; j++) {
        int t = t0 + threadIdx.y + 8 * j;
        tile[threadIdx.y + 8 * j][threadIdx.x] =
            g_kv[(size_t)t * NKV + NKHALF + g * DVV + d0 + threadIdx.x];
    }
    __syncthreads();
    #pragma unroll
    for (int j = 0; j < 4; j++) {
        int d = d0 + threadIdx.y + 8 * j;
        split_store(vth, vtl,
                    ((size_t)g * DVV + d) * S_LEN + t0 + threadIdx.x,
                    tile[threadIdx.x][threadIdx.y + 8 * j]);
    }
}
__global__ void k_zero_h1() {
    size_t i4 = ((size_t)blockIdx.x * 256 + threadIdx.x) * 4;
    *(float4*)(g_h1 + i4) = make_float4(0.f, 0.f, 0.f, 0.f);
}
__global__ void k_zero_out(float* __restrict__ out) {
    size_t i4 = ((size_t)blockIdx.x * 256 + threadIdx.x) * 4;
    *(float4*)(out + i4) = make_float4(0.f, 0.f, 0.f, 0.f);
}
__global__ void k_silu_h1(const float* __restrict__ bias) {
    size_t i4 = ((size_t)blockIdx.x * 256 + threadIdx.x) * 4;
    float4 v = *(const float4*)(g_h1 + i4);
    float4 b = *(const float4*)(bias + (i4 & (FF2 - 1)));
    v.x += b.x; v.y += b.y; v.z += b.z; v.w += b.w;
    v.x /= (1.f + __expf(-v.x)); v.y /= (1.f + __expf(-v.y));
    v.z /= (1.f + __expf(-v.z)); v.w /= (1.f + __expf(-v.w));
    split4(h1h, h1l, i4, v);
}
__global__ void k_silu_out(float* __restrict__ C, const float* __restrict__ bias) {
    size_t i4 = ((size_t)blockIdx.x * 256 + threadIdx.x) * 4;
    float4 v = *(const float4*)(C + i4);
    float4 b = *(const float4*)(bias + (i4 & (FF_OUT - 1)));
    v.x += b.x; v.y += b.y; v.z += b.z; v.w += b.w;
    v.x /= (1.f + __expf(-v.x)); v.y /= (1.f + __expf(-v.y));
    v.z /= (1.f + __expf(-v.z)); v.w /= (1.f + __expf(-v.w));
    *(float4*)(C + i4) = v;
}

// ---------------- row softmax over 1024 cols (q pre-scaled; P -> single fp16)
__global__ void k_softmax() {
    size_t rbase = (size_t)blockIdx.x * S_LEN;
    const float4* row4 = (const float4*)(g_scores + rbase);
    __shared__ float red[33];
    int tid = threadIdx.x;
    float4 v = row4[tid];
    float m = fmaxf(fmaxf(v.x, v.y), fmaxf(v.z, v.w));
    #pragma unroll
    for (int o = 16; o; o >>= 1) m = fmaxf(m, __shfl_xor_sync(0xffffffffu, m, o));
    if ((tid & 31) == 0) red[tid >> 5] = m;
    __syncthreads();
    if (tid < 32) {
        float t = (tid < 8) ? red[tid] : -1e30f;
        #pragma unroll
        for (int o = 4; o; o >>= 1) t = fmaxf(t, __shfl_xor_sync(0xffffffffu, t, o));
        if (tid == 0) red[32] = t;
    }
    __syncthreads();
    m = red[32];
    __syncthreads();
    v.x = __expf(v.x - m); v.y = __expf(v.y - m);
    v.z = __expf(v.z - m); v.w = __expf(v.w - m);
    float s = v.x + v.y + v.z + v.w;
    #pragma unroll
    for (int o = 16; o; o >>= 1) s += __shfl_xor_sync(0xffffffffu, s, o);
    if ((tid & 31) == 0) red[tid >> 5] = s;
    __syncthreads();
    if (tid < 32) {
        float t = (tid < 8) ? red[tid] : 0.f;
        #pragma unroll
        for (int o = 4; o; o >>= 1) t += __shfl_xor_sync(0xffffffffu, t, o);
        if (tid == 0) red[32] = t;
    }
    __syncthreads();
    float inv = 1.f / red[32];
    *(uint2*)(ph + rbase + (size_t)tid * 4) =
        make_uint2(pack2h(v.x * inv, v.y * inv), pack2h(v.z * inv, v.w * inv));
}

// ---------------- launch ----------------
extern "C" void kernel_launch(void* const* d_in, const int* in_sizes, int n_in,
                              void* d_out, int out_size) {
    const float* x     = (const float*)d_in[0];
    const float* gin   = (const float*)d_in[1];
    const float* Wq_w  = (const float*)d_in[2];
    const float* Wq_b  = (const float*)d_in[3];
    const float* Wkv_w = (const float*)d_in[4];
    const float* Wkv_b = (const float*)d_in[5];
    const float* gz    = (const float*)d_in[6];
    const float* W1    = (const float*)d_in[7];
    const float* b1    = (const float*)d_in[8];
    const float* W2    = (const float*)d_in[9];
    const float* b2    = (const float*)d_in[10];
    float* out = (float*)d_out;

    cudaFuncSetAttribute(k_qproj,  cudaFuncAttributeMaxDynamicSharedMemorySize, SMEM_BYTES);
    cudaFuncSetAttribute(k_kvproj, cudaFuncAttributeMaxDynamicSharedMemorySize, SMEM_BYTES);
    cudaFuncSetAttribute(k_scores, cudaFuncAttributeMaxDynamicSharedMemorySize, SMEM_BYTES);
    cudaFuncSetAttribute(k_pv,     cudaFuncAttributeMaxDynamicSharedMemorySize, SMEM_BYTES);
    cudaFuncSetAttribute(k_ffn1,   cudaFuncAttributeMaxDynamicSharedMemorySize, SMEM_BYTES);
    cudaFuncSetAttribute(k_ffn2,   cudaFuncAttributeMaxDynamicSharedMemorySize, SMEM_BYTES);

    k_rms_x   <<<S_LEN, 256>>>(x, gin);
    k_split_w <<<(NQ * D_MODEL) / 1024, 256>>>(Wq_w, 0);
    k_split_w <<<(NKV * D_MODEL) / 1024, 256>>>(Wkv_w, 1);
    k_split_w <<<(FF2 * ZD) / 1024, 256>>>(W1, 2);
    k_split_w <<<(FF_OUT * FF2) / 1024, 256>>>(W2, 3);

    k_qproj   <<<dim3(NQ / BN,     S_LEN / BM), 256, SMEM_BYTES>>>(Wq_b);
    k_kvproj  <<<dim3(NKV / BN,    S_LEN / BM), 256, SMEM_BYTES>>>(Wkv_b);
    k_vt_build<<<dim3(S_LEN / 32, DVV / 32, G_GRP), dim3(32, 8)>>>();

    k_scores  <<<dim3(S_LEN / BN,  S_LEN / BM, G_GRP * H_HEADS), 256, SMEM_BYTES>>>();
    k_softmax <<<G_GRP * H_HEADS * S_LEN, 256>>>();
    k_pv      <<<dim3(1,           S_LEN / BM, G_GRP * H_HEADS), 256, SMEM_BYTES>>>();

    k_rms_z   <<<S_LEN, 256>>>(gz);
    k_zero_h1 <<<(S_LEN * FF2) / 1024, 256>>>();
    k_ffn1    <<<dim3(FF2 / BN,    S_LEN / BM, 2), 256, SMEM_BYTES>>>();
    k_silu_h1 <<<(S_LEN * FF2) / 1024, 256>>>(b1);
    k_zero_out<<<(S_LEN * FF_OUT) / 1024, 256>>>(out);
    k_ffn2    <<<dim3(FF_OUT / BN, S_LEN / BM, 4), 256, SMEM_BYTES>>>(out);
    k_silu_out<<<(S_LEN * FF_OUT) / 1024, 256>>>(out, b2);
}

// round 13
// speedup vs baseline: 4.2083x; 1.1212x over previous
#include <cuda_runtime.h>
#include <cuda_fp16.h>
#include <math.h>
#include <stdint.h>

// ---------------- problem constants ----------------
#define S_LEN   1024
#define D_MODEL 1024
#define G_GRP   8
#define H_HEADS 16
#define DQK     128
#define DVV     128
#define FF_OUT  1024
#define NQ      (G_GRP*H_HEADS*DQK)    /* 16384 */
#define NKV     (G_GRP*(DQK+DVV))      /* 2048  */
#define NKHALF  (G_GRP*DQK)            /* 1024  */
#define ZD      NQ                     /* 16384 */
#define FF2     (2*FF_OUT)             /* 2048  */
#define ATT_SCALE 0.08838834764831845f /* 1/sqrt(128) */

typedef __half hf;

// ---------------- scratch (device globals; referenced ONLY in device code) ---
// (passing these as kernel args from host passes the host shadow — R2-R4 bug)
__device__ __align__(256) float g_kv[S_LEN*NKV];
__device__ __align__(256) float g_scores[134217728];   // G*H*S*S fp32
__device__ __align__(256) float g_z[S_LEN*ZD];
__device__ __align__(256) float g_h1[S_LEN*FF2];

// fp16 operands. Split pairs (hi+lo ≈ 21 mantissa bits) where precision-critical;
// single fp16 where the calibrated error budget allows (x@qproj, Wq, K, P, V, W1).
__device__ __align__(256) hf xh [S_LEN*D_MODEL],  xl [S_LEN*D_MODEL];
__device__ __align__(256) hf wqh[NQ*D_MODEL];                       // SINGLE
__device__ __align__(256) hf wkh[NKV*D_MODEL],    wkl[NKV*D_MODEL];
__device__ __align__(256) hf qh [S_LEN*NQ],       ql [S_LEN*NQ];
__device__ __align__(256) hf kvh[S_LEN*NKV],      kvl[S_LEN*NKV];   // kvh doubles as single-K
__device__ __align__(256) hf vth[G_GRP*DVV*S_LEN];                  // SINGLE (V)
__device__ __align__(256) hf ph [134217728];                        // SINGLE (P)
__device__ __align__(256) hf zh [S_LEN*ZD],       zl [S_LEN*ZD];
__device__ __align__(256) hf w1h[FF2*ZD];                           // SINGLE
__device__ __align__(256) hf h1h[S_LEN*FF2],      h1l[S_LEN*FF2];
__device__ __align__(256) hf w2h[FF_OUT*FF2],     w2l[FF_OUT*FF2];

// ---------------- helpers ----------------
__device__ __forceinline__ uint32_t pack2h(float x, float y) {
    __half2 p = __floats2half2_rn(x, y);
    return *reinterpret_cast<uint32_t*>(&p);
}
// split a pair of consecutive values (i must be 2-aligned)
__device__ __forceinline__ void split2(hf* dh, hf* dl, size_t i, float x, float y) {
    float hx = __half2float(__float2half_rn(x));
    float hy = __half2float(__float2half_rn(y));
    *(uint32_t*)(dh + i) = pack2h(hx, hy);
    *(uint32_t*)(dl + i) = pack2h(x - hx, y - hy);
}
__device__ __forceinline__ void split4(hf* dh, hf* dl, size_t i4, float4 v) {
    float hx = __half2float(__float2half_rn(v.x));
    float hy = __half2float(__float2half_rn(v.y));
    float hz = __half2float(__float2half_rn(v.z));
    float hw = __half2float(__float2half_rn(v.w));
    *(uint2*)(dh + i4) = make_uint2(pack2h(hx, hy), pack2h(hz, hw));
    *(uint2*)(dl + i4) = make_uint2(pack2h(v.x - hx, v.y - hy), pack2h(v.z - hz, v.w - hw));
}

// ---------------- fp16 split mma GEMM, 2-stage cp.async + ldmatrix ----------
// C(128x128 tile) = A(MxK)@B(NxK)^T
// terms: Ah*Bh always; + Ah*Bl if SB; + Al*Bh if SA   (fp32 accum)

__device__ __forceinline__ void mma_f16(float* d, const uint32_t* a, uint32_t b0, uint32_t b1) {
    asm volatile(
        "mma.sync.aligned.m16n8k16.row.col.f32.f16.f16.f32 "
        "{%0,%1,%2,%3}, {%4,%5,%6,%7}, {%8,%9}, {%0,%1,%2,%3};"
        : "+f"(d[0]), "+f"(d[1]), "+f"(d[2]), "+f"(d[3])
        : "r"(a[0]), "r"(a[1]), "r"(a[2]), "r"(a[3]), "r"(b0), "r"(b1));
}
__device__ __forceinline__ void ldsm_x4(uint32_t* r, uint32_t saddr) {
    asm volatile("ldmatrix.sync.aligned.m8n8.x4.shared.b16 {%0,%1,%2,%3}, [%4];"
        : "=r"(r[0]), "=r"(r[1]), "=r"(r[2]), "=r"(r[3]) : "r"(saddr));
}

#define BM 128
#define BN 128
#define BK 32
#define LDP 20                       /* row stride words: 80B = 16B-aligned + conflict-free */
#define ARR_W (BM*LDP)               /* words per array  = 2560 (10240 B)     */
#define STG_W (4*ARR_W)              /* words per stage  = 10240 (40960 B)    */
#define SMEM_BYTES (2*STG_W*4)       /* 81920 B dynamic (2 stages)            */

__device__ __forceinline__ void cp16(uint32_t dst, const void* src) {
    asm volatile("cp.async.cg.shared.global [%0], [%1], 16;" :: "r"(dst), "l"(src));
}

template<bool SA, bool SB>
__device__ __forceinline__ void stage_fill(
    uint32_t sbase,
    const hf* __restrict__ Ah, const hf* __restrict__ Al,
    const hf* __restrict__ Bh, const hf* __restrict__ Bl,
    int k0, int lda, int ldb)
{
    int tid = threadIdx.x;
    #pragma unroll
    for (int j = 0; j < 2; j++) {
        int chunk = tid + j * 256;            // 0..511
        int row = chunk >> 2;                 // 0..127
        int seg = chunk & 3;                  // 16B segment within 64B row
        uint32_t off = (uint32_t)(row * LDP * 4 + seg * 16);
        size_t a_off = (size_t)row * lda + k0 + seg * 8;
        size_t b_off = (size_t)row * ldb + k0 + seg * 8;
        cp16(sbase + 0u*ARR_W*4u + off, Ah + a_off);
        if (SA) cp16(sbase + 1u*ARR_W*4u + off, Al + a_off);
        cp16(sbase + 2u*ARR_W*4u + off, Bh + b_off);
        if (SB) cp16(sbase + 3u*ARR_W*4u + off, Bl + b_off);
    }
}

// MODE: 0 = plain fp32 store, 1 = atomic fp32 add,
//       2 = (acc+bias)*scale -> split(oh,ol),
//       3 = acc+bias -> C fp32 AND split(oh,ol)
template<int MODE, bool SA, bool SB>
__device__ __forceinline__ void gemm_core(
    const hf* __restrict__ Ah, const hf* __restrict__ Al,
    const hf* __restrict__ Bh, const hf* __restrict__ Bl,
    float* __restrict__ C, hf* __restrict__ oh, hf* __restrict__ ol,
    const float* __restrict__ bias, float scale,
    int kbeg, int kend, int lda, int ldb, int ldc)
{
    extern __shared__ uint32_t sh[];
    const uint32_t sb = (uint32_t)__cvta_generic_to_shared(sh);

    const int tid  = threadIdx.x;
    const int wid  = tid >> 5;
    const int lane = tid & 31;
    const int grp  = lane >> 2;
    const int tig  = lane & 3;
    const int mbase = (wid & 3) * 32;
    const int nbase = (wid >> 2) * 64;

    const hf* Abh = Ah + (size_t)blockIdx.y * BM * lda;
    const hf* Abl = SA ? Al + (size_t)blockIdx.y * BM * lda : nullptr;
    const hf* Bbh = Bh + (size_t)blockIdx.x * BN * ldb;
    const hf* Bbl = SB ? Bl + (size_t)blockIdx.x * BN * ldb : nullptr;

    const int a_off = (mbase + (lane & 15)) * LDP + ((lane & 16) ? 4 : 0);
    const int b_off = (nbase + ((lane >> 4) * 8) + (lane & 7)) * LDP + ((lane & 8) ? 4 : 0);

    float acc[2][8][4];
    #pragma unroll
    for (int mi = 0; mi < 2; mi++)
        #pragma unroll
        for (int ni = 0; ni < 8; ni++)
            #pragma unroll
            for (int v = 0; v < 4; v++) acc[mi][ni][v] = 0.f;

    stage_fill<SA,SB>(sb, Abh, Abl, Bbh, Bbl, kbeg, lda, ldb);
    asm volatile("cp.async.commit_group;" ::: "memory");

    int s = 0;
    for (int k0 = kbeg; k0 < kend; k0 += BK, s ^= 1) {
        if (k0 + BK < kend)
            stage_fill<SA,SB>(sb + (uint32_t)(s ^ 1) * STG_W * 4u,
                              Abh, Abl, Bbh, Bbl, k0 + BK, lda, ldb);
        asm volatile("cp.async.commit_group;" ::: "memory");
        asm volatile("cp.async.wait_group 1;" ::: "memory");
        __syncthreads();

        const uint32_t stg = sb + (uint32_t)s * STG_W * 4u;
        #pragma unroll
        for (int kk = 0; kk < 16; kk += 8) {
            uint32_t aH[2][4], aL[2][4];
            ldsm_x4(aH[0], stg + 0u*ARR_W*4u + (uint32_t)(a_off + kk) * 4u);
            ldsm_x4(aH[1], stg + 0u*ARR_W*4u + (uint32_t)(a_off + kk + 16*LDP) * 4u);
            if (SA) {
                ldsm_x4(aL[0], stg + 1u*ARR_W*4u + (uint32_t)(a_off + kk) * 4u);
                ldsm_x4(aL[1], stg + 1u*ARR_W*4u + (uint32_t)(a_off + kk + 16*LDP) * 4u);
            }
            #pragma unroll
            for (int ni2 = 0; ni2 < 4; ni2++) {
                uint32_t bH4[4], bL4[4];
                ldsm_x4(bH4, stg + 2u*ARR_W*4u + (uint32_t)(b_off + kk + ni2*16*LDP) * 4u);
                if (SB)
                    ldsm_x4(bL4, stg + 3u*ARR_W*4u + (uint32_t)(b_off + kk + ni2*16*LDP) * 4u);
                #pragma unroll
                for (int h = 0; h < 2; h++) {
                    int ni = ni2 * 2 + h;
                    #pragma unroll
                    for (int mi = 0; mi < 2; mi++) {
                        mma_f16(acc[mi][ni], aH[mi], bH4[h*2], bH4[h*2+1]);
                        if (SB) mma_f16(acc[mi][ni], aH[mi], bL4[h*2], bL4[h*2+1]);
                        if (SA) mma_f16(acc[mi][ni], aL[mi], bH4[h*2], bH4[h*2+1]);
                    }
                }
            }
        }
        __syncthreads();
    }

    #pragma unroll
    for (int mi = 0; mi < 2; mi++)
        #pragma unroll
        for (int ni = 0; ni < 8; ni++) {
            int row = blockIdx.y * BM + mbase + mi * 16 + grp;
            int col = blockIdx.x * BN + nbase + ni * 8 + tig * 2;
            float c0 = acc[mi][ni][0], c1 = acc[mi][ni][1];
            float c2 = acc[mi][ni][2], c3 = acc[mi][ni][3];
            if (MODE == 0) {
                *(float2*)&C[(size_t)row * ldc + col]       = make_float2(c0, c1);
                *(float2*)&C[(size_t)(row + 8) * ldc + col] = make_float2(c2, c3);
            } else if (MODE == 1) {
                atomicAdd(&C[(size_t)row * ldc + col],           c0);
                atomicAdd(&C[(size_t)row * ldc + col + 1],       c1);
                atomicAdd(&C[(size_t)(row + 8) * ldc + col],     c2);
                atomicAdd(&C[(size_t)(row + 8) * ldc + col + 1], c3);
            } else {
                float b0 = bias[col], b1 = bias[col + 1];
                float v0 = (c0 + b0) * scale, v1 = (c1 + b1) * scale;
                float v2 = (c2 + b0) * scale, v3 = (c3 + b1) * scale;
                if (MODE == 3) {
                    *(float2*)&C[(size_t)row * ldc + col]       = make_float2(v0, v1);
                    *(float2*)&C[(size_t)(row + 8) * ldc + col] = make_float2(v2, v3);
                }
                split2(oh, ol, (size_t)row * ldc + col,       v0, v1);
                split2(oh, ol, (size_t)(row + 8) * ldc + col, v2, v3);
            }
        }
}

// ---------------- GEMM wrapper kernels ----------------
__global__ void __launch_bounds__(256, 2) k_qproj(const float* __restrict__ bias) {
    // 1-term: x SINGLE, Wq SINGLE (q still written as an accurate split of the result)
    gemm_core<2,false,false>(xh, nullptr, wqh, nullptr, nullptr, qh, ql, bias, ATT_SCALE,
                             0, D_MODEL, D_MODEL, D_MODEL, NQ);
}
__global__ void __launch_bounds__(256, 2) k_kvproj(const float* __restrict__ bias) {
    gemm_core<3,true,true>(xh, xl, wkh, wkl, g_kv, kvh, kvl, bias, 1.f,
                           0, D_MODEL, D_MODEL, D_MODEL, NKV);
}
__global__ void __launch_bounds__(256, 2) k_scores() {
    // 2-term: q split, K SINGLE (kvh = fp16 hi of k)
    int batch = blockIdx.z;                 // g*H + h
    int g = batch >> 4;
    gemm_core<0,true,false>(qh + batch * DQK, ql + batch * DQK,
                            kvh + g * DQK,   nullptr,
                            g_scores + (size_t)batch * S_LEN * S_LEN,
                            nullptr, nullptr, nullptr, 1.f,
                            0, DQK, NQ, NKV, S_LEN);
}
__global__ void __launch_bounds__(256, 2) k_pv() {
    // 1-term: P SINGLE, V SINGLE
    int batch = blockIdx.z;
    int g = batch >> 4;
    gemm_core<0,false,false>(ph + (size_t)batch * S_LEN * S_LEN, nullptr,
                             vth + (size_t)g * DVV * S_LEN, nullptr,
                             g_z + batch * DVV, nullptr, nullptr, nullptr, 1.f,
                             0, S_LEN, S_LEN, S_LEN, ZD);
}
__global__ void __launch_bounds__(256, 2) k_ffn1() {
    // 2-term: z split, W1 SINGLE
    int kb = blockIdx.z * (ZD / 2);
    gemm_core<1,true,false>(zh, zl, w1h, nullptr, g_h1, nullptr, nullptr, nullptr, 1.f,
                            kb, kb + ZD / 2, ZD, ZD, FF2);
}
__global__ void __launch_bounds__(256, 2) k_ffn2(float* __restrict__ out) {
    int kb = blockIdx.z * (FF2 / 4);
    gemm_core<1,true,true>(h1h, h1l, w2h, w2l, out, nullptr, nullptr, nullptr, 1.f,
                           kb, kb + FF2 / 4, FF2, FF2, FF_OUT);
}

// ---------------- rmsnorm (writes fp16 hi/lo, vectorized) ----------------
__device__ __forceinline__ void rms_body(const float* __restrict__ in,
                                         const float* __restrict__ gamma,
                                         hf* __restrict__ oh, hf* __restrict__ ol,
                                         int cols)
{
    const float4* x4 = (const float4*)(in + (size_t)blockIdx.x * cols);
    const float4* g4 = (const float4*)gamma;
    size_t obase = (size_t)blockIdx.x * cols;
    int nv = cols >> 2;
    float ss = 0.f;
    for (int c = threadIdx.x; c < nv; c += blockDim.x) {
        float4 v = x4[c];
        ss += v.x*v.x + v.y*v.y + v.z*v.z + v.w*v.w;
    }
    __shared__ float red[33];
    #pragma unroll
    for (int o = 16; o; o >>= 1) ss += __shfl_xor_sync(0xffffffffu, ss, o);
    if ((threadIdx.x & 31) == 0) red[threadIdx.x >> 5] = ss;
    __syncthreads();
    if (threadIdx.x < 32) {
        float v = (threadIdx.x < (blockDim.x >> 5)) ? red[threadIdx.x] : 0.f;
        #pragma unroll
        for (int o = 16; o; o >>= 1) v += __shfl_xor_sync(0xffffffffu, v, o);
        if (threadIdx.x == 0) red[32] = v;
    }
    __syncthreads();
    float scale = sqrtf((float)cols) / fmaxf(sqrtf(red[32]), 1e-12f);
    for (int c = threadIdx.x; c < nv; c += blockDim.x) {
        float4 v = x4[c];
        float4 g = g4[c];
        v.x *= scale * g.x; v.y *= scale * g.y; v.z *= scale * g.z; v.w *= scale * g.w;
        split4(oh, ol, obase + (size_t)c * 4, v);
    }
}
__global__ void k_rms_x(const float* __restrict__ x, const float* __restrict__ gamma) {
    rms_body(x, gamma, xh, xl, D_MODEL);
}
__global__ void k_rms_z(const float* __restrict__ gamma) {
    rms_body(g_z, gamma, zh, zl, ZD);
}

// ---------------- weight split (vectorized; Wq,W1 single fp16) --------------
__global__ void k_split_w(const float* __restrict__ src, int which) {
    size_t i4 = ((size_t)blockIdx.x * 256 + threadIdx.x) * 4;
    float4 v = *(const float4*)(src + i4);
    switch (which) {
        case 0: *(uint2*)(wqh + i4) = make_uint2(pack2h(v.x, v.y), pack2h(v.z, v.w)); break;
        case 1: split4(wkh, wkl, i4, v); break;
        case 2: *(uint2*)(w1h + i4) = make_uint2(pack2h(v.x, v.y), pack2h(v.z, v.w)); break;
        case 3: split4(w2h, w2l, i4, v); break;
    }
}

// ---------------- elementwise kernels ----------------
// tiled transpose: vt[g][d][t] = kv[t][NKHALF + g*128 + d]  (single fp16)
__global__ void k_vt_build() {
    __shared__ float tile[32][33];
    int t0 = blockIdx.x * 32, d0 = blockIdx.y * 32, g = blockIdx.z;
    #pragma unroll
    for (int j = 0; j < 4; j++) {
        int t = t0 + threadIdx.y + 8 * j;
        tile[threadIdx.y + 8 * j][threadIdx.x] =
            g_kv[(size_t)t * NKV + NKHALF + g * DVV + d0 + threadIdx.x];
    }
    __syncthreads();
    #pragma unroll
    for (int j = 0; j < 4; j++) {
        int d = d0 + threadIdx.y + 8 * j;
        vth[((size_t)g * DVV + d) * S_LEN + t0 + threadIdx.x] =
            __float2half_rn(tile[threadIdx.x][threadIdx.y + 8 * j]);
    }
}
__global__ void k_zero_h1() {
    size_t i4 = ((size_t)blockIdx.x * 256 + threadIdx.x) * 4;
    *(float4*)(g_h1 + i4) = make_float4(0.f, 0.f, 0.f, 0.f);
}
__global__ void k_zero_out(float* __restrict__ out) {
    size_t i4 = ((size_t)blockIdx.x * 256 + threadIdx.x) * 4;
    *(float4*)(out + i4) = make_float4(0.f, 0.f, 0.f, 0.f);
}
__global__ void k_silu_h1(const float* __restrict__ bias) {
    size_t i4 = ((size_t)blockIdx.x * 256 + threadIdx.x) * 4;
    float4 v = *(const float4*)(g_h1 + i4);
    float4 b = *(const float4*)(bias + (i4 & (FF2 - 1)));
    v.x += b.x; v.y += b.y; v.z += b.z; v.w += b.w;
    v.x /= (1.f + __expf(-v.x)); v.y /= (1.f + __expf(-v.y));
    v.z /= (1.f + __expf(-v.z)); v.w /= (1.f + __expf(-v.w));
    split4(h1h, h1l, i4, v);
}
__global__ void k_silu_out(float* __restrict__ C, const float* __restrict__ bias) {
    size_t i4 = ((size_t)blockIdx.x * 256 + threadIdx.x) * 4;
    float4 v = *(const float4*)(C + i4);
    float4 b = *(const float4*)(bias + (i4 & (FF_OUT - 1)));
    v.x += b.x; v.y += b.y; v.z += b.z; v.w += b.w;
    v.x /= (1.f + __expf(-v.x)); v.y /= (1.f + __expf(-v.y));
    v.z /= (1.f + __expf(-v.z)); v.w /= (1.f + __expf(-v.w));
    *(float4*)(C + i4) = v;
}

// ---------------- row softmax over 1024 cols (q pre-scaled; P -> single fp16)
__global__ void k_softmax() {
    size_t rbase = (size_t)blockIdx.x * S_LEN;
    const float4* row4 = (const float4*)(g_scores + rbase);
    __shared__ float red[33];
    int tid = threadIdx.x;
    float4 v = row4[tid];
    float m = fmaxf(fmaxf(v.x, v.y), fmaxf(v.z, v.w));
    #pragma unroll
    for (int o = 16; o; o >>= 1) m = fmaxf(m, __shfl_xor_sync(0xffffffffu, m, o));
    if ((tid & 31) == 0) red[tid >> 5] = m;
    __syncthreads();
    if (tid < 32) {
        float t = (tid < 8) ? red[tid] : -1e30f;
        #pragma unroll
        for (int o = 4; o; o >>= 1) t = fmaxf(t, __shfl_xor_sync(0xffffffffu, t, o));
        if (tid == 0) red[32] = t;
    }
    __syncthreads();
    m = red[32];
    __syncthreads();
    v.x = __expf(v.x - m); v.y = __expf(v.y - m);
    v.z = __expf(v.z - m); v.w = __expf(v.w - m);
    float s = v.x + v.y + v.z + v.w;
    #pragma unroll
    for (int o = 16; o; o >>= 1) s += __shfl_xor_sync(0xffffffffu, s, o);
    if ((tid & 31) == 0) red[tid >> 5] = s;
    __syncthreads();
    if (tid < 32) {
        float t = (tid < 8) ? red[tid] : 0.f;
        #pragma unroll
        for (int o = 4; o; o >>= 1) t += __shfl_xor_sync(0xffffffffu, t, o);
        if (tid == 0) red[32] = t;
    }
    __syncthreads();
    float inv = 1.f / red[32];
    *(uint2*)(ph + rbase + (size_t)tid * 4) =
        make_uint2(pack2h(v.x * inv, v.y * inv), pack2h(v.z * inv, v.w * inv));
}

// ---------------- launch ----------------
extern "C" void kernel_launch(void* const* d_in, const int* in_sizes, int n_in,
                              void* d_out, int out_size) {
    const float* x     = (const float*)d_in[0];
    const float* gin   = (const float*)d_in[1];
    const float* Wq_w  = (const float*)d_in[2];
    const float* Wq_b  = (const float*)d_in[3];
    const float* Wkv_w = (const float*)d_in[4];
    const float* Wkv_b = (const float*)d_in[5];
    const float* gz    = (const float*)d_in[6];
    const float* W1    = (const float*)d_in[7];
    const float* b1    = (const float*)d_in[8];
    const float* W2    = (const float*)d_in[9];
    const float* b2    = (const float*)d_in[10];
    float* out = (float*)d_out;

    cudaFuncSetAttribute(k_qproj,  cudaFuncAttributeMaxDynamicSharedMemorySize, SMEM_BYTES);
    cudaFuncSetAttribute(k_kvproj, cudaFuncAttributeMaxDynamicSharedMemorySize, SMEM_BYTES);
    cudaFuncSetAttribute(k_scores, cudaFuncAttributeMaxDynamicSharedMemorySize, SMEM_BYTES);
    cudaFuncSetAttribute(k_pv,     cudaFuncAttributeMaxDynamicSharedMemorySize, SMEM_BYTES);
    cudaFuncSetAttribute(k_ffn1,   cudaFuncAttributeMaxDynamicSharedMemorySize, SMEM_BYTES);
    cudaFuncSetAttribute(k_ffn2,   cudaFuncAttributeMaxDynamicSharedMemorySize, SMEM_BYTES);

    k_rms_x   <<<S_LEN, 256>>>(x, gin);
    k_split_w <<<(NQ * D_MODEL) / 1024, 256>>>(Wq_w, 0);
    k_split_w <<<(NKV * D_MODEL) / 1024, 256>>>(Wkv_w, 1);
    k_split_w <<<(FF2 * ZD) / 1024, 256>>>(W1, 2);
    k_split_w <<<(FF_OUT * FF2) / 1024, 256>>>(W2, 3);

    k_qproj   <<<dim3(NQ / BN,     S_LEN / BM), 256, SMEM_BYTES>>>(Wq_b);
    k_kvproj  <<<dim3(NKV / BN,    S_LEN / BM), 256, SMEM_BYTES>>>(Wkv_b);
    k_vt_build<<<dim3(S_LEN / 32, DVV / 32, G_GRP), dim3(32, 8)>>>();

    k_scores  <<<dim3(S_LEN / BN,  S_LEN / BM, G_GRP * H_HEADS), 256, SMEM_BYTES>>>();
    k_softmax <<<G_GRP * H_HEADS * S_LEN, 256>>>();
    k_pv      <<<dim3(1,           S_LEN / BM, G_GRP * H_HEADS), 256, SMEM_BYTES>>>();

    k_rms_z   <<<S_LEN, 256>>>(gz);
    k_zero_h1 <<<(S_LEN * FF2) / 1024, 256>>>();
    k_ffn1    <<<dim3(FF2 / BN,    S_LEN / BM, 2), 256, SMEM_BYTES>>>();
    k_silu_h1 <<<(S_LEN * FF2) / 1024, 256>>>(b1);
    k_zero_out<<<(S_LEN * FF_OUT) / 1024, 256>>>(out);
    k_ffn2    <<<dim3(FF_OUT / BN, S_LEN / BM, 4), 256, SMEM_BYTES>>>(out);
    k_silu_out<<<(S_LEN * FF_OUT) / 1024, 256>>>(out, b2);
}

// round 14
// speedup vs baseline: 5.4003x; 1.2833x over previous
#include <cuda_runtime.h>
#include <cuda_fp16.h>
#include <math.h>
#include <stdint.h>

// ---------------- problem constants ----------------
#define S_LEN   1024
#define D_MODEL 1024
#define G_GRP   8
#define H_HEADS 16
#define DQK     128
#define DVV     128
#define FF_OUT  1024
#define NQ      (G_GRP*H_HEADS*DQK)    /* 16384 */
#define NKV     (G_GRP*(DQK+DVV))      /* 2048  */
#define NKHALF  (G_GRP*DQK)            /* 1024  */
#define ZD      NQ                     /* 16384 */
#define FF2     (2*FF_OUT)             /* 2048  */
#define ATT_SCALE 0.08838834764831845f /* 1/sqrt(128) */

typedef __half hf;

// ---------------- scratch (device globals; referenced ONLY in device code) ---
// (passing these as kernel args from host passes the host shadow — R2-R4 bug)
__device__ __align__(256) float g_kv[S_LEN*NKV];
__device__ __align__(256) float g_scores[134217728];   // G*H*S*S fp32
__device__ __align__(256) float g_z[S_LEN*ZD];
__device__ __align__(256) float g_h1[S_LEN*FF2];

// fp16 operands. Split pairs where precision-critical; single fp16 where the
// calibrated error budget allows (q, Wq, K, P, V, z@ffn1, W1).
__device__ __align__(256) hf xh [S_LEN*D_MODEL],  xl [S_LEN*D_MODEL];
__device__ __align__(256) hf wqh[NQ*D_MODEL];                       // SINGLE
__device__ __align__(256) hf wkh[NKV*D_MODEL],    wkl[NKV*D_MODEL];
__device__ __align__(256) hf qh [S_LEN*NQ];                         // SINGLE
__device__ __align__(256) hf kvh[S_LEN*NKV],      kvl[S_LEN*NKV];   // kvh doubles as single-K
__device__ __align__(256) hf vth[G_GRP*DVV*S_LEN];                  // SINGLE (V)
__device__ __align__(256) hf ph [134217728];                        // SINGLE (P)
__device__ __align__(256) hf zh [S_LEN*ZD];                         // SINGLE (z)
__device__ __align__(256) hf w1h[FF2*ZD];                           // SINGLE
__device__ __align__(256) hf h1h[S_LEN*FF2],      h1l[S_LEN*FF2];
__device__ __align__(256) hf w2h[FF_OUT*FF2],     w2l[FF_OUT*FF2];

// ---------------- helpers ----------------
__device__ __forceinline__ uint32_t pack2h(float x, float y) {
    __half2 p = __floats2half2_rn(x, y);
    return *reinterpret_cast<uint32_t*>(&p);
}
// split a pair of consecutive values (i must be 2-aligned)
__device__ __forceinline__ void split2(hf* dh, hf* dl, size_t i, float x, float y) {
    float hx = __half2float(__float2half_rn(x));
    float hy = __half2float(__float2half_rn(y));
    *(uint32_t*)(dh + i) = pack2h(hx, hy);
    *(uint32_t*)(dl + i) = pack2h(x - hx, y - hy);
}
__device__ __forceinline__ void split4(hf* dh, hf* dl, size_t i4, float4 v) {
    float hx = __half2float(__float2half_rn(v.x));
    float hy = __half2float(__float2half_rn(v.y));
    float hz = __half2float(__float2half_rn(v.z));
    float hw = __half2float(__float2half_rn(v.w));
    *(uint2*)(dh + i4) = make_uint2(pack2h(hx, hy), pack2h(hz, hw));
    *(uint2*)(dl + i4) = make_uint2(pack2h(v.x - hx, v.y - hy), pack2h(v.z - hz, v.w - hw));
}

// ---------------- fp16 split mma GEMM, 2-stage cp.async + ldmatrix ----------
// C(128x128 tile) = A(MxK)@B(NxK)^T
// terms: Ah*Bh always; + Ah*Bl if SB; + Al*Bh if SA   (fp32 accum)

__device__ __forceinline__ void mma_f16(float* d, const uint32_t* a, uint32_t b0, uint32_t b1) {
    asm volatile(
        "mma.sync.aligned.m16n8k16.row.col.f32.f16.f16.f32 "
        "{%0,%1,%2,%3}, {%4,%5,%6,%7}, {%8,%9}, {%0,%1,%2,%3};"
        : "+f"(d[0]), "+f"(d[1]), "+f"(d[2]), "+f"(d[3])
        : "r"(a[0]), "r"(a[1]), "r"(a[2]), "r"(a[3]), "r"(b0), "r"(b1));
}
__device__ __forceinline__ void ldsm_x4(uint32_t* r, uint32_t saddr) {
    asm volatile("ldmatrix.sync.aligned.m8n8.x4.shared.b16 {%0,%1,%2,%3}, [%4];"
        : "=r"(r[0]), "=r"(r[1]), "=r"(r[2]), "=r"(r[3]) : "r"(saddr));
}

#define BM 128
#define BN 128
#define BK 32
#define LDP 20                       /* row stride words: 80B = 16B-aligned + conflict-free */
#define ARR_W (BM*LDP)               /* words per array  = 2560 (10240 B)     */
#define STG_W (4*ARR_W)              /* words per stage  = 10240 (40960 B)    */
#define SMEM_BYTES (2*STG_W*4)       /* 81920 B dynamic (2 stages)            */

__device__ __forceinline__ void cp16(uint32_t dst, const void* src) {
    asm volatile("cp.async.cg.shared.global [%0], [%1], 16;" :: "r"(dst), "l"(src));
}

template<bool SA, bool SB>
__device__ __forceinline__ void stage_fill(
    uint32_t sbase,
    const hf* __restrict__ Ah, const hf* __restrict__ Al,
    const hf* __restrict__ Bh, const hf* __restrict__ Bl,
    int k0, int lda, int ldb)
{
    int tid = threadIdx.x;
    #pragma unroll
    for (int j = 0; j < 2; j++) {
        int chunk = tid + j * 256;            // 0..511
        int row = chunk >> 2;                 // 0..127
        int seg = chunk & 3;                  // 16B segment within 64B row
        uint32_t off = (uint32_t)(row * LDP * 4 + seg * 16);
        size_t a_off = (size_t)row * lda + k0 + seg * 8;
        size_t b_off = (size_t)row * ldb + k0 + seg * 8;
        cp16(sbase + 0u*ARR_W*4u + off, Ah + a_off);
        if (SA) cp16(sbase + 1u*ARR_W*4u + off, Al + a_off);
        cp16(sbase + 2u*ARR_W*4u + off, Bh + b_off);
        if (SB) cp16(sbase + 3u*ARR_W*4u + off, Bl + b_off);
    }
}

// MODE: 0 = plain fp32 store, 1 = atomic fp32 add,
//       2 = (acc+bias)*scale -> split(oh,ol),
//       3 = acc+bias -> C fp32 AND split(oh,ol),
//       4 = (acc+bias)*scale -> single fp16(oh)
template<int MODE, bool SA, bool SB>
__device__ __forceinline__ void gemm_core(
    const hf* __restrict__ Ah, const hf* __restrict__ Al,
    const hf* __restrict__ Bh, const hf* __restrict__ Bl,
    float* __restrict__ C, hf* __restrict__ oh, hf* __restrict__ ol,
    const float* __restrict__ bias, float scale,
    int kbeg, int kend, int lda, int ldb, int ldc)
{
    extern __shared__ uint32_t sh[];
    const uint32_t sb = (uint32_t)__cvta_generic_to_shared(sh);

    const int tid  = threadIdx.x;
    const int wid  = tid >> 5;
    const int lane = tid & 31;
    const int grp  = lane >> 2;
    const int tig  = lane & 3;
    const int mbase = (wid & 3) * 32;
    const int nbase = (wid >> 2) * 64;

    const hf* Abh = Ah + (size_t)blockIdx.y * BM * lda;
    const hf* Abl = SA ? Al + (size_t)blockIdx.y * BM * lda : nullptr;
    const hf* Bbh = Bh + (size_t)blockIdx.x * BN * ldb;
    const hf* Bbl = SB ? Bl + (size_t)blockIdx.x * BN * ldb : nullptr;

    const int a_off = (mbase + (lane & 15)) * LDP + ((lane & 16) ? 4 : 0);
    const int b_off = (nbase + ((lane >> 4) * 8) + (lane & 7)) * LDP + ((lane & 8) ? 4 : 0);

    float acc[2][8][4];
    #pragma unroll
    for (int mi = 0; mi < 2; mi++)
        #pragma unroll
        for (int ni = 0; ni < 8; ni++)
            #pragma unroll
            for (int v = 0; v < 4; v++) acc[mi][ni][v] = 0.f;

    stage_fill<SA,SB>(sb, Abh, Abl, Bbh, Bbl, kbeg, lda, ldb);
    asm volatile("cp.async.commit_group;" ::: "memory");

    int s = 0;
    for (int k0 = kbeg; k0 < kend; k0 += BK, s ^= 1) {
        if (k0 + BK < kend)
            stage_fill<SA,SB>(sb + (uint32_t)(s ^ 1) * STG_W * 4u,
                              Abh, Abl, Bbh, Bbl, k0 + BK, lda, ldb);
        asm volatile("cp.async.commit_group;" ::: "memory");
        asm volatile("cp.async.wait_group 1;" ::: "memory");
        __syncthreads();

        const uint32_t stg = sb + (uint32_t)s * STG_W * 4u;
        #pragma unroll
        for (int kk = 0; kk < 16; kk += 8) {
            uint32_t aH[2][4], aL[2][4];
            ldsm_x4(aH[0], stg + 0u*ARR_W*4u + (uint32_t)(a_off + kk) * 4u);
            ldsm_x4(aH[1], stg + 0u*ARR_W*4u + (uint32_t)(a_off + kk + 16*LDP) * 4u);
            if (SA) {
                ldsm_x4(aL[0], stg + 1u*ARR_W*4u + (uint32_t)(a_off + kk) * 4u);
                ldsm_x4(aL[1], stg + 1u*ARR_W*4u + (uint32_t)(a_off + kk + 16*LDP) * 4u);
            }
            #pragma unroll
            for (int ni2 = 0; ni2 < 4; ni2++) {
                uint32_t bH4[4], bL4[4];
                ldsm_x4(bH4, stg + 2u*ARR_W*4u + (uint32_t)(b_off + kk + ni2*16*LDP) * 4u);
                if (SB)
                    ldsm_x4(bL4, stg + 3u*ARR_W*4u + (uint32_t)(b_off + kk + ni2*16*LDP) * 4u);
                #pragma unroll
                for (int h = 0; h < 2; h++) {
                    int ni = ni2 * 2 + h;
                    #pragma unroll
                    for (int mi = 0; mi < 2; mi++) {
                        mma_f16(acc[mi][ni], aH[mi], bH4[h*2], bH4[h*2+1]);
                        if (SB) mma_f16(acc[mi][ni], aH[mi], bL4[h*2], bL4[h*2+1]);
                        if (SA) mma_f16(acc[mi][ni], aL[mi], bH4[h*2], bH4[h*2+1]);
                    }
                }
            }
        }
        __syncthreads();
    }

    #pragma unroll
    for (int mi = 0; mi < 2; mi++)
        #pragma unroll
        for (int ni = 0; ni < 8; ni++) {
            int row = blockIdx.y * BM + mbase + mi * 16 + grp;
            int col = blockIdx.x * BN + nbase + ni * 8 + tig * 2;
            float c0 = acc[mi][ni][0], c1 = acc[mi][ni][1];
            float c2 = acc[mi][ni][2], c3 = acc[mi][ni][3];
            if (MODE == 0) {
                *(float2*)&C[(size_t)row * ldc + col]       = make_float2(c0, c1);
                *(float2*)&C[(size_t)(row + 8) * ldc + col] = make_float2(c2, c3);
            } else if (MODE == 1) {
                atomicAdd(&C[(size_t)row * ldc + col],           c0);
                atomicAdd(&C[(size_t)row * ldc + col + 1],       c1);
                atomicAdd(&C[(size_t)(row + 8) * ldc + col],     c2);
                atomicAdd(&C[(size_t)(row + 8) * ldc + col + 1], c3);
            } else {
                float b0 = bias[col], b1 = bias[col + 1];
                float v0 = (c0 + b0) * scale, v1 = (c1 + b1) * scale;
                float v2 = (c2 + b0) * scale, v3 = (c3 + b1) * scale;
                if (MODE == 3) {
                    *(float2*)&C[(size_t)row * ldc + col]       = make_float2(v0, v1);
                    *(float2*)&C[(size_t)(row + 8) * ldc + col] = make_float2(v2, v3);
                }
                if (MODE == 4) {
                    *(uint32_t*)(oh + (size_t)row * ldc + col)       = pack2h(v0, v1);
                    *(uint32_t*)(oh + (size_t)(row + 8) * ldc + col) = pack2h(v2, v3);
                } else {
                    split2(oh, ol, (size_t)row * ldc + col,       v0, v1);
                    split2(oh, ol, (size_t)(row + 8) * ldc + col, v2, v3);
                }
            }
        }
}

// ---------------- GEMM wrapper kernels ----------------
__global__ void __launch_bounds__(256, 2) k_qproj(const float* __restrict__ bias) {
    // 1-term: x SINGLE, Wq SINGLE -> q single fp16
    gemm_core<4,false,false>(xh, nullptr, wqh, nullptr, nullptr, qh, nullptr, bias, ATT_SCALE,
                             0, D_MODEL, D_MODEL, D_MODEL, NQ);
}
__global__ void __launch_bounds__(256, 2) k_kvproj(const float* __restrict__ bias) {
    gemm_core<3,true,true>(xh, xl, wkh, wkl, g_kv, kvh, kvl, bias, 1.f,
                           0, D_MODEL, D_MODEL, D_MODEL, NKV);
}
__global__ void __launch_bounds__(256, 2) k_scores() {
    // 1-term: q SINGLE, K SINGLE (kvh = fp16 hi of k)
    int batch = blockIdx.z;                 // g*H + h
    int g = batch >> 4;
    gemm_core<0,false,false>(qh + batch * DQK, nullptr,
                             kvh + g * DQK,   nullptr,
                             g_scores + (size_t)batch * S_LEN * S_LEN,
                             nullptr, nullptr, nullptr, 1.f,
                             0, DQK, NQ, NKV, S_LEN);
}
__global__ void __launch_bounds__(256, 2) k_pv() {
    // 1-term: P SINGLE, V SINGLE
    int batch = blockIdx.z;
    int g = batch >> 4;
    gemm_core<0,false,false>(ph + (size_t)batch * S_LEN * S_LEN, nullptr,
                             vth + (size_t)g * DVV * S_LEN, nullptr,
                             g_z + batch * DVV, nullptr, nullptr, nullptr, 1.f,
                             0, S_LEN, S_LEN, S_LEN, ZD);
}
__global__ void __launch_bounds__(256, 2) k_ffn1() {
    // 1-term: z SINGLE, W1 SINGLE
    int kb = blockIdx.z * (ZD / 2);
    gemm_core<1,false,false>(zh, nullptr, w1h, nullptr, g_h1, nullptr, nullptr, nullptr, 1.f,
                             kb, kb + ZD / 2, ZD, ZD, FF2);
}
__global__ void __launch_bounds__(256, 2) k_ffn2(float* __restrict__ out) {
    int kb = blockIdx.z * (FF2 / 4);
    gemm_core<1,true,true>(h1h, h1l, w2h, w2l, out, nullptr, nullptr, nullptr, 1.f,
                           kb, kb + FF2 / 4, FF2, FF2, FF_OUT);
}

// ---------------- rmsnorm (vectorized; split or single output) --------------
template<bool SPLIT>
__device__ __forceinline__ void rms_body(const float* __restrict__ in,
                                         const float* __restrict__ gamma,
                                         hf* __restrict__ oh, hf* __restrict__ ol,
                                         int cols)
{
    const float4* x4 = (const float4*)(in + (size_t)blockIdx.x * cols);
    const float4* g4 = (const float4*)gamma;
    size_t obase = (size_t)blockIdx.x * cols;
    int nv = cols >> 2;
    float ss = 0.f;
    for (int c = threadIdx.x; c < nv; c += blockDim.x) {
        float4 v = x4[c];
        ss += v.x*v.x + v.y*v.y + v.z*v.z + v.w*v.w;
    }
    __shared__ float red[33];
    #pragma unroll
    for (int o = 16; o; o >>= 1) ss += __shfl_xor_sync(0xffffffffu, ss, o);
    if ((threadIdx.x & 31) == 0) red[threadIdx.x >> 5] = ss;
    __syncthreads();
    if (threadIdx.x < 32) {
        float v = (threadIdx.x < (blockDim.x >> 5)) ? red[threadIdx.x] : 0.f;
        #pragma unroll
        for (int o = 16; o; o >>= 1) v += __shfl_xor_sync(0xffffffffu, v, o);
        if (threadIdx.x == 0) red[32] = v;
    }
    __syncthreads();
    float scale = sqrtf((float)cols) / fmaxf(sqrtf(red[32]), 1e-12f);
    for (int c = threadIdx.x; c < nv; c += blockDim.x) {
        float4 v = x4[c];
        float4 g = g4[c];
        v.x *= scale * g.x; v.y *= scale * g.y; v.z *= scale * g.z; v.w *= scale * g.w;
        if (SPLIT)
            split4(oh, ol, obase + (size_t)c * 4, v);
        else
            *(uint2*)(oh + obase + (size_t)c * 4) =
                make_uint2(pack2h(v.x, v.y), pack2h(v.z, v.w));
    }
}
__global__ void k_rms_x(const float* __restrict__ x, const float* __restrict__ gamma) {
    rms_body<true>(x, gamma, xh, xl, D_MODEL);
}
__global__ void k_rms_z(const float* __restrict__ gamma) {
    rms_body<false>(g_z, gamma, zh, nullptr, ZD);
}

// ---------------- weight split (vectorized; Wq,W1 single fp16) --------------
__global__ void k_split_w(const float* __restrict__ src, int which) {
    size_t i4 = ((size_t)blockIdx.x * 256 + threadIdx.x) * 4;
    float4 v = *(const float4*)(src + i4);
    switch (which) {
        case 0: *(uint2*)(wqh + i4) = make_uint2(pack2h(v.x, v.y), pack2h(v.z, v.w)); break;
        case 1: split4(wkh, wkl, i4, v); break;
        case 2: *(uint2*)(w1h + i4) = make_uint2(pack2h(v.x, v.y), pack2h(v.z, v.w)); break;
        case 3: split4(w2h, w2l, i4, v); break;
    }
}

// ---------------- elementwise kernels ----------------
// tiled transpose: vt[g][d][t] = kv[t][NKHALF + g*128 + d]  (single fp16)
__global__ void k_vt_build() {
    __shared__ float tile[32][33];
    int t0 = blockIdx.x * 32, d0 = blockIdx.y * 32, g = blockIdx.z;
    #pragma unroll
    for (int j = 0; j < 4; j++) {
        int t = t0 + threadIdx.y + 8 * j;
        tile[threadIdx.y + 8 * j][threadIdx.x] =
            g_kv[(size_t)t * NKV + NKHALF + g * DVV + d0 + threadIdx.x];
    }
    __syncthreads();
    #pragma unroll
    for (int j = 0; j < 4; j++) {
        int d = d0 + threadIdx.y + 8 * j;
        vth[((size_t)g * DVV + d) * S_LEN + t0 + threadIdx.x] =
            __float2half_rn(tile[threadIdx.x][threadIdx.y + 8 * j]);
    }
}
__global__ void k_zero_h1() {
    size_t i4 = ((size_t)blockIdx.x * 256 + threadIdx.x) * 4;
    *(float4*)(g_h1 + i4) = make_float4(0.f, 0.f, 0.f, 0.f);
}
__global__ void k_zero_out(float* __restrict__ out) {
    size_t i4 = ((size_t)blockIdx.x * 256 + threadIdx.x) * 4;
    *(float4*)(out + i4) = make_float4(0.f, 0.f, 0.f, 0.f);
}
__global__ void k_silu_h1(const float* __restrict__ bias) {
    size_t i4 = ((size_t)blockIdx.x * 256 + threadIdx.x) * 4;
    float4 v = *(const float4*)(g_h1 + i4);
    float4 b = *(const float4*)(bias + (i4 & (FF2 - 1)));
    v.x += b.x; v.y += b.y; v.z += b.z; v.w += b.w;
    v.x /= (1.f + __expf(-v.x)); v.y /= (1.f + __expf(-v.y));
    v.z /= (1.f + __expf(-v.z)); v.w /= (1.f + __expf(-v.w));
    split4(h1h, h1l, i4, v);
}
__global__ void k_silu_out(float* __restrict__ C, const float* __restrict__ bias) {
    size_t i4 = ((size_t)blockIdx.x * 256 + threadIdx.x) * 4;
    float4 v = *(const float4*)(C + i4);
    float4 b = *(const float4*)(bias + (i4 & (FF_OUT - 1)));
    v.x += b.x; v.y += b.y; v.z += b.z; v.w += b.w;
    v.x /= (1.f + __expf(-v.x)); v.y /= (1.f + __expf(-v.y));
    v.z /= (1.f + __expf(-v.z)); v.w /= (1.f + __expf(-v.w));
    *(float4*)(C + i4) = v;
}

// ---------------- row softmax over 1024 cols (q pre-scaled; P -> single fp16)
__global__ void k_softmax() {
    size_t rbase = (size_t)blockIdx.x * S_LEN;
    const float4* row4 = (const float4*)(g_scores + rbase);
    __shared__ float red[33];
    int tid = threadIdx.x;
    float4 v = row4[tid];
    float m = fmaxf(fmaxf(v.x, v.y), fmaxf(v.z, v.w));
    #pragma unroll
    for (int o = 16; o; o >>= 1) m = fmaxf(m, __shfl_xor_sync(0xffffffffu, m, o));
    if ((tid & 31) == 0) red[tid >> 5] = m;
    __syncthreads();
    if (tid < 32) {
        float t = (tid < 8) ? red[tid] : -1e30f;
        #pragma unroll
        for (int o = 4; o; o >>= 1) t = fmaxf(t, __shfl_xor_sync(0xffffffffu, t, o));
        if (tid == 0) red[32] = t;
    }
    __syncthreads();
    m = red[32];
    __syncthreads();
    v.x = __expf(v.x - m); v.y = __expf(v.y - m);
    v.z = __expf(v.z - m); v.w = __expf(v.w - m);
    float s = v.x + v.y + v.z + v.w;
    #pragma unroll
    for (int o = 16; o; o >>= 1) s += __shfl_xor_sync(0xffffffffu, s, o);
    if ((tid & 31) == 0) red[tid >> 5] = s;
    __syncthreads();
    if (tid < 32) {
        float t = (tid < 8) ? red[tid] : 0.f;
        #pragma unroll
        for (int o = 4; o; o >>= 1) t += __shfl_xor_sync(0xffffffffu, t, o);
        if (tid == 0) red[32] = t;
    }
    __syncthreads();
    float inv = 1.f / red[32];
    *(uint2*)(ph + rbase + (size_t)tid * 4) =
        make_uint2(pack2h(v.x * inv, v.y * inv), pack2h(v.z * inv, v.w * inv));
}

// ---------------- launch ----------------
extern "C" void kernel_launch(void* const* d_in, const int* in_sizes, int n_in,
                              void* d_out, int out_size) {
    const float* x     = (const float*)d_in[0];
    const float* gin   = (const float*)d_in[1];
    const float* Wq_w  = (const float*)d_in[2];
    const float* Wq_b  = (const float*)d_in[3];
    const float* Wkv_w = (const float*)d_in[4];
    const float* Wkv_b = (const float*)d_in[5];
    const float* gz    = (const float*)d_in[6];
    const float* W1    = (const float*)d_in[7];
    const float* b1    = (const float*)d_in[8];
    const float* W2    = (const float*)d_in[9];
    const float* b2    = (const float*)d_in[10];
    float* out = (float*)d_out;

    cudaFuncSetAttribute(k_qproj,  cudaFuncAttributeMaxDynamicSharedMemorySize, SMEM_BYTES);
    cudaFuncSetAttribute(k_kvproj, cudaFuncAttributeMaxDynamicSharedMemorySize, SMEM_BYTES);
    cudaFuncSetAttribute(k_scores, cudaFuncAttributeMaxDynamicSharedMemorySize, SMEM_BYTES);
    cudaFuncSetAttribute(k_pv,     cudaFuncAttributeMaxDynamicSharedMemorySize, SMEM_BYTES);
    cudaFuncSetAttribute(k_ffn1,   cudaFuncAttributeMaxDynamicSharedMemorySize, SMEM_BYTES);
    cudaFuncSetAttribute(k_ffn2,   cudaFuncAttributeMaxDynamicSharedMemorySize, SMEM_BYTES);

    k_rms_x   <<<S_LEN, 256>>>(x, gin);
    k_split_w <<<(NQ * D_MODEL) / 1024, 256>>>(Wq_w, 0);
    k_split_w <<<(NKV * D_MODEL) / 1024, 256>>>(Wkv_w, 1);
    k_split_w <<<(FF2 * ZD) / 1024, 256>>>(W1, 2);
    k_split_w <<<(FF_OUT * FF2) / 1024, 256>>>(W2, 3);

    k_qproj   <<<dim3(NQ / BN,     S_LEN / BM), 256, SMEM_BYTES>>>(Wq_b);
    k_kvproj  <<<dim3(NKV / BN,    S_LEN / BM), 256, SMEM_BYTES>>>(Wkv_b);
    k_vt_build<<<dim3(S_LEN / 32, DVV / 32, G_GRP), dim3(32, 8)>>>();

    k_scores  <<<dim3(S_LEN / BN,  S_LEN / BM, G_GRP * H_HEADS), 256, SMEM_BYTES>>>();
    k_softmax <<<G_GRP * H_HEADS * S_LEN, 256>>>();
    k_pv      <<<dim3(1,           S_LEN / BM, G_GRP * H_HEADS), 256, SMEM_BYTES>>>();

    k_rms_z   <<<S_LEN, 256>>>(gz);
    k_zero_h1 <<<(S_LEN * FF2) / 1024, 256>>>();
    k_ffn1    <<<dim3(FF2 / BN,    S_LEN / BM, 2), 256, SMEM_BYTES>>>();
    k_silu_h1 <<<(S_LEN * FF2) / 1024, 256>>>(b1);
    k_zero_out<<<(S_LEN * FF_OUT) / 1024, 256>>>(out);
    k_ffn2    <<<dim3(FF_OUT / BN, S_LEN / BM, 4), 256, SMEM_BYTES>>>(out);
    k_silu_out<<<(S_LEN * FF_OUT) / 1024, 256>>>(out, b2);
}

// round 15
// speedup vs baseline: 5.5043x; 1.0193x over previous
#include <cuda_runtime.h>
#include <cuda_fp16.h>
#include <math.h>
#include <stdint.h>

// ---------------- problem constants ----------------
#define S_LEN   1024
#define D_MODEL 1024
#define G_GRP   8
#define H_HEADS 16
#define DQK     128
#define DVV     128
#define FF_OUT  1024
#define NQ      (G_GRP*H_HEADS*DQK)    /* 16384 */
#define NKV     (G_GRP*(DQK+DVV))      /* 2048  */
#define NKHALF  (G_GRP*DQK)            /* 1024  */
#define ZD      NQ                     /* 16384 */
#define FF2     (2*FF_OUT)             /* 2048  */
#define ATT_SCALE 0.08838834764831845f /* 1/sqrt(128) */

typedef __half hf;

// ---------------- scratch (device globals; referenced ONLY in device code) ---
// (passing these as kernel args from host passes the host shadow — R2-R4 bug)
__device__ __align__(256) float g_kv[S_LEN*NKV];
__device__ __align__(256) float g_z[S_LEN*ZD];
__device__ __align__(256) float g_h1[S_LEN*FF2];

// fp16 operands. Split pairs where precision-critical; single fp16 where the
// calibrated error budget allows (q, Wq, K, scores, P, V, z@ffn1, W1).
__device__ __align__(256) hf xh [S_LEN*D_MODEL],  xl [S_LEN*D_MODEL];
__device__ __align__(256) hf wqh[NQ*D_MODEL];                       // SINGLE
__device__ __align__(256) hf wkh[NKV*D_MODEL],    wkl[NKV*D_MODEL];
__device__ __align__(256) hf qh [S_LEN*NQ];                         // SINGLE
__device__ __align__(256) hf kvh[S_LEN*NKV],      kvl[S_LEN*NKV];   // kvh doubles as single-K
__device__ __align__(256) hf vth[G_GRP*DVV*S_LEN];                  // SINGLE (V)
__device__ __align__(256) hf sch[134217728];                        // SINGLE (raw scores)
__device__ __align__(256) hf ph [134217728];                        // SINGLE (softmax P)
__device__ __align__(256) hf zh [S_LEN*ZD];                         // SINGLE (z)
__device__ __align__(256) hf w1h[FF2*ZD];                           // SINGLE
__device__ __align__(256) hf h1h[S_LEN*FF2],      h1l[S_LEN*FF2];
__device__ __align__(256) hf w2h[FF_OUT*FF2],     w2l[FF_OUT*FF2];

// ---------------- helpers ----------------
__device__ __forceinline__ uint32_t pack2h(float x, float y) {
    __half2 p = __floats2half2_rn(x, y);
    return *reinterpret_cast<uint32_t*>(&p);
}
// split a pair of consecutive values (i must be 2-aligned)
__device__ __forceinline__ void split2(hf* dh, hf* dl, size_t i, float x, float y) {
    float hx = __half2float(__float2half_rn(x));
    float hy = __half2float(__float2half_rn(y));
    *(uint32_t*)(dh + i) = pack2h(hx, hy);
    *(uint32_t*)(dl + i) = pack2h(x - hx, y - hy);
}
__device__ __forceinline__ void split4(hf* dh, hf* dl, size_t i4, float4 v) {
    float hx = __half2float(__float2half_rn(v.x));
    float hy = __half2float(__float2half_rn(v.y));
    float hz = __half2float(__float2half_rn(v.z));
    float hw = __half2float(__float2half_rn(v.w));
    *(uint2*)(dh + i4) = make_uint2(pack2h(hx, hy), pack2h(hz, hw));
    *(uint2*)(dl + i4) = make_uint2(pack2h(v.x - hx, v.y - hy), pack2h(v.z - hz, v.w - hw));
}

// ---------------- fp16 split mma GEMM, 2-stage cp.async + ldmatrix ----------
// C(128x128 tile) = A(MxK)@B(NxK)^T
// terms: Ah*Bh always; + Ah*Bl if SB; + Al*Bh if SA   (fp32 accum)

__device__ __forceinline__ void mma_f16(float* d, const uint32_t* a, uint32_t b0, uint32_t b1) {
    asm volatile(
        "mma.sync.aligned.m16n8k16.row.col.f32.f16.f16.f32 "
        "{%0,%1,%2,%3}, {%4,%5,%6,%7}, {%8,%9}, {%0,%1,%2,%3};"
        : "+f"(d[0]), "+f"(d[1]), "+f"(d[2]), "+f"(d[3])
        : "r"(a[0]), "r"(a[1]), "r"(a[2]), "r"(a[3]), "r"(b0), "r"(b1));
}
__device__ __forceinline__ void ldsm_x4(uint32_t* r, uint32_t saddr) {
    asm volatile("ldmatrix.sync.aligned.m8n8.x4.shared.b16 {%0,%1,%2,%3}, [%4];"
        : "=r"(r[0]), "=r"(r[1]), "=r"(r[2]), "=r"(r[3]) : "r"(saddr));
}

#define BM 128
#define BN 128
#define BK 32
#define LDP 20                       /* row stride words: 80B = 16B-aligned + conflict-free */
#define ARR_W (BM*LDP)               /* words per array  = 2560 (10240 B)     */
#define STG_W (4*ARR_W)              /* words per stage  = 10240 (40960 B)    */
#define SMEM_BYTES (2*STG_W*4)       /* 81920 B dynamic (2 stages)            */

__device__ __forceinline__ void cp16(uint32_t dst, const void* src) {
    asm volatile("cp.async.cg.shared.global [%0], [%1], 16;" :: "r"(dst), "l"(src));
}

template<bool SA, bool SB>
__device__ __forceinline__ void stage_fill(
    uint32_t sbase,
    const hf* __restrict__ Ah, const hf* __restrict__ Al,
    const hf* __restrict__ Bh, const hf* __restrict__ Bl,
    int k0, int lda, int ldb)
{
    int tid = threadIdx.x;
    #pragma unroll
    for (int j = 0; j < 2; j++) {
        int chunk = tid + j * 256;            // 0..511
        int row = chunk >> 2;                 // 0..127
        int seg = chunk & 3;                  // 16B segment within 64B row
        uint32_t off = (uint32_t)(row * LDP * 4 + seg * 16);
        size_t a_off = (size_t)row * lda + k0 + seg * 8;
        size_t b_off = (size_t)row * ldb + k0 + seg * 8;
        cp16(sbase + 0u*ARR_W*4u + off, Ah + a_off);
        if (SA) cp16(sbase + 1u*ARR_W*4u + off, Al + a_off);
        cp16(sbase + 2u*ARR_W*4u + off, Bh + b_off);
        if (SB) cp16(sbase + 3u*ARR_W*4u + off, Bl + b_off);
    }
}

// MODE: 0 = plain fp32 store, 1 = atomic fp32 add,
//       2 = (acc+bias)*scale -> split(oh,ol),
//       3 = acc+bias -> C fp32 AND split(oh,ol),
//       4 = (acc+bias)*scale -> single fp16(oh),
//       5 = acc -> single fp16(oh)            (no bias)
template<int MODE, bool SA, bool SB>
__device__ __forceinline__ void gemm_core(
    const hf* __restrict__ Ah, const hf* __restrict__ Al,
    const hf* __restrict__ Bh, const hf* __restrict__ Bl,
    float* __restrict__ C, hf* __restrict__ oh, hf* __restrict__ ol,
    const float* __restrict__ bias, float scale,
    int kbeg, int kend, int lda, int ldb, int ldc)
{
    extern __shared__ uint32_t sh[];
    const uint32_t sb = (uint32_t)__cvta_generic_to_shared(sh);

    const int tid  = threadIdx.x;
    const int wid  = tid >> 5;
    const int lane = tid & 31;
    const int grp  = lane >> 2;
    const int tig  = lane & 3;
    const int mbase = (wid & 3) * 32;
    const int nbase = (wid >> 2) * 64;

    const hf* Abh = Ah + (size_t)blockIdx.y * BM * lda;
    const hf* Abl = SA ? Al + (size_t)blockIdx.y * BM * lda : nullptr;
    const hf* Bbh = Bh + (size_t)blockIdx.x * BN * ldb;
    const hf* Bbl = SB ? Bl + (size_t)blockIdx.x * BN * ldb : nullptr;

    const int a_off = (mbase + (lane & 15)) * LDP + ((lane & 16) ? 4 : 0);
    const int b_off = (nbase + ((lane >> 4) * 8) + (lane & 7)) * LDP + ((lane & 8) ? 4 : 0);

    float acc[2][8][4];
    #pragma unroll
    for (int mi = 0; mi < 2; mi++)
        #pragma unroll
        for (int ni = 0; ni < 8; ni++)
            #pragma unroll
            for (int v = 0; v < 4; v++) acc[mi][ni][v] = 0.f;

    stage_fill<SA,SB>(sb, Abh, Abl, Bbh, Bbl, kbeg, lda, ldb);
    asm volatile("cp.async.commit_group;" ::: "memory");

    int s = 0;
    for (int k0 = kbeg; k0 < kend; k0 += BK, s ^= 1) {
        if (k0 + BK < kend)
            stage_fill<SA,SB>(sb + (uint32_t)(s ^ 1) * STG_W * 4u,
                              Abh, Abl, Bbh, Bbl, k0 + BK, lda, ldb);
        asm volatile("cp.async.commit_group;" ::: "memory");
        asm volatile("cp.async.wait_group 1;" ::: "memory");
        __syncthreads();

        const uint32_t stg = sb + (uint32_t)s * STG_W * 4u;
        #pragma unroll
        for (int kk = 0; kk < 16; kk += 8) {
            uint32_t aH[2][4], aL[2][4];
            ldsm_x4(aH[0], stg + 0u*ARR_W*4u + (uint32_t)(a_off + kk) * 4u);
            ldsm_x4(aH[1], stg + 0u*ARR_W*4u + (uint32_t)(a_off + kk + 16*LDP) * 4u);
            if (SA) {
                ldsm_x4(aL[0], stg + 1u*ARR_W*4u + (uint32_t)(a_off + kk) * 4u);
                ldsm_x4(aL[1], stg + 1u*ARR_W*4u + (uint32_t)(a_off + kk + 16*LDP) * 4u);
            }
            #pragma unroll
            for (int ni2 = 0; ni2 < 4; ni2++) {
                uint32_t bH4[4], bL4[4];
                ldsm_x4(bH4, stg + 2u*ARR_W*4u + (uint32_t)(b_off + kk + ni2*16*LDP) * 4u);
                if (SB)
                    ldsm_x4(bL4, stg + 3u*ARR_W*4u + (uint32_t)(b_off + kk + ni2*16*LDP) * 4u);
                #pragma unroll
                for (int h = 0; h < 2; h++) {
                    int ni = ni2 * 2 + h;
                    #pragma unroll
                    for (int mi = 0; mi < 2; mi++) {
                        mma_f16(acc[mi][ni], aH[mi], bH4[h*2], bH4[h*2+1]);
                        if (SB) mma_f16(acc[mi][ni], aH[mi], bL4[h*2], bL4[h*2+1]);
                        if (SA) mma_f16(acc[mi][ni], aL[mi], bH4[h*2], bH4[h*2+1]);
                    }
                }
            }
        }
        __syncthreads();
    }

    #pragma unroll
    for (int mi = 0; mi < 2; mi++)
        #pragma unroll
        for (int ni = 0; ni < 8; ni++) {
            int row = blockIdx.y * BM + mbase + mi * 16 + grp;
            int col = blockIdx.x * BN + nbase + ni * 8 + tig * 2;
            float c0 = acc[mi][ni][0], c1 = acc[mi][ni][1];
            float c2 = acc[mi][ni][2], c3 = acc[mi][ni][3];
            if (MODE == 0) {
                *(float2*)&C[(size_t)row * ldc + col]       = make_float2(c0, c1);
                *(float2*)&C[(size_t)(row + 8) * ldc + col] = make_float2(c2, c3);
            } else if (MODE == 1) {
                atomicAdd(&C[(size_t)row * ldc + col],           c0);
                atomicAdd(&C[(size_t)row * ldc + col + 1],       c1);
                atomicAdd(&C[(size_t)(row + 8) * ldc + col],     c2);
                atomicAdd(&C[(size_t)(row + 8) * ldc + col + 1], c3);
            } else if (MODE == 5) {
                *(uint32_t*)(oh + (size_t)row * ldc + col)       = pack2h(c0, c1);
                *(uint32_t*)(oh + (size_t)(row + 8) * ldc + col) = pack2h(c2, c3);
            } else {
                float b0 = bias[col], b1 = bias[col + 1];
                float v0 = (c0 + b0) * scale, v1 = (c1 + b1) * scale;
                float v2 = (c2 + b0) * scale, v3 = (c3 + b1) * scale;
                if (MODE == 3) {
                    *(float2*)&C[(size_t)row * ldc + col]       = make_float2(v0, v1);
                    *(float2*)&C[(size_t)(row + 8) * ldc + col] = make_float2(v2, v3);
                }
                if (MODE == 4) {
                    *(uint32_t*)(oh + (size_t)row * ldc + col)       = pack2h(v0, v1);
                    *(uint32_t*)(oh + (size_t)(row + 8) * ldc + col) = pack2h(v2, v3);
                } else {
                    split2(oh, ol, (size_t)row * ldc + col,       v0, v1);
                    split2(oh, ol, (size_t)(row + 8) * ldc + col, v2, v3);
                }
            }
        }
}

// ---------------- GEMM wrapper kernels ----------------
__global__ void __launch_bounds__(256, 2) k_qproj(const float* __restrict__ bias) {
    // 1-term: x SINGLE, Wq SINGLE -> q single fp16
    gemm_core<4,false,false>(xh, nullptr, wqh, nullptr, nullptr, qh, nullptr, bias, ATT_SCALE,
                             0, D_MODEL, D_MODEL, D_MODEL, NQ);
}
__global__ void __launch_bounds__(256, 2) k_kvproj(const float* __restrict__ bias) {
    gemm_core<3,true,true>(xh, xl, wkh, wkl, g_kv, kvh, kvl, bias, 1.f,
                           0, D_MODEL, D_MODEL, D_MODEL, NKV);
}
__global__ void __launch_bounds__(256, 2) k_scores() {
    // 1-term: q SINGLE, K SINGLE -> raw scores stored fp16
    int batch = blockIdx.z;                 // g*H + h
    int g = batch >> 4;
    gemm_core<5,false,false>(qh + batch * DQK, nullptr,
                             kvh + g * DQK,   nullptr,
                             nullptr, sch + (size_t)batch * S_LEN * S_LEN, nullptr,
                             nullptr, 1.f,
                             0, DQK, NQ, NKV, S_LEN);
}
__global__ void __launch_bounds__(256, 2) k_pv() {
    // 1-term: P SINGLE, V SINGLE
    int batch = blockIdx.z;
    int g = batch >> 4;
    gemm_core<0,false,false>(ph + (size_t)batch * S_LEN * S_LEN, nullptr,
                             vth + (size_t)g * DVV * S_LEN, nullptr,
                             g_z + batch * DVV, nullptr, nullptr, nullptr, 1.f,
                             0, S_LEN, S_LEN, S_LEN, ZD);
}
__global__ void __launch_bounds__(256, 2) k_ffn1() {
    // 1-term: z SINGLE, W1 SINGLE
    int kb = blockIdx.z * (ZD / 2);
    gemm_core<1,false,false>(zh, nullptr, w1h, nullptr, g_h1, nullptr, nullptr, nullptr, 1.f,
                             kb, kb + ZD / 2, ZD, ZD, FF2);
}
__global__ void __launch_bounds__(256, 2) k_ffn2(float* __restrict__ out) {
    int kb = blockIdx.z * (FF2 / 4);
    gemm_core<1,true,true>(h1h, h1l, w2h, w2l, out, nullptr, nullptr, nullptr, 1.f,
                           kb, kb + FF2 / 4, FF2, FF2, FF_OUT);
}

// ---------------- rmsnorm (vectorized; split or single output) --------------
template<bool SPLIT>
__device__ __forceinline__ void rms_body(const float* __restrict__ in,
                                         const float* __restrict__ gamma,
                                         hf* __restrict__ oh, hf* __restrict__ ol,
                                         int cols)
{
    const float4* x4 = (const float4*)(in + (size_t)blockIdx.x * cols);
    const float4* g4 = (const float4*)gamma;
    size_t obase = (size_t)blockIdx.x * cols;
    int nv = cols >> 2;
    float ss = 0.f;
    for (int c = threadIdx.x; c < nv; c += blockDim.x) {
        float4 v = x4[c];
        ss += v.x*v.x + v.y*v.y + v.z*v.z + v.w*v.w;
    }
    __shared__ float red[33];
    #pragma unroll
    for (int o = 16; o; o >>= 1) ss += __shfl_xor_sync(0xffffffffu, ss, o);
    if ((threadIdx.x & 31) == 0) red[threadIdx.x >> 5] = ss;
    __syncthreads();
    if (threadIdx.x < 32) {
        float v = (threadIdx.x < (blockDim.x >> 5)) ? red[threadIdx.x] : 0.f;
        #pragma unroll
        for (int o = 16; o; o >>= 1) v += __shfl_xor_sync(0xffffffffu, v, o);
        if (threadIdx.x == 0) red[32] = v;
    }
    __syncthreads();
    float scale = sqrtf((float)cols) / fmaxf(sqrtf(red[32]), 1e-12f);
    for (int c = threadIdx.x; c < nv; c += blockDim.x) {
        float4 v = x4[c];
        float4 g = g4[c];
        v.x *= scale * g.x; v.y *= scale * g.y; v.z *= scale * g.z; v.w *= scale * g.w;
        if (SPLIT)
            split4(oh, ol, obase + (size_t)c * 4, v);
        else
            *(uint2*)(oh + obase + (size_t)c * 4) =
                make_uint2(pack2h(v.x, v.y), pack2h(v.z, v.w));
    }
}
__global__ void k_rms_x(const float* __restrict__ x, const float* __restrict__ gamma) {
    rms_body<true>(x, gamma, xh, xl, D_MODEL);
}
__global__ void k_rms_z(const float* __restrict__ gamma) {
    rms_body<false>(g_z, gamma, zh, nullptr, ZD);
}

// ---------------- weight split (vectorized; Wq,W1 single fp16) --------------
__global__ void k_split_w(const float* __restrict__ src, int which) {
    size_t i4 = ((size_t)blockIdx.x * 256 + threadIdx.x) * 4;
    float4 v = *(const float4*)(src + i4);
    switch (which) {
        case 0: *(uint2*)(wqh + i4) = make_uint2(pack2h(v.x, v.y), pack2h(v.z, v.w)); break;
        case 1: split4(wkh, wkl, i4, v); break;
        case 2: *(uint2*)(w1h + i4) = make_uint2(pack2h(v.x, v.y), pack2h(v.z, v.w)); break;
        case 3: split4(w2h, w2l, i4, v); break;
    }
}

// ---------------- elementwise kernels ----------------
// tiled transpose: vt[g][d][t] = kv[t][NKHALF + g*128 + d]  (single fp16)
__global__ void k_vt_build() {
    __shared__ float tile[32][33];
    int t0 = blockIdx.x * 32, d0 = blockIdx.y * 32, g = blockIdx.z;
    #pragma unroll
    for (int j = 0; j < 4; j++) {
        int t = t0 + threadIdx.y + 8 * j;
        tile[threadIdx.y + 8 * j][threadIdx.x] =
            g_kv[(size_t)t * NKV + NKHALF + g * DVV + d0 + threadIdx.x];
    }
    __syncthreads();
    #pragma unroll
    for (int j = 0; j < 4; j++) {
        int d = d0 + threadIdx.y + 8 * j;
        vth[((size_t)g * DVV + d) * S_LEN + t0 + threadIdx.x] =
            __float2half_rn(tile[threadIdx.x][threadIdx.y + 8 * j]);
    }
}
__global__ void k_zero_h1() {
    size_t i4 = ((size_t)blockIdx.x * 256 + threadIdx.x) * 4;
    *(float4*)(g_h1 + i4) = make_float4(0.f, 0.f, 0.f, 0.f);
}
__global__ void k_zero_out(float* __restrict__ out) {
    size_t i4 = ((size_t)blockIdx.x * 256 + threadIdx.x) * 4;
    *(float4*)(out + i4) = make_float4(0.f, 0.f, 0.f, 0.f);
}
__global__ void k_silu_h1(const float* __restrict__ bias) {
    size_t i4 = ((size_t)blockIdx.x * 256 + threadIdx.x) * 4;
    float4 v = *(const float4*)(g_h1 + i4);
    float4 b = *(const float4*)(bias + (i4 & (FF2 - 1)));
    v.x += b.x; v.y += b.y; v.z += b.z; v.w += b.w;
    v.x /= (1.f + __expf(-v.x)); v.y /= (1.f + __expf(-v.y));
    v.z /= (1.f + __expf(-v.z)); v.w /= (1.f + __expf(-v.w));
    split4(h1h, h1l, i4, v);
}
__global__ void k_silu_out(float* __restrict__ C, const float* __restrict__ bias) {
    size_t i4 = ((size_t)blockIdx.x * 256 + threadIdx.x) * 4;
    float4 v = *(const float4*)(C + i4);
    float4 b = *(const float4*)(bias + (i4 & (FF_OUT - 1)));
    v.x += b.x; v.y += b.y; v.z += b.z; v.w += b.w;
    v.x /= (1.f + __expf(-v.x)); v.y /= (1.f + __expf(-v.y));
    v.z /= (1.f + __expf(-v.z)); v.w /= (1.f + __expf(-v.w));
    *(float4*)(C + i4) = v;
}

// ---------------- row softmax over 1024 cols (fp16 scores in, fp16 P out) ---
__global__ void k_softmax() {
    size_t rbase = (size_t)blockIdx.x * S_LEN;
    const uint2* row2 = (const uint2*)(sch + rbase);
    __shared__ float red[33];
    int tid = threadIdx.x;
    uint2 raw = row2[tid];
    __half2 h01 = *reinterpret_cast<__half2*>(&raw.x);
    __half2 h23 = *reinterpret_cast<__half2*>(&raw.y);
    float4 v = make_float4(__half2float(__low2half(h01)),  __half2float(__high2half(h01)),
                           __half2float(__low2half(h23)),  __half2float(__high2half(h23)));
    float m = fmaxf(fmaxf(v.x, v.y), fmaxf(v.z, v.w));
    #pragma unroll
    for (int o = 16; o; o >>= 1) m = fmaxf(m, __shfl_xor_sync(0xffffffffu, m, o));
    if ((tid & 31) == 0) red[tid >> 5] = m;
    __syncthreads();
    if (tid < 32) {
        float t = (tid < 8) ? red[tid] : -1e30f;
        #pragma unroll
        for (int o = 4; o; o >>= 1) t = fmaxf(t, __shfl_xor_sync(0xffffffffu, t, o));
        if (tid == 0) red[32] = t;
    }
    __syncthreads();
    m = red[32];
    __syncthreads();
    v.x = __expf(v.x - m); v.y = __expf(v.y - m);
    v.z = __expf(v.z - m); v.w = __expf(v.w - m);
    float s = v.x + v.y + v.z + v.w;
    #pragma unroll
    for (int o = 16; o; o >>= 1) s += __shfl_xor_sync(0xffffffffu, s, o);
    if ((tid & 31) == 0) red[tid >> 5] = s;
    __syncthreads();
    if (tid < 32) {
        float t = (tid < 8) ? red[tid] : 0.f;
        #pragma unroll
        for (int o = 4; o; o >>= 1) t += __shfl_xor_sync(0xffffffffu, t, o);
        if (tid == 0) red[32] = t;
    }
    __syncthreads();
    float inv = 1.f / red[32];
    *(uint2*)(ph + rbase + (size_t)tid * 4) =
        make_uint2(pack2h(v.x * inv, v.y * inv), pack2h(v.z * inv, v.w * inv));
}

// ---------------- launch ----------------
extern "C" void kernel_launch(void* const* d_in, const int* in_sizes, int n_in,
                              void* d_out, int out_size) {
    const float* x     = (const float*)d_in[0];
    const float* gin   = (const float*)d_in[1];
    const float* Wq_w  = (const float*)d_in[2];
    const float* Wq_b  = (const float*)d_in[3];
    const float* Wkv_w = (const float*)d_in[4];
    const float* Wkv_b = (const float*)d_in[5];
    const float* gz    = (const float*)d_in[6];
    const float* W1    = (const float*)d_in[7];
    const float* b1    = (const float*)d_in[8];
    const float* W2    = (const float*)d_in[9];
    const float* b2    = (const float*)d_in[10];
    float* out = (float*)d_out;

    cudaFuncSetAttribute(k_qproj,  cudaFuncAttributeMaxDynamicSharedMemorySize, SMEM_BYTES);
    cudaFuncSetAttribute(k_kvproj, cudaFuncAttributeMaxDynamicSharedMemorySize, SMEM_BYTES);
    cudaFuncSetAttribute(k_scores, cudaFuncAttributeMaxDynamicSharedMemorySize, SMEM_BYTES);
    cudaFuncSetAttribute(k_pv,     cudaFuncAttributeMaxDynamicSharedMemorySize, SMEM_BYTES);
    cudaFuncSetAttribute(k_ffn1,   cudaFuncAttributeMaxDynamicSharedMemorySize, SMEM_BYTES);
    cudaFuncSetAttribute(k_ffn2,   cudaFuncAttributeMaxDynamicSharedMemorySize, SMEM_BYTES);

    k_rms_x   <<<S_LEN, 256>>>(x, gin);
    k_split_w <<<(NQ * D_MODEL) / 1024, 256>>>(Wq_w, 0);
    k_split_w <<<(NKV * D_MODEL) / 1024, 256>>>(Wkv_w, 1);
    k_split_w <<<(FF2 * ZD) / 1024, 256>>>(W1, 2);
    k_split_w <<<(FF_OUT * FF2) / 1024, 256>>>(W2, 3);

    k_qproj   <<<dim3(NQ / BN,     S_LEN / BM), 256, SMEM_BYTES>>>(Wq_b);
    k_kvproj  <<<dim3(NKV / BN,    S_LEN / BM), 256, SMEM_BYTES>>>(Wkv_b);
    k_vt_build<<<dim3(S_LEN / 32, DVV / 32, G_GRP), dim3(32, 8)>>>();

    k_scores  <<<dim3(S_LEN / BN,  S_LEN / BM, G_GRP * H_HEADS), 256, SMEM_BYTES>>>();
    k_softmax <<<G_GRP * H_HEADS * S_LEN, 256>>>();
    k_pv      <<<dim3(1,           S_LEN / BM, G_GRP * H_HEADS), 256, SMEM_BYTES>>>();

    k_rms_z   <<<S_LEN, 256>>>(gz);
    k_zero_h1 <<<(S_LEN * FF2) / 1024, 256>>>();
    k_ffn1    <<<dim3(FF2 / BN,    S_LEN / BM, 2), 256, SMEM_BYTES>>>();
    k_silu_h1 <<<(S_LEN * FF2) / 1024, 256>>>(b1);
    k_zero_out<<<(S_LEN * FF_OUT) / 1024, 256>>>(out);
    k_ffn2    <<<dim3(FF_OUT / BN, S_LEN / BM, 4), 256, SMEM_BYTES>>>(out);
    k_silu_out<<<(S_LEN * FF_OUT) / 1024, 256>>>(out, b2);
}

// round 16
// speedup vs baseline: 5.7730x; 1.0488x over previous
#include <cuda_runtime.h>
#include <cuda_fp16.h>
#include <math.h>
#include <stdint.h>

// ---------------- problem constants ----------------
#define S_LEN   1024
#define D_MODEL 1024
#define G_GRP   8
#define H_HEADS 16
#define DQK     128
#define DVV     128
#define FF_OUT  1024
#define NQ      (G_GRP*H_HEADS*DQK)    /* 16384 */
#define NKV     (G_GRP*(DQK+DVV))      /* 2048  */
#define NKHALF  (G_GRP*DQK)            /* 1024  */
#define ZD      NQ                     /* 16384 */
#define FF2     (2*FF_OUT)             /* 2048  */
#define ATT_SCALE 0.08838834764831845f /* 1/sqrt(128) */

typedef __half hf;

// ---------------- scratch (device globals; referenced ONLY in device code) ---
// (passing these as kernel args from host passes the host shadow — R2-R4 bug)
__device__ __align__(256) float g_kv[S_LEN*NKV];
__device__ __align__(256) float g_z[S_LEN*ZD];
__device__ __align__(256) float g_h1[S_LEN*FF2];

// fp16 operands. Split pairs only where still precision-critical (x, rest single).
__device__ __align__(256) hf xh [S_LEN*D_MODEL],  xl [S_LEN*D_MODEL];
__device__ __align__(256) hf wqh[NQ*D_MODEL];                       // SINGLE
__device__ __align__(256) hf wkh[NKV*D_MODEL];                      // SINGLE
__device__ __align__(256) hf qh [S_LEN*NQ];                         // SINGLE
__device__ __align__(256) hf kvh[S_LEN*NKV];                        // SINGLE (K)
__device__ __align__(256) hf vth[G_GRP*DVV*S_LEN];                  // SINGLE (V)
__device__ __align__(256) hf sch[134217728];                        // SINGLE (raw scores)
__device__ __align__(256) hf ph [134217728];                        // SINGLE (softmax P)
__device__ __align__(256) hf zh [S_LEN*ZD];                         // SINGLE (z)
__device__ __align__(256) hf w1h[FF2*ZD];                           // SINGLE
__device__ __align__(256) hf h1h[S_LEN*FF2];                        // SINGLE
__device__ __align__(256) hf w2h[FF_OUT*FF2];                       // SINGLE

// ---------------- helpers ----------------
__device__ __forceinline__ uint32_t pack2h(float x, float y) {
    __half2 p = __floats2half2_rn(x, y);
    return *reinterpret_cast<uint32_t*>(&p);
}
__device__ __forceinline__ void split4(hf* dh, hf* dl, size_t i4, float4 v) {
    float hx = __half2float(__float2half_rn(v.x));
    float hy = __half2float(__float2half_rn(v.y));
    float hz = __half2float(__float2half_rn(v.z));
    float hw = __half2float(__float2half_rn(v.w));
    *(uint2*)(dh + i4) = make_uint2(pack2h(hx, hy), pack2h(hz, hw));
    *(uint2*)(dl + i4) = make_uint2(pack2h(v.x - hx, v.y - hy), pack2h(v.z - hz, v.w - hw));
}

// ---------------- fp16 split mma GEMM, 2-stage cp.async + ldmatrix ----------
// C(128x128 tile) = A(MxK)@B(NxK)^T
// terms: Ah*Bh always; + Ah*Bl if SB; + Al*Bh if SA   (fp32 accum)

__device__ __forceinline__ void mma_f16(float* d, const uint32_t* a, uint32_t b0, uint32_t b1) {
    asm volatile(
        "mma.sync.aligned.m16n8k16.row.col.f32.f16.f16.f32 "
        "{%0,%1,%2,%3}, {%4,%5,%6,%7}, {%8,%9}, {%0,%1,%2,%3};"
        : "+f"(d[0]), "+f"(d[1]), "+f"(d[2]), "+f"(d[3])
        : "r"(a[0]), "r"(a[1]), "r"(a[2]), "r"(a[3]), "r"(b0), "r"(b1));
}
__device__ __forceinline__ void ldsm_x4(uint32_t* r, uint32_t saddr) {
    asm volatile("ldmatrix.sync.aligned.m8n8.x4.shared.b16 {%0,%1,%2,%3}, [%4];"
        : "=r"(r[0]), "=r"(r[1]), "=r"(r[2]), "=r"(r[3]) : "r"(saddr));
}

#define BM 128
#define BN 128
#define BK 32
#define LDP 20                       /* row stride words: 80B = 16B-aligned + conflict-free */
#define ARR_W (BM*LDP)               /* words per array  = 2560 (10240 B)     */
#define STG_W (4*ARR_W)              /* words per stage  = 10240 (40960 B)    */
#define SMEM_BYTES (2*STG_W*4)       /* 81920 B dynamic (2 stages)            */

__device__ __forceinline__ void cp16(uint32_t dst, const void* src) {
    asm volatile("cp.async.cg.shared.global [%0], [%1], 16;" :: "r"(dst), "l"(src));
}

template<bool SA, bool SB>
__device__ __forceinline__ void stage_fill(
    uint32_t sbase,
    const hf* __restrict__ Ah, const hf* __restrict__ Al,
    const hf* __restrict__ Bh, const hf* __restrict__ Bl,
    int k0, int lda, int ldb)
{
    int tid = threadIdx.x;
    #pragma unroll
    for (int j = 0; j < 2; j++) {
        int chunk = tid + j * 256;            // 0..511
        int row = chunk >> 2;                 // 0..127
        int seg = chunk & 3;                  // 16B segment within 64B row
        uint32_t off = (uint32_t)(row * LDP * 4 + seg * 16);
        size_t a_off = (size_t)row * lda + k0 + seg * 8;
        size_t b_off = (size_t)row * ldb + k0 + seg * 8;
        cp16(sbase + 0u*ARR_W*4u + off, Ah + a_off);
        if (SA) cp16(sbase + 1u*ARR_W*4u + off, Al + a_off);
        cp16(sbase + 2u*ARR_W*4u + off, Bh + b_off);
        if (SB) cp16(sbase + 3u*ARR_W*4u + off, Bl + b_off);
    }
}

// MODE: 0 = plain fp32 store, 1 = atomic fp32 add,
//       4 = (acc+bias)*scale -> single fp16(oh),
//       5 = acc -> single fp16(oh),
//       6 = acc+bias -> C fp32 AND single fp16(oh)
template<int MODE, bool SA, bool SB>
__device__ __forceinline__ void gemm_core(
    const hf* __restrict__ Ah, const hf* __restrict__ Al,
    const hf* __restrict__ Bh, const hf* __restrict__ Bl,
    float* __restrict__ C, hf* __restrict__ oh,
    const float* __restrict__ bias, float scale,
    int kbeg, int kend, int lda, int ldb, int ldc)
{
    extern __shared__ uint32_t sh[];
    const uint32_t sb = (uint32_t)__cvta_generic_to_shared(sh);

    const int tid  = threadIdx.x;
    const int wid  = tid >> 5;
    const int lane = tid & 31;
    const int grp  = lane >> 2;
    const int tig  = lane & 3;
    const int mbase = (wid & 3) * 32;
    const int nbase = (wid >> 2) * 64;

    const hf* Abh = Ah + (size_t)blockIdx.y * BM * lda;
    const hf* Abl = SA ? Al + (size_t)blockIdx.y * BM * lda : nullptr;
    const hf* Bbh = Bh + (size_t)blockIdx.x * BN * ldb;
    const hf* Bbl = SB ? Bl + (size_t)blockIdx.x * BN * ldb : nullptr;

    const int a_off = (mbase + (lane & 15)) * LDP + ((lane & 16) ? 4 : 0);
    const int b_off = (nbase + ((lane >> 4) * 8) + (lane & 7)) * LDP + ((lane & 8) ? 4 : 0);

    float acc[2][8][4];
    #pragma unroll
    for (int mi = 0; mi < 2; mi++)
        #pragma unroll
        for (int ni = 0; ni < 8; ni++)
            #pragma unroll
            for (int v = 0; v < 4; v++) acc[mi][ni][v] = 0.f;

    stage_fill<SA,SB>(sb, Abh, Abl, Bbh, Bbl, kbeg, lda, ldb);
    asm volatile("cp.async.commit_group;" ::: "memory");

    int s = 0;
    for (int k0 = kbeg; k0 < kend; k0 += BK, s ^= 1) {
        if (k0 + BK < kend)
            stage_fill<SA,SB>(sb + (uint32_t)(s ^ 1) * STG_W * 4u,
                              Abh, Abl, Bbh, Bbl, k0 + BK, lda, ldb);
        asm volatile("cp.async.commit_group;" ::: "memory");
        asm volatile("cp.async.wait_group 1;" ::: "memory");
        __syncthreads();

        const uint32_t stg = sb + (uint32_t)s * STG_W * 4u;
        #pragma unroll
        for (int kk = 0; kk < 16; kk += 8) {
            uint32_t aH[2][4], aL[2][4];
            ldsm_x4(aH[0], stg + 0u*ARR_W*4u + (uint32_t)(a_off + kk) * 4u);
            ldsm_x4(aH[1], stg + 0u*ARR_W*4u + (uint32_t)(a_off + kk + 16*LDP) * 4u);
            if (SA) {
                ldsm_x4(aL[0], stg + 1u*ARR_W*4u + (uint32_t)(a_off + kk) * 4u);
                ldsm_x4(aL[1], stg + 1u*ARR_W*4u + (uint32_t)(a_off + kk + 16*LDP) * 4u);
            }
            #pragma unroll
            for (int ni2 = 0; ni2 < 4; ni2++) {
                uint32_t bH4[4], bL4[4];
                ldsm_x4(bH4, stg + 2u*ARR_W*4u + (uint32_t)(b_off + kk + ni2*16*LDP) * 4u);
                if (SB)
                    ldsm_x4(bL4, stg + 3u*ARR_W*4u + (uint32_t)(b_off + kk + ni2*16*LDP) * 4u);
                #pragma unroll
                for (int h = 0; h < 2; h++) {
                    int ni = ni2 * 2 + h;
                    #pragma unroll
                    for (int mi = 0; mi < 2; mi++) {
                        mma_f16(acc[mi][ni], aH[mi], bH4[h*2], bH4[h*2+1]);
                        if (SB) mma_f16(acc[mi][ni], aH[mi], bL4[h*2], bL4[h*2+1]);
                        if (SA) mma_f16(acc[mi][ni], aL[mi], bH4[h*2], bH4[h*2+1]);
                    }
                }
            }
        }
        __syncthreads();
    }

    #pragma unroll
    for (int mi = 0; mi < 2; mi++)
        #pragma unroll
        for (int ni = 0; ni < 8; ni++) {
            int row = blockIdx.y * BM + mbase + mi * 16 + grp;
            int col = blockIdx.x * BN + nbase + ni * 8 + tig * 2;
            float c0 = acc[mi][ni][0], c1 = acc[mi][ni][1];
            float c2 = acc[mi][ni][2], c3 = acc[mi][ni][3];
            if (MODE == 0) {
                *(float2*)&C[(size_t)row * ldc + col]       = make_float2(c0, c1);
                *(float2*)&C[(size_t)(row + 8) * ldc + col] = make_float2(c2, c3);
            } else if (MODE == 1) {
                atomicAdd(&C[(size_t)row * ldc + col],           c0);
                atomicAdd(&C[(size_t)row * ldc + col + 1],       c1);
                atomicAdd(&C[(size_t)(row + 8) * ldc + col],     c2);
                atomicAdd(&C[(size_t)(row + 8) * ldc + col + 1], c3);
            } else if (MODE == 5) {
                *(uint32_t*)(oh + (size_t)row * ldc + col)       = pack2h(c0, c1);
                *(uint32_t*)(oh + (size_t)(row + 8) * ldc + col) = pack2h(c2, c3);
            } else {
                float b0 = bias[col], b1 = bias[col + 1];
                float v0 = (c0 + b0) * scale, v1 = (c1 + b1) * scale;
                float v2 = (c2 + b0) * scale, v3 = (c3 + b1) * scale;
                if (MODE == 6) {
                    *(float2*)&C[(size_t)row * ldc + col]       = make_float2(v0, v1);
                    *(float2*)&C[(size_t)(row + 8) * ldc + col] = make_float2(v2, v3);
                }
                *(uint32_t*)(oh + (size_t)row * ldc + col)       = pack2h(v0, v1);
                *(uint32_t*)(oh + (size_t)(row + 8) * ldc + col) = pack2h(v2, v3);
            }
        }
}

// ---------------- GEMM wrapper kernels ----------------
__global__ void __launch_bounds__(256, 2) k_qproj(const float* __restrict__ bias) {
    // 1-term: x SINGLE, Wq SINGLE -> q single fp16
    gemm_core<4,false,false>(xh, nullptr, wqh, nullptr, nullptr, qh, bias, ATT_SCALE,
                             0, D_MODEL, D_MODEL, D_MODEL, NQ);
}
__global__ void __launch_bounds__(256, 2) k_kvproj(const float* __restrict__ bias) {
    // 1-term: x SINGLE, Wk SINGLE -> kv fp32 (for V path) + kvh single fp16 (K)
    gemm_core<6,false,false>(xh, nullptr, wkh, nullptr, g_kv, kvh, bias, 1.f,
                             0, D_MODEL, D_MODEL, D_MODEL, NKV);
}
__global__ void __launch_bounds__(256, 2) k_scores() {
    // 1-term: q SINGLE, K SINGLE -> raw scores stored fp16
    int batch = blockIdx.z;                 // g*H + h
    int g = batch >> 4;
    gemm_core<5,false,false>(qh + batch * DQK, nullptr,
                             kvh + g * DQK,   nullptr,
                             nullptr, sch + (size_t)batch * S_LEN * S_LEN,
                             nullptr, 1.f,
                             0, DQK, NQ, NKV, S_LEN);
}
__global__ void __launch_bounds__(256, 2) k_pv() {
    // 1-term: P SINGLE, V SINGLE
    int batch = blockIdx.z;
    int g = batch >> 4;
    gemm_core<0,false,false>(ph + (size_t)batch * S_LEN * S_LEN, nullptr,
                             vth + (size_t)g * DVV * S_LEN, nullptr,
                             g_z + batch * DVV, nullptr, nullptr, 1.f,
                             0, S_LEN, S_LEN, S_LEN, ZD);
}
__global__ void __launch_bounds__(256, 2) k_ffn1() {
    // 1-term: z SINGLE, W1 SINGLE
    int kb = blockIdx.z * (ZD / 2);
    gemm_core<1,false,false>(zh, nullptr, w1h, nullptr, g_h1, nullptr, nullptr, 1.f,
                             kb, kb + ZD / 2, ZD, ZD, FF2);
}
__global__ void __launch_bounds__(256, 2) k_ffn2(float* __restrict__ out) {
    // 1-term: h1 SINGLE, W2 SINGLE
    int kb = blockIdx.z * (FF2 / 4);
    gemm_core<1,false,false>(h1h, nullptr, w2h, nullptr, out, nullptr, nullptr, 1.f,
                             kb, kb + FF2 / 4, FF2, FF2, FF_OUT);
}

// ---------------- rmsnorm (vectorized; split or single output) --------------
template<bool SPLIT>
__device__ __forceinline__ void rms_body(const float* __restrict__ in,
                                         const float* __restrict__ gamma,
                                         hf* __restrict__ oh, hf* __restrict__ ol,
                                         int cols)
{
    const float4* x4 = (const float4*)(in + (size_t)blockIdx.x * cols);
    const float4* g4 = (const float4*)gamma;
    size_t obase = (size_t)blockIdx.x * cols;
    int nv = cols >> 2;
    float ss = 0.f;
    for (int c = threadIdx.x; c < nv; c += blockDim.x) {
        float4 v = x4[c];
        ss += v.x*v.x + v.y*v.y + v.z*v.z + v.w*v.w;
    }
    __shared__ float red[33];
    #pragma unroll
    for (int o = 16; o; o >>= 1) ss += __shfl_xor_sync(0xffffffffu, ss, o);
    if ((threadIdx.x & 31) == 0) red[threadIdx.x >> 5] = ss;
    __syncthreads();
    if (threadIdx.x < 32) {
        float v = (threadIdx.x < (blockDim.x >> 5)) ? red[threadIdx.x] : 0.f;
        #pragma unroll
        for (int o = 16; o; o >>= 1) v += __shfl_xor_sync(0xffffffffu, v, o);
        if (threadIdx.x == 0) red[32] = v;
    }
    __syncthreads();
    float scale = sqrtf((float)cols) / fmaxf(sqrtf(red[32]), 1e-12f);
    for (int c = threadIdx.x; c < nv; c += blockDim.x) {
        float4 v = x4[c];
        float4 g = g4[c];
        v.x *= scale * g.x; v.y *= scale * g.y; v.z *= scale * g.z; v.w *= scale * g.w;
        if (SPLIT)
            split4(oh, ol, obase + (size_t)c * 4, v);
        else
            *(uint2*)(oh + obase + (size_t)c * 4) =
                make_uint2(pack2h(v.x, v.y), pack2h(v.z, v.w));
    }
}
__global__ void k_rms_x(const float* __restrict__ x, const float* __restrict__ gamma) {
    rms_body<true>(x, gamma, xh, xl, D_MODEL);
}
__global__ void k_rms_z(const float* __restrict__ gamma) {
    rms_body<false>(g_z, gamma, zh, nullptr, ZD);
}

// ---------------- weight split (vectorized; all singles now) ----------------
__global__ void k_split_w(const float* __restrict__ src, int which) {
    size_t i4 = ((size_t)blockIdx.x * 256 + threadIdx.x) * 4;
    float4 v = *(const float4*)(src + i4);
    uint2 p = make_uint2(pack2h(v.x, v.y), pack2h(v.z, v.w));
    switch (which) {
        case 0: *(uint2*)(wqh + i4) = p; break;
        case 1: *(uint2*)(wkh + i4) = p; break;
        case 2: *(uint2*)(w1h + i4) = p; break;
        case 3: *(uint2*)(w2h + i4) = p; break;
    }
}

// ---------------- elementwise kernels ----------------
// tiled transpose: vt[g][d][t] = kv[t][NKHALF + g*128 + d]  (single fp16)
__global__ void k_vt_build() {
    __shared__ float tile[32][33];
    int t0 = blockIdx.x * 32, d0 = blockIdx.y * 32, g = blockIdx.z;
    #pragma unroll
    for (int j = 0; j < 4; j++) {
        int t = t0 + threadIdx.y + 8 * j;
        tile[threadIdx.y + 8 * j][threadIdx.x] =
            g_kv[(size_t)t * NKV + NKHALF + g * DVV + d0 + threadIdx.x];
    }
    __syncthreads();
    #pragma unroll
    for (int j = 0; j < 4; j++) {
        int d = d0 + threadIdx.y + 8 * j;
        vth[((size_t)g * DVV + d) * S_LEN + t0 + threadIdx.x] =
            __float2half_rn(tile[threadIdx.x][threadIdx.y + 8 * j]);
    }
}
__global__ void k_zero_h1() {
    size_t i4 = ((size_t)blockIdx.x * 256 + threadIdx.x) * 4;
    *(float4*)(g_h1 + i4) = make_float4(0.f, 0.f, 0.f, 0.f);
}
__global__ void k_zero_out(float* __restrict__ out) {
    size_t i4 = ((size_t)blockIdx.x * 256 + threadIdx.x) * 4;
    *(float4*)(out + i4) = make_float4(0.f, 0.f, 0.f, 0.f);
}
__global__ void k_silu_h1(const float* __restrict__ bias) {
    size_t i4 = ((size_t)blockIdx.x * 256 + threadIdx.x) * 4;
    float4 v = *(const float4*)(g_h1 + i4);
    float4 b = *(const float4*)(bias + (i4 & (FF2 - 1)));
    v.x += b.x; v.y += b.y; v.z += b.z; v.w += b.w;
    v.x /= (1.f + __expf(-v.x)); v.y /= (1.f + __expf(-v.y));
    v.z /= (1.f + __expf(-v.z)); v.w /= (1.f + __expf(-v.w));
    *(uint2*)(h1h + i4) = make_uint2(pack2h(v.x, v.y), pack2h(v.z, v.w));
}
__global__ void k_silu_out(float* __restrict__ C, const float* __restrict__ bias) {
    size_t i4 = ((size_t)blockIdx.x * 256 + threadIdx.x) * 4;
    float4 v = *(const float4*)(C + i4);
    float4 b = *(const float4*)(bias + (i4 & (FF_OUT - 1)));
    v.x += b.x; v.y += b.y; v.z += b.z; v.w += b.w;
    v.x /= (1.f + __expf(-v.x)); v.y /= (1.f + __expf(-v.y));
    v.z /= (1.f + __expf(-v.z)); v.w /= (1.f + __expf(-v.w));
    *(float4*)(C + i4) = v;
}

// ---------------- row softmax over 1024 cols (fp16 scores in, fp16 P out) ---
__global__ void k_softmax() {
    size_t rbase = (size_t)blockIdx.x * S_LEN;
    const uint2* row2 = (const uint2*)(sch + rbase);
    __shared__ float red[33];
    int tid = threadIdx.x;
    uint2 raw = row2[tid];
    __half2 h01 = *reinterpret_cast<__half2*>(&raw.x);
    __half2 h23 = *reinterpret_cast<__half2*>(&raw.y);
    float4 v = make_float4(__half2float(__low2half(h01)),  __half2float(__high2half(h01)),
                           __half2float(__low2half(h23)),  __half2float(__high2half(h23)));
    float m = fmaxf(fmaxf(v.x, v.y), fmaxf(v.z, v.w));
    #pragma unroll
    for (int o = 16; o; o >>= 1) m = fmaxf(m, __shfl_xor_sync(0xffffffffu, m, o));
    if ((tid & 31) == 0) red[tid >> 5] = m;
    __syncthreads();
    if (tid < 32) {
        float t = (tid < 8) ? red[tid] : -1e30f;
        #pragma unroll
        for (int o = 4; o; o >>= 1) t = fmaxf(t, __shfl_xor_sync(0xffffffffu, t, o));
        if (tid == 0) red[32] = t;
    }
    __syncthreads();
    m = red[32];
    __syncthreads();
    v.x = __expf(v.x - m); v.y = __expf(v.y - m);
    v.z = __expf(v.z - m); v.w = __expf(v.w - m);
    float s = v.x + v.y + v.z + v.w;
    #pragma unroll
    for (int o = 16; o; o >>= 1) s += __shfl_xor_sync(0xffffffffu, s, o);
    if ((tid & 31) == 0) red[tid >> 5] = s;
    __syncthreads();
    if (tid < 32) {
        float t = (tid < 8) ? red[tid] : 0.f;
        #pragma unroll
        for (int o = 4; o; o >>= 1) t += __shfl_xor_sync(0xffffffffu, t, o);
        if (tid == 0) red[32] = t;
    }
    __syncthreads();
    float inv = 1.f / red[32];
    *(uint2*)(ph + rbase + (size_t)tid * 4) =
        make_uint2(pack2h(v.x * inv, v.y * inv), pack2h(v.z * inv, v.w * inv));
}

// ---------------- launch ----------------
extern "C" void kernel_launch(void* const* d_in, const int* in_sizes, int n_in,
                              void* d_out, int out_size) {
    const float* x     = (const float*)d_in[0];
    const float* gin   = (const float*)d_in[1];
    const float* Wq_w  = (const float*)d_in[2];
    const float* Wq_b  = (const float*)d_in[3];
    const float* Wkv_w = (const float*)d_in[4];
    const float* Wkv_b = (const float*)d_in[5];
    const float* gz    = (const float*)d_in[6];
    const float* W1    = (const float*)d_in[7];
    const float* b1    = (const float*)d_in[8];
    const float* W2    = (const float*)d_in[9];
    const float* b2    = (const float*)d_in[10];
    float* out = (float*)d_out;

    cudaFuncSetAttribute(k_qproj,  cudaFuncAttributeMaxDynamicSharedMemorySize, SMEM_BYTES);
    cudaFuncSetAttribute(k_kvproj, cudaFuncAttributeMaxDynamicSharedMemorySize, SMEM_BYTES);
    cudaFuncSetAttribute(k_scores, cudaFuncAttributeMaxDynamicSharedMemorySize, SMEM_BYTES);
    cudaFuncSetAttribute(k_pv,     cudaFuncAttributeMaxDynamicSharedMemorySize, SMEM_BYTES);
    cudaFuncSetAttribute(k_ffn1,   cudaFuncAttributeMaxDynamicSharedMemorySize, SMEM_BYTES);
    cudaFuncSetAttribute(k_ffn2,   cudaFuncAttributeMaxDynamicSharedMemorySize, SMEM_BYTES);

    k_rms_x   <<<S_LEN, 256>>>(x, gin);
    k_split_w <<<(NQ * D_MODEL) / 1024, 256>>>(Wq_w, 0);
    k_split_w <<<(NKV * D_MODEL) / 1024, 256>>>(Wkv_w, 1);
    k_split_w <<<(FF2 * ZD) / 1024, 256>>>(W1, 2);
    k_split_w <<<(FF_OUT * FF2) / 1024, 256>>>(W2, 3);

    k_qproj   <<<dim3(NQ / BN,     S_LEN / BM), 256, SMEM_BYTES>>>(Wq_b);
    k_kvproj  <<<dim3(NKV / BN,    S_LEN / BM), 256, SMEM_BYTES>>>(Wkv_b);
    k_vt_build<<<dim3(S_LEN / 32, DVV / 32, G_GRP), dim3(32, 8)>>>();

    k_scores  <<<dim3(S_LEN / BN,  S_LEN / BM, G_GRP * H_HEADS), 256, SMEM_BYTES>>>();
    k_softmax <<<G_GRP * H_HEADS * S_LEN, 256>>>();
    k_pv      <<<dim3(1,           S_LEN / BM, G_GRP * H_HEADS), 256, SMEM_BYTES>>>();

    k_rms_z   <<<S_LEN, 256>>>(gz);
    k_zero_h1 <<<(S_LEN * FF2) / 1024, 256>>>();
    k_ffn1    <<<dim3(FF2 / BN,    S_LEN / BM, 2), 256, SMEM_BYTES>>>();
    k_silu_h1 <<<(S_LEN * FF2) / 1024, 256>>>(b1);
    k_zero_out<<<(S_LEN * FF_OUT) / 1024, 256>>>(out);
    k_ffn2    <<<dim3(FF_OUT / BN, S_LEN / BM, 4), 256, SMEM_BYTES>>>(out);
    k_silu_out<<<(S_LEN * FF_OUT) / 1024, 256>>>(out, b2);
}

// round 17
// speedup vs baseline: 6.3063x; 1.0924x over previous
#include <cuda_runtime.h>
#include <cuda_fp16.h>
#include <math.h>
#include <stdint.h>

// ---------------- problem constants ----------------
#define S_LEN   1024
#define D_MODEL 1024
#define G_GRP   8
#define H_HEADS 16
#define DQK     128
#define DVV     128
#define FF_OUT  1024
#define NQ      (G_GRP*H_HEADS*DQK)    /* 16384 */
#define NKV     (G_GRP*(DQK+DVV))      /* 2048  */
#define NKHALF  (G_GRP*DQK)            /* 1024  */
#define ZD      NQ                     /* 16384 */
#define FF2     (2*FF_OUT)             /* 2048  */
#define ATT_SCALE 0.08838834764831845f /* 1/sqrt(128) */

typedef __half hf;

// ---------------- scratch (device globals; referenced ONLY in device code) ---
// (passing these as kernel args from host passes the host shadow — R2-R4 bug)
__device__ __align__(256) float g_z[S_LEN*ZD];
__device__ __align__(256) float g_h1[S_LEN*FF2];

// fp16 operands (all GEMM inputs single fp16; x keeps a split pair only for
// potential future use of xl — currently only xh is consumed).
__device__ __align__(256) hf xh [S_LEN*D_MODEL];
__device__ __align__(256) hf wqh[NQ*D_MODEL];
__device__ __align__(256) hf wkh[NKV*D_MODEL];
__device__ __align__(256) hf qh [S_LEN*NQ];
__device__ __align__(256) hf kvh[S_LEN*NKV];                        // K (cols < NKHALF used)
__device__ __align__(256) hf vth[G_GRP*DVV*S_LEN];                  // V transposed
__device__ __align__(256) hf sch[134217728];                        // raw scores
__device__ __align__(256) hf ph [134217728];                        // softmax P
__device__ __align__(256) hf zh [S_LEN*ZD];
__device__ __align__(256) hf w1h[FF2*ZD];
__device__ __align__(256) hf h1h[S_LEN*FF2];
__device__ __align__(256) hf w2h[FF_OUT*FF2];

// ---------------- helpers ----------------
__device__ __forceinline__ uint32_t pack2h(float x, float y) {
    __half2 p = __floats2half2_rn(x, y);
    return *reinterpret_cast<uint32_t*>(&p);
}

// ---------------- 1-term fp16 mma GEMM, BK=64, 2-stage cp.async + ldmatrix --
// C(128x128 tile) = A(MxK)@B(NxK)^T, fp32 accum.

__device__ __forceinline__ void mma_f16(float* d, const uint32_t* a, uint32_t b0, uint32_t b1) {
    asm volatile(
        "mma.sync.aligned.m16n8k16.row.col.f32.f16.f16.f32 "
        "{%0,%1,%2,%3}, {%4,%5,%6,%7}, {%8,%9}, {%0,%1,%2,%3};"
        : "+f"(d[0]), "+f"(d[1]), "+f"(d[2]), "+f"(d[3])
        : "r"(a[0]), "r"(a[1]), "r"(a[2]), "r"(a[3]), "r"(b0), "r"(b1));
}
__device__ __forceinline__ void ldsm_x4(uint32_t* r, uint32_t saddr) {
    asm volatile("ldmatrix.sync.aligned.m8n8.x4.shared.b16 {%0,%1,%2,%3}, [%4];"
        : "=r"(r[0]), "=r"(r[1]), "=r"(r[2]), "=r"(r[3]) : "r"(saddr));
}

#define BM 128
#define BN 128
#define BK 64
#define LDP 36                       /* row stride words: 144B = 16B-aligned; 36%32=4 -> 8 distinct banks */
#define ARR_W (BM*LDP)               /* words per array  = 4608 (18432 B)     */
#define STG_W (2*ARR_W)              /* words per stage  = 9216 (36864 B)     */
#define SMEM_BYTES (2*STG_W*4)       /* 73728 B dynamic (2 stages)            */

__device__ __forceinline__ void cp16(uint32_t dst, const void* src) {
    asm volatile("cp.async.cg.shared.global [%0], [%1], 16;" :: "r"(dst), "l"(src));
}

__device__ __forceinline__ void stage_fill(
    uint32_t sbase,
    const hf* __restrict__ Ah, const hf* __restrict__ Bh,
    int k0, int lda, int ldb)
{
    int tid = threadIdx.x;
    // per array: 128 rows x 64 halfs (128B = 8 segs of 16B) = 1024 chunks
    #pragma unroll
    for (int j = 0; j < 4; j++) {
        int chunk = tid + j * 256;            // 0..1023
        int row = chunk >> 3;                 // 0..127
        int seg = chunk & 7;                  // 16B segment within 128B row
        uint32_t off = (uint32_t)(row * LDP * 4 + seg * 16);
        cp16(sbase + off,               Ah + (size_t)row * lda + k0 + seg * 8);
        cp16(sbase + ARR_W * 4u + off,  Bh + (size_t)row * ldb + k0 + seg * 8);
    }
}

// MODE: 0 = plain fp32 store, 1 = atomic fp32 add,
//       4 = (acc+bias)*scale -> single fp16(oh),
//       5 = acc -> single fp16(oh),
//       7 = acc+bias -> kv epilogue: K half -> oh (kvh layout), V half -> vth transposed
template<int MODE>
__device__ __forceinline__ void gemm_core(
    const hf* __restrict__ Ah, const hf* __restrict__ Bh,
    float* __restrict__ C, hf* __restrict__ oh,
    const float* __restrict__ bias, float scale,
    int kbeg, int kend, int lda, int ldb, int ldc)
{
    extern __shared__ uint32_t sh[];
    const uint32_t sb = (uint32_t)__cvta_generic_to_shared(sh);

    const int tid  = threadIdx.x;
    const int wid  = tid >> 5;
    const int lane = tid & 31;
    const int grp  = lane >> 2;
    const int tig  = lane & 3;
    const int mbase = (wid & 3) * 32;
    const int nbase = (wid >> 2) * 64;

    const hf* Ab = Ah + (size_t)blockIdx.y * BM * lda;
    const hf* Bb = Bh + (size_t)blockIdx.x * BN * ldb;

    const int a_off = (mbase + (lane & 15)) * LDP + ((lane & 16) ? 4 : 0);
    const int b_off = (nbase + ((lane >> 4) * 8) + (lane & 7)) * LDP + ((lane & 8) ? 4 : 0);

    float acc[2][8][4];
    #pragma unroll
    for (int mi = 0; mi < 2; mi++)
        #pragma unroll
        for (int ni = 0; ni < 8; ni++)
            #pragma unroll
            for (int v = 0; v < 4; v++) acc[mi][ni][v] = 0.f;

    stage_fill(sb, Ab, Bb, kbeg, lda, ldb);
    asm volatile("cp.async.commit_group;" ::: "memory");

    int s = 0;
    for (int k0 = kbeg; k0 < kend; k0 += BK, s ^= 1) {
        if (k0 + BK < kend)
            stage_fill(sb + (uint32_t)(s ^ 1) * STG_W * 4u, Ab, Bb, k0 + BK, lda, ldb);
        asm volatile("cp.async.commit_group;" ::: "memory");
        asm volatile("cp.async.wait_group 1;" ::: "memory");
        __syncthreads();

        const uint32_t stg = sb + (uint32_t)s * STG_W * 4u;
        #pragma unroll
        for (int kk = 0; kk < 32; kk += 8) {      // 4 k16 steps per BK=64
            uint32_t aH[2][4];
            ldsm_x4(aH[0], stg + (uint32_t)(a_off + kk) * 4u);
            ldsm_x4(aH[1], stg + (uint32_t)(a_off + kk + 16*LDP) * 4u);
            #pragma unroll
            for (int ni2 = 0; ni2 < 4; ni2++) {
                uint32_t bH4[4];
                ldsm_x4(bH4, stg + ARR_W * 4u + (uint32_t)(b_off + kk + ni2*16*LDP) * 4u);
                #pragma unroll
                for (int h = 0; h < 2; h++) {
                    int ni = ni2 * 2 + h;
                    #pragma unroll
                    for (int mi = 0; mi < 2; mi++)
                        mma_f16(acc[mi][ni], aH[mi], bH4[h*2], bH4[h*2+1]);
                }
            }
        }
        __syncthreads();
    }

    #pragma unroll
    for (int mi = 0; mi < 2; mi++)
        #pragma unroll
        for (int ni = 0; ni < 8; ni++) {
            int row = blockIdx.y * BM + mbase + mi * 16 + grp;
            int col = blockIdx.x * BN + nbase + ni * 8 + tig * 2;
            float c0 = acc[mi][ni][0], c1 = acc[mi][ni][1];
            float c2 = acc[mi][ni][2], c3 = acc[mi][ni][3];
            if (MODE == 0) {
                *(float2*)&C[(size_t)row * ldc + col]       = make_float2(c0, c1);
                *(float2*)&C[(size_t)(row + 8) * ldc + col] = make_float2(c2, c3);
            } else if (MODE == 1) {
                atomicAdd(&C[(size_t)row * ldc + col],           c0);
                atomicAdd(&C[(size_t)row * ldc + col + 1],       c1);
                atomicAdd(&C[(size_t)(row + 8) * ldc + col],     c2);
                atomicAdd(&C[(size_t)(row + 8) * ldc + col + 1], c3);
            } else if (MODE == 5) {
                *(uint32_t*)(oh + (size_t)row * ldc + col)       = pack2h(c0, c1);
                *(uint32_t*)(oh + (size_t)(row + 8) * ldc + col) = pack2h(c2, c3);
            } else if (MODE == 4) {
                float b0 = bias[col], b1 = bias[col + 1];
                *(uint32_t*)(oh + (size_t)row * ldc + col) =
                    pack2h((c0 + b0) * scale, (c1 + b1) * scale);
                *(uint32_t*)(oh + (size_t)(row + 8) * ldc + col) =
                    pack2h((c2 + b0) * scale, (c3 + b1) * scale);
            } else {  // MODE 7: fused kv epilogue
                float b0 = bias[col], b1 = bias[col + 1];
                float v0 = c0 + b0, v1 = c1 + b1;
                float v2 = c2 + b0, v3 = c3 + b1;
                if (col < NKHALF) {
                    *(uint32_t*)(oh + (size_t)row * ldc + col)       = pack2h(v0, v1);
                    *(uint32_t*)(oh + (size_t)(row + 8) * ldc + col) = pack2h(v2, v3);
                } else {
                    int d0 = col - NKHALF;      // == g*DVV + d, matching vth layout
                    vth[(size_t)d0 * S_LEN + row]           = __float2half_rn(v0);
                    vth[(size_t)(d0 + 1) * S_LEN + row]     = __float2half_rn(v1);
                    vth[(size_t)d0 * S_LEN + row + 8]       = __float2half_rn(v2);
                    vth[(size_t)(d0 + 1) * S_LEN + row + 8] = __float2half_rn(v3);
                }
            }
        }
}

// ---------------- GEMM wrapper kernels ----------------
__global__ void __launch_bounds__(256, 2) k_qproj(const float* __restrict__ bias) {
    gemm_core<4>(xh, wqh, nullptr, qh, bias, ATT_SCALE,
                 0, D_MODEL, D_MODEL, D_MODEL, NQ);
}
__global__ void __launch_bounds__(256, 2) k_kvproj(const float* __restrict__ bias) {
    // fused: K half -> kvh, V half -> vth (transposed), numerics identical to old path
    gemm_core<7>(xh, wkh, nullptr, kvh, bias, 1.f,
                 0, D_MODEL, D_MODEL, D_MODEL, NKV);
}
__global__ void __launch_bounds__(256, 2) k_scores() {
    int batch = blockIdx.z;                 // g*H + h
    int g = batch >> 4;
    gemm_core<5>(qh + batch * DQK, kvh + g * DQK,
                 nullptr, sch + (size_t)batch * S_LEN * S_LEN,
                 nullptr, 1.f,
                 0, DQK, NQ, NKV, S_LEN);
}
__global__ void __launch_bounds__(256, 2) k_pv() {
    int batch = blockIdx.z;
    int g = batch >> 4;
    gemm_core<0>(ph + (size_t)batch * S_LEN * S_LEN,
                 vth + (size_t)g * DVV * S_LEN,
                 g_z + batch * DVV, nullptr, nullptr, 1.f,
                 0, S_LEN, S_LEN, S_LEN, ZD);
}
__global__ void __launch_bounds__(256, 2) k_ffn1() {
    int kb = blockIdx.z * (ZD / 2);
    gemm_core<1>(zh, w1h, g_h1, nullptr, nullptr, 1.f,
                 kb, kb + ZD / 2, ZD, ZD, FF2);
}
__global__ void __launch_bounds__(256, 2) k_ffn2(float* __restrict__ out) {
    int kb = blockIdx.z * (FF2 / 4);
    gemm_core<1>(h1h, w2h, out, nullptr, nullptr, 1.f,
                 kb, kb + FF2 / 4, FF2, FF2, FF_OUT);
}

// ---------------- rmsnorm (vectorized; single fp16 output) ----------------
__device__ __forceinline__ void rms_body(const float* __restrict__ in,
                                         const float* __restrict__ gamma,
                                         hf* __restrict__ oh, int cols)
{
    const float4* x4 = (const float4*)(in + (size_t)blockIdx.x * cols);
    const float4* g4 = (const float4*)gamma;
    size_t obase = (size_t)blockIdx.x * cols;
    int nv = cols >> 2;
    float ss = 0.f;
    for (int c = threadIdx.x; c < nv; c += blockDim.x) {
        float4 v = x4[c];
        ss += v.x*v.x + v.y*v.y + v.z*v.z + v.w*v.w;
    }
    __shared__ float red[33];
    #pragma unroll
    for (int o = 16; o; o >>= 1) ss += __shfl_xor_sync(0xffffffffu, ss, o);
    if ((threadIdx.x & 31) == 0) red[threadIdx.x >> 5] = ss;
    __syncthreads();
    if (threadIdx.x < 32) {
        float v = (threadIdx.x < (blockDim.x >> 5)) ? red[threadIdx.x] : 0.f;
        #pragma unroll
        for (int o = 16; o; o >>= 1) v += __shfl_xor_sync(0xffffffffu, v, o);
        if (threadIdx.x == 0) red[32] = v;
    }
    __syncthreads();
    float scale = sqrtf((float)cols) / fmaxf(sqrtf(red[32]), 1e-12f);
    for (int c = threadIdx.x; c < nv; c += blockDim.x) {
        float4 v = x4[c];
        float4 g = g4[c];
        v.x *= scale * g.x; v.y *= scale * g.y; v.z *= scale * g.z; v.w *= scale * g.w;
        *(uint2*)(oh + obase + (size_t)c * 4) =
            make_uint2(pack2h(v.x, v.y), pack2h(v.z, v.w));
    }
}
__global__ void k_rms_x(const float* __restrict__ x, const float* __restrict__ gamma) {
    rms_body(x, gamma, xh, D_MODEL);
}
__global__ void k_rms_z(const float* __restrict__ gamma) {
    rms_body(g_z, gamma, zh, ZD);
}

// ---------------- weight convert (vectorized; all single fp16) --------------
__global__ void k_split_w(const float* __restrict__ src, int which) {
    size_t i4 = ((size_t)blockIdx.x * 256 + threadIdx.x) * 4;
    float4 v = *(const float4*)(src + i4);
    uint2 p = make_uint2(pack2h(v.x, v.y), pack2h(v.z, v.w));
    switch (which) {
        case 0: *(uint2*)(wqh + i4) = p; break;
        case 1: *(uint2*)(wkh + i4) = p; break;
        case 2: *(uint2*)(w1h + i4) = p; break;
        case 3: *(uint2*)(w2h + i4) = p; break;
    }
}

// ---------------- elementwise kernels ----------------
__global__ void k_zero_h1() {
    size_t i4 = ((size_t)blockIdx.x * 256 + threadIdx.x) * 4;
    *(float4*)(g_h1 + i4) = make_float4(0.f, 0.f, 0.f, 0.f);
}
__global__ void k_zero_out(float* __restrict__ out) {
    size_t i4 = ((size_t)blockIdx.x * 256 + threadIdx.x) * 4;
    *(float4*)(out + i4) = make_float4(0.f, 0.f, 0.f, 0.f);
}
__global__ void k_silu_h1(const float* __restrict__ bias) {
    size_t i4 = ((size_t)blockIdx.x * 256 + threadIdx.x) * 4;
    float4 v = *(const float4*)(g_h1 + i4);
    float4 b = *(const float4*)(bias + (i4 & (FF2 - 1)));
    v.x += b.x; v.y += b.y; v.z += b.z; v.w += b.w;
    v.x /= (1.f + __expf(-v.x)); v.y /= (1.f + __expf(-v.y));
    v.z /= (1.f + __expf(-v.z)); v.w /= (1.f + __expf(-v.w));
    *(uint2*)(h1h + i4) = make_uint2(pack2h(v.x, v.y), pack2h(v.z, v.w));
}
__global__ void k_silu_out(float* __restrict__ C, const float* __restrict__ bias) {
    size_t i4 = ((size_t)blockIdx.x * 256 + threadIdx.x) * 4;
    float4 v = *(const float4*)(C + i4);
    float4 b = *(const float4*)(bias + (i4 & (FF_OUT - 1)));
    v.x += b.x; v.y += b.y; v.z += b.z; v.w += b.w;
    v.x /= (1.f + __expf(-v.x)); v.y /= (1.f + __expf(-v.y));
    v.z /= (1.f + __expf(-v.z)); v.w /= (1.f + __expf(-v.w));
    *(float4*)(C + i4) = v;
}

// ---------------- row softmax over 1024 cols (fp16 scores in, fp16 P out) ---
__global__ void k_softmax() {
    size_t rbase = (size_t)blockIdx.x * S_LEN;
    const uint2* row2 = (const uint2*)(sch + rbase);
    __shared__ float red[33];
    int tid = threadIdx.x;
    uint2 raw = row2[tid];
    __half2 h01 = *reinterpret_cast<__half2*>(&raw.x);
    __half2 h23 = *reinterpret_cast<__half2*>(&raw.y);
    float4 v = make_float4(__half2float(__low2half(h01)),  __half2float(__high2half(h01)),
                           __half2float(__low2half(h23)),  __half2float(__high2half(h23)));
    float m = fmaxf(fmaxf(v.x, v.y), fmaxf(v.z, v.w));
    #pragma unroll
    for (int o = 16; o; o >>= 1) m = fmaxf(m, __shfl_xor_sync(0xffffffffu, m, o));
    if ((tid & 31) == 0) red[tid >> 5] = m;
    __syncthreads();
    if (tid < 32) {
        float t = (tid < 8) ? red[tid] : -1e30f;
        #pragma unroll
        for (int o = 4; o; o >>= 1) t = fmaxf(t, __shfl_xor_sync(0xffffffffu, t, o));
        if (tid == 0) red[32] = t;
    }
    __syncthreads();
    m = red[32];
    __syncthreads();
    v.x = __expf(v.x - m); v.y = __expf(v.y - m);
    v.z = __expf(v.z - m); v.w = __expf(v.w - m);
    float s = v.x + v.y + v.z + v.w;
    #pragma unroll
    for (int o = 16; o; o >>= 1) s += __shfl_xor_sync(0xffffffffu, s, o);
    if ((tid & 31) == 0) red[tid >> 5] = s;
    __syncthreads();
    if (tid < 32) {
        float t = (tid < 8) ? red[tid] : 0.f;
        #pragma unroll
        for (int o = 4; o; o >>= 1) t += __shfl_xor_sync(0xffffffffu, t, o);
        if (tid == 0) red[32] = t;
    }
    __syncthreads();
    float inv = 1.f / red[32];
    *(uint2*)(ph + rbase + (size_t)tid * 4) =
        make_uint2(pack2h(v.x * inv, v.y * inv), pack2h(v.z * inv, v.w * inv));
}

// ---------------- launch ----------------
extern "C" void kernel_launch(void* const* d_in, const int* in_sizes, int n_in,
                              void* d_out, int out_size) {
    const float* x     = (const float*)d_in[0];
    const float* gin   = (const float*)d_in[1];
    const float* Wq_w  = (const float*)d_in[2];
    const float* Wq_b  = (const float*)d_in[3];
    const float* Wkv_w = (const float*)d_in[4];
    const float* Wkv_b = (const float*)d_in[5];
    const float* gz    = (const float*)d_in[6];
    const float* W1    = (const float*)d_in[7];
    const float* b1    = (const float*)d_in[8];
    const float* W2    = (const float*)d_in[9];
    const float* b2    = (const float*)d_in[10];
    float* out = (float*)d_out;

    cudaFuncSetAttribute(k_qproj,  cudaFuncAttributeMaxDynamicSharedMemorySize, SMEM_BYTES);
    cudaFuncSetAttribute(k_kvproj, cudaFuncAttributeMaxDynamicSharedMemorySize, SMEM_BYTES);
    cudaFuncSetAttribute(k_scores, cudaFuncAttributeMaxDynamicSharedMemorySize, SMEM_BYTES);
    cudaFuncSetAttribute(k_pv,     cudaFuncAttributeMaxDynamicSharedMemorySize, SMEM_BYTES);
    cudaFuncSetAttribute(k_ffn1,   cudaFuncAttributeMaxDynamicSharedMemorySize, SMEM_BYTES);
    cudaFuncSetAttribute(k_ffn2,   cudaFuncAttributeMaxDynamicSharedMemorySize, SMEM_BYTES);

    k_rms_x   <<<S_LEN, 256>>>(x, gin);
    k_split_w <<<(NQ * D_MODEL) / 1024, 256>>>(Wq_w, 0);
    k_split_w <<<(NKV * D_MODEL) / 1024, 256>>>(Wkv_w, 1);
    k_split_w <<<(FF2 * ZD) / 1024, 256>>>(W1, 2);
    k_split_w <<<(FF_OUT * FF2) / 1024, 256>>>(W2, 3);

    k_qproj   <<<dim3(NQ / BN,     S_LEN / BM), 256, SMEM_BYTES>>>(Wq_b);
    k_kvproj  <<<dim3(NKV / BN,    S_LEN / BM), 256, SMEM_BYTES>>>(Wkv_b);

    k_scores  <<<dim3(S_LEN / BN,  S_LEN / BM, G_GRP * H_HEADS), 256, SMEM_BYTES>>>();
    k_softmax <<<G_GRP * H_HEADS * S_LEN, 256>>>();
    k_pv      <<<dim3(1,           S_LEN / BM, G_GRP * H_HEADS), 256, SMEM_BYTES>>>();

    k_rms_z   <<<S_LEN, 256>>>(gz);
    k_zero_h1 <<<(S_LEN * FF2) / 1024, 256>>>();
    k_ffn1    <<<dim3(FF2 / BN,    S_LEN / BM, 2), 256, SMEM_BYTES>>>();
    k_silu_h1 <<<(S_LEN * FF2) / 1024, 256>>>(b1);
    k_zero_out<<<(S_LEN * FF_OUT) / 1024, 256>>>(out);
    k_ffn2    <<<dim3(FF_OUT / BN, S_LEN / BM, 4), 256, SMEM_BYTES>>>(out);
    k_silu_out<<<(S_LEN * FF_OUT) / 1024, 256>>>(out, b2);
}